// round 2
// baseline (speedup 1.0000x reference)
#include <cuda_runtime.h>

#define B_  2
#define S_  2048
#define D_  1024
#define H_  16
#define DK_ 64
#define M_  (B_ * S_)   // 4096

// Scratch (allocation-free: __device__ globals)
__device__ float g_q [B_ * S_ * D_];
__device__ float g_k [B_ * S_ * D_];
__device__ float g_v [B_ * S_ * D_];
__device__ float g_ao[B_ * S_ * D_];

// ---------------------------------------------------------------------------
// GEMM: C[M,N] = A[M,K] @ W[K,N] + bias[N]
// 64x64 tile, BK=16, 256 threads, 4x4 accum per thread.
// ---------------------------------------------------------------------------
__global__ __launch_bounds__(256) void gemm_bias_kernel(
    const float* __restrict__ A,
    const float* __restrict__ W,
    const float* __restrict__ bias,
    float* __restrict__ C,
    int M, int N, int K)
{
    __shared__ float As[16][65];   // transposed A tile, padded (conflict-free)
    __shared__ float Bs[16][64];   // B tile (float4-friendly)

    const int tid = threadIdx.x;
    const int ty  = tid >> 4;      // 0..15
    const int tx  = tid & 15;      // 0..15
    const int m0  = blockIdx.y * 64;
    const int n0  = blockIdx.x * 64;

    // A tile load mapping: one float4 per thread (64 rows x 16 cols)
    const int ar  = tid >> 2;          // 0..63
    const int ac4 = (tid & 3) * 4;     // 0,4,8,12
    // B tile load mapping: one float4 per thread (16 rows x 64 cols)
    const int br  = tid >> 4;          // 0..15
    const int bc4 = (tid & 15) * 4;    // 0..60

    float acc[4][4] = {};

    for (int k0 = 0; k0 < K; k0 += 16) {
        float4 av = *reinterpret_cast<const float4*>(
            &A[(size_t)(m0 + ar) * K + k0 + ac4]);
        float4 bv = *reinterpret_cast<const float4*>(
            &W[(size_t)(k0 + br) * N + n0 + bc4]);

        As[ac4 + 0][ar] = av.x;
        As[ac4 + 1][ar] = av.y;
        As[ac4 + 2][ar] = av.z;
        As[ac4 + 3][ar] = av.w;
        *reinterpret_cast<float4*>(&Bs[br][bc4]) = bv;
        __syncthreads();

        #pragma unroll
        for (int k = 0; k < 16; k++) {
            float a[4];
            #pragma unroll
            for (int i = 0; i < 4; i++) a[i] = As[k][ty * 4 + i];
            float4 b4 = *reinterpret_cast<const float4*>(&Bs[k][tx * 4]);
            const float b[4] = {b4.x, b4.y, b4.z, b4.w};
            #pragma unroll
            for (int i = 0; i < 4; i++)
                #pragma unroll
                for (int j = 0; j < 4; j++)
                    acc[i][j] = fmaf(a[i], b[j], acc[i][j]);
        }
        __syncthreads();
    }

    #pragma unroll
    for (int i = 0; i < 4; i++) {
        const int m = m0 + ty * 4 + i;
        #pragma unroll
        for (int j = 0; j < 4; j++) {
            const int n = n0 + tx * 4 + j;
            C[(size_t)m * N + n] = acc[i][j] + bias[n];
        }
    }
}

// ---------------------------------------------------------------------------
// Flash attention with relative-positional term folded into the K tile:
//   K_eff[t,d] = kh[b,h,t,d] + k_pe[h,d,t]
//   scores = (Q @ K_eff^T) * (1/sqrt(d_k)); online softmax; O = P @ V.
// One block = (b, h, 64-query tile). 256 threads, 4x4 per thread.
// ---------------------------------------------------------------------------
#define AQ 64
#define AK 64
#define SM_Q 0
#define SM_K (64 * 65)
#define SM_P (2 * 64 * 65)
#define SM_V (3 * 64 * 65)
#define ATTN_SMEM_FLOATS (3 * 64 * 65 + 64 * 64)
#define ATTN_SMEM_BYTES  (ATTN_SMEM_FLOATS * 4)

__global__ __launch_bounds__(256) void attn_kernel(
    const float* __restrict__ pe)   // k_pe [H, DK, S]
{
    extern __shared__ float sm[];
    float* Qs = sm + SM_Q;   // [64][65]
    float* Ks = sm + SM_K;   // [64][65]
    float* Ps = sm + SM_P;   // [64][65]
    float* Vs = sm + SM_V;   // [64][64]

    const int b  = blockIdx.z;
    const int h  = blockIdx.y;
    const int q0 = blockIdx.x * AQ;
    const int tid = threadIdx.x;
    const int ty  = tid >> 4;
    const int tx  = tid & 15;

    // Load Q tile: 64 rows x 64 dims
    const float* qbase = g_q + ((size_t)b * S_ + q0) * D_ + h * DK_;
    #pragma unroll
    for (int i = 0; i < (AQ * DK_) / 256; i++) {
        int idx = tid + i * 256;
        int r = idx >> 6, c = idx & 63;
        Qs[r * 65 + c] = qbase[(size_t)r * D_ + c];
    }

    float m_i[4], l_i[4], o[4][4];
    #pragma unroll
    for (int i = 0; i < 4; i++) {
        m_i[i] = -1e30f;
        l_i[i] = 0.f;
        #pragma unroll
        for (int j = 0; j < 4; j++) o[i][j] = 0.f;
    }

    const float scale = 0.125f;   // 1/sqrt(64)

    for (int t0 = 0; t0 < S_; t0 += AK) {
        const float* kbase  = g_k + ((size_t)b * S_ + t0) * D_ + h * DK_;
        const float* vbase  = g_v + ((size_t)b * S_ + t0) * D_ + h * DK_;
        const float* pebase = pe + (size_t)h * DK_ * S_ + t0;

        __syncthreads();   // previous iteration done with Ks/Vs/Ps
        #pragma unroll
        for (int i = 0; i < 16; i++) {
            int idx = tid + i * 256;
            int r = idx >> 6, c = idx & 63;
            Ks[r * 65 + c] = kbase[(size_t)r * D_ + c];
            Vs[r * 64 + c] = vbase[(size_t)r * D_ + c];
        }
        __syncthreads();
        // Fold positional keys in: Ks[j][d] += pe[h][d][t0+j]  (coalesced over j)
        #pragma unroll
        for (int i = 0; i < 16; i++) {
            int idx = tid + i * 256;
            int d = idx >> 6, j = idx & 63;
            Ks[j * 65 + d] += pebase[(size_t)d * S_ + j];
        }
        __syncthreads();

        // S = Q @ K_eff^T
        float s[4][4] = {};
        #pragma unroll
        for (int d = 0; d < DK_; d++) {
            float qv[4], kv[4];
            #pragma unroll
            for (int i = 0; i < 4; i++) qv[i] = Qs[(ty * 4 + i) * 65 + d];
            #pragma unroll
            for (int j = 0; j < 4; j++) kv[j] = Ks[(tx * 4 + j) * 65 + d];
            #pragma unroll
            for (int i = 0; i < 4; i++)
                #pragma unroll
                for (int j = 0; j < 4; j++)
                    s[i][j] = fmaf(qv[i], kv[j], s[i][j]);
        }
        #pragma unroll
        for (int i = 0; i < 4; i++)
            #pragma unroll
            for (int j = 0; j < 4; j++)
                s[i][j] *= scale;

        // Online softmax (row stats reduced across the 16-lane tx group)
        #pragma unroll
        for (int i = 0; i < 4; i++) {
            float mx = fmaxf(fmaxf(s[i][0], s[i][1]), fmaxf(s[i][2], s[i][3]));
            #pragma unroll
            for (int off = 8; off > 0; off >>= 1)
                mx = fmaxf(mx, __shfl_xor_sync(0xffffffffu, mx, off));
            float mnew = fmaxf(m_i[i], mx);
            float corr = __expf(m_i[i] - mnew);
            m_i[i] = mnew;

            float rs = 0.f;
            #pragma unroll
            for (int j = 0; j < 4; j++) {
                float p = __expf(s[i][j] - mnew);
                Ps[(ty * 4 + i) * 65 + (tx * 4 + j)] = p;
                rs += p;
            }
            #pragma unroll
            for (int off = 8; off > 0; off >>= 1)
                rs += __shfl_xor_sync(0xffffffffu, rs, off);
            l_i[i] = l_i[i] * corr + rs;
            #pragma unroll
            for (int j = 0; j < 4; j++) o[i][j] *= corr;
        }
        __syncthreads();   // Ps visible to all

        // O += P @ V
        #pragma unroll
        for (int t = 0; t < AK; t++) {
            float pv[4];
            #pragma unroll
            for (int i = 0; i < 4; i++) pv[i] = Ps[(ty * 4 + i) * 65 + t];
            float4 v4 = *reinterpret_cast<const float4*>(&Vs[t * 64 + tx * 4]);
            const float vv[4] = {v4.x, v4.y, v4.z, v4.w};
            #pragma unroll
            for (int i = 0; i < 4; i++)
                #pragma unroll
                for (int j = 0; j < 4; j++)
                    o[i][j] = fmaf(pv[i], vv[j], o[i][j]);
        }
    }

    // Normalize and store in [B, S, H*DK] layout (ready for the O-projection)
    float* obase = g_ao + ((size_t)b * S_ + q0) * D_ + h * DK_;
    #pragma unroll
    for (int i = 0; i < 4; i++) {
        const float inv = 1.f / l_i[i];
        #pragma unroll
        for (int j = 0; j < 4; j++)
            obase[(size_t)(ty * 4 + i) * D_ + tx * 4 + j] = o[i][j] * inv;
    }
}

// ---------------------------------------------------------------------------
extern "C" void kernel_launch(void* const* d_in, const int* in_sizes, int n_in,
                              void* d_out, int out_size)
{
    const float* q  = (const float*)d_in[0];
    const float* k  = (const float*)d_in[1];
    const float* v  = (const float*)d_in[2];
    const float* pe = (const float*)d_in[3];
    const float* Wq = (const float*)d_in[4];
    const float* bq = (const float*)d_in[5];
    const float* Wk = (const float*)d_in[6];
    const float* bk = (const float*)d_in[7];
    const float* Wv = (const float*)d_in[8];
    const float* bv = (const float*)d_in[9];
    const float* Wo = (const float*)d_in[10];
    const float* bo = (const float*)d_in[11];
    float* out = (float*)d_out;

    float *pq, *pk, *pvv, *pao;
    cudaGetSymbolAddress((void**)&pq,  g_q);
    cudaGetSymbolAddress((void**)&pk,  g_k);
    cudaGetSymbolAddress((void**)&pvv, g_v);
    cudaGetSymbolAddress((void**)&pao, g_ao);

    cudaFuncSetAttribute(attn_kernel,
                         cudaFuncAttributeMaxDynamicSharedMemorySize,
                         ATTN_SMEM_BYTES);

    dim3 gg(D_ / 64, M_ / 64);   // (16, 64)
    gemm_bias_kernel<<<gg, 256>>>(q, Wq, bq, pq,  M_, D_, D_);
    gemm_bias_kernel<<<gg, 256>>>(k, Wk, bk, pk,  M_, D_, D_);
    gemm_bias_kernel<<<gg, 256>>>(v, Wv, bv, pvv, M_, D_, D_);

    attn_kernel<<<dim3(S_ / AQ, H_, B_), 256, ATTN_SMEM_BYTES>>>(pe);

    gemm_bias_kernel<<<gg, 256>>>(pao, Wo, bo, out, M_, D_, D_);
}

// round 5
// speedup vs baseline: 1.2589x; 1.2589x over previous
#include <cuda_runtime.h>
#include <cuda_bf16.h>
#include <cstdint>

#define B_  2
#define S_  2048
#define D_  1024
#define H_  16
#define DK_ 64
#define M_  (B_ * S_)   // 4096

// Scratch (allocation-free: __device__ globals)
__device__ float g_q [B_ * S_ * D_];
__device__ float g_k [B_ * S_ * D_];
__device__ float g_v [B_ * S_ * D_];
__device__ float g_ao[B_ * S_ * D_];
__device__ __nv_bfloat16 g_whi[4 * D_ * D_];   // transposed weights [N,K], hi part
__device__ __nv_bfloat16 g_wlo[4 * D_ * D_];   // transposed weights [N,K], lo part

__device__ __forceinline__ uint32_t pack_bf(float a, float b) {
    uint32_t ha = __bfloat16_as_ushort(__float2bfloat16_rn(a));
    uint32_t hb = __bfloat16_as_ushort(__float2bfloat16_rn(b));
    return ha | (hb << 16);
}

// m16n8k16 bf16 mma with fp32 accumulate (PTX ISA sm_80+, no arch suffix)
__device__ __forceinline__ void mma16816(float c[4], const uint32_t a[4],
                                         uint32_t b0, uint32_t b1) {
    asm volatile(
        "mma.sync.aligned.m16n8k16.row.col.f32.bf16.bf16.f32 "
        "{%0,%1,%2,%3}, {%4,%5,%6,%7}, {%8,%9}, {%0,%1,%2,%3};"
        : "+f"(c[0]), "+f"(c[1]), "+f"(c[2]), "+f"(c[3])
        : "r"(a[0]), "r"(a[1]), "r"(a[2]), "r"(a[3]), "r"(b0), "r"(b1));
}

// ===========================================================================
// Weight preprocessing: W[K,N] fp32 -> Wt_hi/Wt_lo [N,K] bf16
// ===========================================================================
__global__ __launch_bounds__(256) void split_transpose_kernel(
    const float* __restrict__ W,
    __nv_bfloat16* __restrict__ Th,
    __nv_bfloat16* __restrict__ Tl)
{
    __shared__ float t[32][33];
    const int tx = threadIdx.x, ty = threadIdx.y;
    const int n0 = blockIdx.x * 32, k0 = blockIdx.y * 32;
    #pragma unroll
    for (int i = 0; i < 4; i++)
        t[ty + i * 8][tx] = W[(size_t)(k0 + ty + i * 8) * D_ + n0 + tx];
    __syncthreads();
    #pragma unroll
    for (int i = 0; i < 4; i++) {
        float x = t[tx][ty + i * 8];
        __nv_bfloat16 hi = __float2bfloat16_rn(x);
        float lo = x - __bfloat162float(hi);
        size_t o = (size_t)(n0 + ty + i * 8) * D_ + k0 + tx;
        Th[o] = hi;
        Tl[o] = __float2bfloat16_rn(lo);
    }
}

// ===========================================================================
// mma.sync GEMM: C[M,1024] = A[M,1024] @ Wt^T + bias   (Wt [N,K] bf16 hi/lo)
// CTA tile 128x128, BK=32, 256 threads (8 warps, 4m x 2n, 32x64 per warp).
// 3-pass hi/lo: Ah*Bh + Ah*Bl + Al*Bh  (near-fp32 accuracy).
// ===========================================================================
#define PADK 56                              // bf16 per smem row (112B, 16B-aligned)
#define TILE_BYTES (128 * PADK * 2)          // 14336
#define SM_AH 0
#define SM_AL (1 * TILE_BYTES)
#define SM_BH (2 * TILE_BYTES)
#define SM_BL (3 * TILE_BYTES)
#define GEMM_SMEM (4 * TILE_BYTES)           // 57344 B

__global__ __launch_bounds__(256, 1)
void gemm_mma_kernel(const float* __restrict__ A,
                     const __nv_bfloat16* __restrict__ Bh,
                     const __nv_bfloat16* __restrict__ Bl,
                     const float* __restrict__ bias,
                     float* __restrict__ C)
{
    extern __shared__ char sm[];
    const int tid    = threadIdx.x;
    const int wid    = tid >> 5;
    const int lane   = tid & 31;
    const int gid    = lane >> 2;     // 0..7
    const int tg     = lane & 3;      // 0..3
    const int warp_m = wid & 3;       // 0..3  (32 rows each)
    const int warp_n = wid >> 2;      // 0..1  (64 cols each)
    const int n0 = blockIdx.x * 128;
    const int m0 = blockIdx.y * 128;

    float acc[2][8][4];
    #pragma unroll
    for (int mt = 0; mt < 2; mt++)
        #pragma unroll
        for (int nt = 0; nt < 8; nt++)
            #pragma unroll
            for (int i = 0; i < 4; i++) acc[mt][nt][i] = 0.f;

    // global->smem mappings
    const int ar = tid >> 1;                 // A row 0..127
    const int ac = (tid & 1) * 16;           // A col base (floats)
    const int bn = tid >> 1;                 // B row 0..127
    const int bk = (tid & 1) * 16;           // B col base (bf16)

    for (int k0 = 0; k0 < D_; k0 += 32) {
        __syncthreads();   // previous iteration's mma done with smem

        // ---- A tile [128 x 32] fp32 -> hi/lo bf16 ----
        {
            const float* ab = A + (size_t)(m0 + ar) * D_ + k0 + ac;
            #pragma unroll
            for (int i = 0; i < 4; i++) {
                float4 v = *reinterpret_cast<const float4*>(ab + i * 4);
                float hx = __bfloat162float(__float2bfloat16_rn(v.x));
                float hy = __bfloat162float(__float2bfloat16_rn(v.y));
                float hz = __bfloat162float(__float2bfloat16_rn(v.z));
                float hw = __bfloat162float(__float2bfloat16_rn(v.w));
                uint2 hi = make_uint2(pack_bf(v.x, v.y), pack_bf(v.z, v.w));
                uint2 lo = make_uint2(pack_bf(v.x - hx, v.y - hy),
                                      pack_bf(v.z - hz, v.w - hw));
                const int off = (ar * PADK + ac + i * 4) * 2;
                *reinterpret_cast<uint2*>(sm + SM_AH + off) = hi;
                *reinterpret_cast<uint2*>(sm + SM_AL + off) = lo;
            }
        }
        // ---- B tiles [128 x 32] bf16 hi/lo (pre-split, [N,K] row-major) ----
        {
            const __nv_bfloat16* bhb = Bh + (size_t)(n0 + bn) * D_ + k0 + bk;
            const __nv_bfloat16* blb = Bl + (size_t)(n0 + bn) * D_ + k0 + bk;
            #pragma unroll
            for (int j = 0; j < 2; j++) {
                uint4 vh = *reinterpret_cast<const uint4*>(bhb + j * 8);
                uint4 vl = *reinterpret_cast<const uint4*>(blb + j * 8);
                const int off = (bn * PADK + bk + j * 8) * 2;
                *reinterpret_cast<uint4*>(sm + SM_BH + off) = vh;
                *reinterpret_cast<uint4*>(sm + SM_BL + off) = vl;
            }
        }
        __syncthreads();

        #pragma unroll
        for (int ks = 0; ks < 2; ks++) {
            const int kk = ks * 16 + 2 * tg;
            // A fragments (hi & lo) for both 16-row subtiles
            uint32_t ah[2][4], al[2][4];
            #pragma unroll
            for (int mt = 0; mt < 2; mt++) {
                const int r = (warp_m * 32 + mt * 16 + gid) * PADK;
                ah[mt][0] = *reinterpret_cast<const uint32_t*>(sm + SM_AH + (r + kk) * 2);
                ah[mt][1] = *reinterpret_cast<const uint32_t*>(sm + SM_AH + (r + PADK * 8 + kk) * 2);
                ah[mt][2] = *reinterpret_cast<const uint32_t*>(sm + SM_AH + (r + kk + 8) * 2);
                ah[mt][3] = *reinterpret_cast<const uint32_t*>(sm + SM_AH + (r + PADK * 8 + kk + 8) * 2);
                al[mt][0] = *reinterpret_cast<const uint32_t*>(sm + SM_AL + (r + kk) * 2);
                al[mt][1] = *reinterpret_cast<const uint32_t*>(sm + SM_AL + (r + PADK * 8 + kk) * 2);
                al[mt][2] = *reinterpret_cast<const uint32_t*>(sm + SM_AL + (r + kk + 8) * 2);
                al[mt][3] = *reinterpret_cast<const uint32_t*>(sm + SM_AL + (r + PADK * 8 + kk + 8) * 2);
            }
            #pragma unroll
            for (int nt = 0; nt < 8; nt++) {
                const int rb = (warp_n * 64 + nt * 8 + gid) * PADK;
                uint32_t bh0 = *reinterpret_cast<const uint32_t*>(sm + SM_BH + (rb + kk) * 2);
                uint32_t bh1 = *reinterpret_cast<const uint32_t*>(sm + SM_BH + (rb + kk + 8) * 2);
                uint32_t bl0 = *reinterpret_cast<const uint32_t*>(sm + SM_BL + (rb + kk) * 2);
                uint32_t bl1 = *reinterpret_cast<const uint32_t*>(sm + SM_BL + (rb + kk + 8) * 2);
                #pragma unroll
                for (int mt = 0; mt < 2; mt++) {
                    mma16816(acc[mt][nt], ah[mt], bh0, bh1);
                    mma16816(acc[mt][nt], ah[mt], bl0, bl1);
                    mma16816(acc[mt][nt], al[mt], bh0, bh1);
                }
            }
        }
    }

    // ---- epilogue: acc -> gmem with bias ----
    #pragma unroll
    for (int mt = 0; mt < 2; mt++) {
        const int row = m0 + warp_m * 32 + mt * 16 + gid;
        #pragma unroll
        for (int nt = 0; nt < 8; nt++) {
            const int col = n0 + warp_n * 64 + nt * 8 + 2 * tg;
            const float bx = bias[col], by = bias[col + 1];
            float2 v0 = make_float2(acc[mt][nt][0] + bx, acc[mt][nt][1] + by);
            float2 v1 = make_float2(acc[mt][nt][2] + bx, acc[mt][nt][3] + by);
            *reinterpret_cast<float2*>(C + (size_t)row * D_ + col) = v0;
            *reinterpret_cast<float2*>(C + (size_t)(row + 8) * D_ + col) = v1;
        }
    }
}

// ===========================================================================
// Flash attention (proven round-2 version): PE folded into K tile, fp32 SIMT
// ===========================================================================
#define AQ 64
#define AK 64
#define SM_Q 0
#define SM_K (64 * 65)
#define SM_P (2 * 64 * 65)
#define SM_V (3 * 64 * 65)
#define ATTN_SMEM_FLOATS (3 * 64 * 65 + 64 * 64)
#define ATTN_SMEM_BYTES  (ATTN_SMEM_FLOATS * 4)

__global__ __launch_bounds__(256) void attn_kernel(
    const float* __restrict__ pe)   // k_pe [H, DK, S]
{
    extern __shared__ float smf[];
    float* Qs = smf + SM_Q;
    float* Ks = smf + SM_K;
    float* Ps = smf + SM_P;
    float* Vs = smf + SM_V;

    const int b  = blockIdx.z;
    const int h  = blockIdx.y;
    const int q0 = blockIdx.x * AQ;
    const int tid = threadIdx.x;
    const int ty  = tid >> 4;
    const int tx  = tid & 15;

    const float* qbase = g_q + ((size_t)b * S_ + q0) * D_ + h * DK_;
    #pragma unroll
    for (int i = 0; i < (AQ * DK_) / 256; i++) {
        int idx = tid + i * 256;
        int r = idx >> 6, c = idx & 63;
        Qs[r * 65 + c] = qbase[(size_t)r * D_ + c];
    }

    float m_i[4], l_i[4], o[4][4];
    #pragma unroll
    for (int i = 0; i < 4; i++) {
        m_i[i] = -1e30f;
        l_i[i] = 0.f;
        #pragma unroll
        for (int j = 0; j < 4; j++) o[i][j] = 0.f;
    }

    const float scale = 0.125f;

    for (int t0 = 0; t0 < S_; t0 += AK) {
        const float* kbase  = g_k + ((size_t)b * S_ + t0) * D_ + h * DK_;
        const float* vbase  = g_v + ((size_t)b * S_ + t0) * D_ + h * DK_;
        const float* pebase = pe + (size_t)h * DK_ * S_ + t0;

        __syncthreads();
        #pragma unroll
        for (int i = 0; i < 16; i++) {
            int idx = tid + i * 256;
            int r = idx >> 6, c = idx & 63;
            Ks[r * 65 + c] = kbase[(size_t)r * D_ + c];
            Vs[r * 64 + c] = vbase[(size_t)r * D_ + c];
        }
        __syncthreads();
        #pragma unroll
        for (int i = 0; i < 16; i++) {
            int idx = tid + i * 256;
            int d = idx >> 6, j = idx & 63;
            Ks[j * 65 + d] += pebase[(size_t)d * S_ + j];
        }
        __syncthreads();

        float s[4][4] = {};
        #pragma unroll
        for (int d = 0; d < DK_; d++) {
            float qv[4], kv[4];
            #pragma unroll
            for (int i = 0; i < 4; i++) qv[i] = Qs[(ty * 4 + i) * 65 + d];
            #pragma unroll
            for (int j = 0; j < 4; j++) kv[j] = Ks[(tx * 4 + j) * 65 + d];
            #pragma unroll
            for (int i = 0; i < 4; i++)
                #pragma unroll
                for (int j = 0; j < 4; j++)
                    s[i][j] = fmaf(qv[i], kv[j], s[i][j]);
        }
        #pragma unroll
        for (int i = 0; i < 4; i++)
            #pragma unroll
            for (int j = 0; j < 4; j++)
                s[i][j] *= scale;

        #pragma unroll
        for (int i = 0; i < 4; i++) {
            float mx = fmaxf(fmaxf(s[i][0], s[i][1]), fmaxf(s[i][2], s[i][3]));
            #pragma unroll
            for (int off = 8; off > 0; off >>= 1)
                mx = fmaxf(mx, __shfl_xor_sync(0xffffffffu, mx, off));
            float mnew = fmaxf(m_i[i], mx);
            float corr = __expf(m_i[i] - mnew);
            m_i[i] = mnew;

            float rs = 0.f;
            #pragma unroll
            for (int j = 0; j < 4; j++) {
                float p = __expf(s[i][j] - mnew);
                Ps[(ty * 4 + i) * 65 + (tx * 4 + j)] = p;
                rs += p;
            }
            #pragma unroll
            for (int off = 8; off > 0; off >>= 1)
                rs += __shfl_xor_sync(0xffffffffu, rs, off);
            l_i[i] = l_i[i] * corr + rs;
            #pragma unroll
            for (int j = 0; j < 4; j++) o[i][j] *= corr;
        }
        __syncthreads();

        #pragma unroll
        for (int t = 0; t < AK; t++) {
            float pv[4];
            #pragma unroll
            for (int i = 0; i < 4; i++) pv[i] = Ps[(ty * 4 + i) * 65 + t];
            float4 v4 = *reinterpret_cast<const float4*>(&Vs[t * 64 + tx * 4]);
            const float vv[4] = {v4.x, v4.y, v4.z, v4.w};
            #pragma unroll
            for (int i = 0; i < 4; i++)
                #pragma unroll
                for (int j = 0; j < 4; j++)
                    o[i][j] = fmaf(pv[i], vv[j], o[i][j]);
        }
    }

    float* obase = g_ao + ((size_t)b * S_ + q0) * D_ + h * DK_;
    #pragma unroll
    for (int i = 0; i < 4; i++) {
        const float inv = 1.f / l_i[i];
        #pragma unroll
        for (int j = 0; j < 4; j++)
            obase[(size_t)(ty * 4 + i) * D_ + tx * 4 + j] = o[i][j] * inv;
    }
}

// ===========================================================================
extern "C" void kernel_launch(void* const* d_in, const int* in_sizes, int n_in,
                              void* d_out, int out_size)
{
    const float* q  = (const float*)d_in[0];
    const float* k  = (const float*)d_in[1];
    const float* v  = (const float*)d_in[2];
    const float* pe = (const float*)d_in[3];
    const float* Wq = (const float*)d_in[4];
    const float* bq = (const float*)d_in[5];
    const float* Wk = (const float*)d_in[6];
    const float* bk = (const float*)d_in[7];
    const float* Wv = (const float*)d_in[8];
    const float* bv = (const float*)d_in[9];
    const float* Wo = (const float*)d_in[10];
    const float* bo = (const float*)d_in[11];
    float* out = (float*)d_out;

    float *pq, *pk, *pvv, *pao;
    __nv_bfloat16 *whi, *wlo;
    cudaGetSymbolAddress((void**)&pq,  g_q);
    cudaGetSymbolAddress((void**)&pk,  g_k);
    cudaGetSymbolAddress((void**)&pvv, g_v);
    cudaGetSymbolAddress((void**)&pao, g_ao);
    cudaGetSymbolAddress((void**)&whi, g_whi);
    cudaGetSymbolAddress((void**)&wlo, g_wlo);

    cudaFuncSetAttribute(gemm_mma_kernel,
                         cudaFuncAttributeMaxDynamicSharedMemorySize, GEMM_SMEM);
    cudaFuncSetAttribute(attn_kernel,
                         cudaFuncAttributeMaxDynamicSharedMemorySize, ATTN_SMEM_BYTES);

    // 1) weight transpose + hi/lo split
    dim3 tb(32, 8), tg(D_ / 32, D_ / 32);
    split_transpose_kernel<<<tg, tb>>>(Wq, whi + 0 * D_ * D_, wlo + 0 * D_ * D_);
    split_transpose_kernel<<<tg, tb>>>(Wk, whi + 1 * D_ * D_, wlo + 1 * D_ * D_);
    split_transpose_kernel<<<tg, tb>>>(Wv, whi + 2 * D_ * D_, wlo + 2 * D_ * D_);
    split_transpose_kernel<<<tg, tb>>>(Wo, whi + 3 * D_ * D_, wlo + 3 * D_ * D_);

    // 2) Q/K/V projections on tensor cores (mma.sync)
    dim3 gg(D_ / 128, M_ / 128);   // (8, 32)
    gemm_mma_kernel<<<gg, 256, GEMM_SMEM>>>(q, whi + 0 * D_ * D_, wlo + 0 * D_ * D_, bq, pq);
    gemm_mma_kernel<<<gg, 256, GEMM_SMEM>>>(k, whi + 1 * D_ * D_, wlo + 1 * D_ * D_, bk, pk);
    gemm_mma_kernel<<<gg, 256, GEMM_SMEM>>>(v, whi + 2 * D_ * D_, wlo + 2 * D_ * D_, bv, pvv);

    // 3) attention (SIMT, unchanged)
    attn_kernel<<<dim3(S_ / AQ, H_, B_), 256, ATTN_SMEM_BYTES>>>(pe);

    // 4) output projection on tensor cores
    gemm_mma_kernel<<<gg, 256, GEMM_SMEM>>>(pao, whi + 3 * D_ * D_, wlo + 3 * D_ * D_, bo, out);
}

// round 6
// speedup vs baseline: 1.6502x; 1.3109x over previous
#include <cuda_runtime.h>
#include <cuda_bf16.h>
#include <cstdint>

#define B_  2
#define S_  2048
#define D_  1024
#define H_  16
#define DK_ 64
#define M_  (B_ * S_)   // 4096

// Scratch (allocation-free: __device__ globals)
__device__ float g_q [B_ * S_ * D_];
__device__ float g_k [B_ * S_ * D_];
__device__ float g_v [B_ * S_ * D_];
__device__ float g_ao[B_ * S_ * D_];
__device__ __nv_bfloat16 g_whi[4 * D_ * D_];   // transposed weights [N,K], hi part
__device__ __nv_bfloat16 g_wlo[4 * D_ * D_];   // transposed weights [N,K], lo part

__device__ __forceinline__ uint32_t pack_bf(float a, float b) {
    uint32_t ha = __bfloat16_as_ushort(__float2bfloat16_rn(a));
    uint32_t hb = __bfloat16_as_ushort(__float2bfloat16_rn(b));
    return ha | (hb << 16);
}
// pack hi parts, emit lo parts
__device__ __forceinline__ uint32_t pack_hilo(float a, float b, uint32_t& lo) {
    __nv_bfloat16 ha = __float2bfloat16_rn(a);
    __nv_bfloat16 hb = __float2bfloat16_rn(b);
    lo = pack_bf(a - __bfloat162float(ha), b - __bfloat162float(hb));
    return (uint32_t)__bfloat16_as_ushort(ha) |
           ((uint32_t)__bfloat16_as_ushort(hb) << 16);
}

// m16n8k16 bf16 mma with fp32 accumulate (PTX ISA sm_80+, no arch suffix)
__device__ __forceinline__ void mma16816(float c[4], const uint32_t a[4],
                                         uint32_t b0, uint32_t b1) {
    asm volatile(
        "mma.sync.aligned.m16n8k16.row.col.f32.bf16.bf16.f32 "
        "{%0,%1,%2,%3}, {%4,%5,%6,%7}, {%8,%9}, {%0,%1,%2,%3};"
        : "+f"(c[0]), "+f"(c[1]), "+f"(c[2]), "+f"(c[3])
        : "r"(a[0]), "r"(a[1]), "r"(a[2]), "r"(a[3]), "r"(b0), "r"(b1));
}

// ===========================================================================
// Weight preprocessing: W[K,N] fp32 -> Wt_hi/Wt_lo [N,K] bf16
// ===========================================================================
__global__ __launch_bounds__(256) void split_transpose_kernel(
    const float* __restrict__ W,
    __nv_bfloat16* __restrict__ Th,
    __nv_bfloat16* __restrict__ Tl)
{
    __shared__ float t[32][33];
    const int tx = threadIdx.x, ty = threadIdx.y;
    const int n0 = blockIdx.x * 32, k0 = blockIdx.y * 32;
    #pragma unroll
    for (int i = 0; i < 4; i++)
        t[ty + i * 8][tx] = W[(size_t)(k0 + ty + i * 8) * D_ + n0 + tx];
    __syncthreads();
    #pragma unroll
    for (int i = 0; i < 4; i++) {
        float x = t[tx][ty + i * 8];
        __nv_bfloat16 hi = __float2bfloat16_rn(x);
        float lo = x - __bfloat162float(hi);
        size_t o = (size_t)(n0 + ty + i * 8) * D_ + k0 + tx;
        Th[o] = hi;
        Tl[o] = __float2bfloat16_rn(lo);
    }
}

// ===========================================================================
// mma.sync GEMM (unchanged from round 5, proven)
// ===========================================================================
#define PADK 56
#define TILE_BYTES (128 * PADK * 2)
#define SM_AH 0
#define SM_AL (1 * TILE_BYTES)
#define SM_BH (2 * TILE_BYTES)
#define SM_BL (3 * TILE_BYTES)
#define GEMM_SMEM (4 * TILE_BYTES)

__global__ __launch_bounds__(256, 1)
void gemm_mma_kernel(const float* __restrict__ A,
                     const __nv_bfloat16* __restrict__ Bh,
                     const __nv_bfloat16* __restrict__ Bl,
                     const float* __restrict__ bias,
                     float* __restrict__ C)
{
    extern __shared__ char sm[];
    const int tid    = threadIdx.x;
    const int wid    = tid >> 5;
    const int lane   = tid & 31;
    const int gid    = lane >> 2;
    const int tg     = lane & 3;
    const int warp_m = wid & 3;
    const int warp_n = wid >> 2;
    const int n0 = blockIdx.x * 128;
    const int m0 = blockIdx.y * 128;

    float acc[2][8][4];
    #pragma unroll
    for (int mt = 0; mt < 2; mt++)
        #pragma unroll
        for (int nt = 0; nt < 8; nt++)
            #pragma unroll
            for (int i = 0; i < 4; i++) acc[mt][nt][i] = 0.f;

    const int ar = tid >> 1;
    const int ac = (tid & 1) * 16;
    const int bn = tid >> 1;
    const int bk = (tid & 1) * 16;

    for (int k0 = 0; k0 < D_; k0 += 32) {
        __syncthreads();
        {
            const float* ab = A + (size_t)(m0 + ar) * D_ + k0 + ac;
            #pragma unroll
            for (int i = 0; i < 4; i++) {
                float4 v = *reinterpret_cast<const float4*>(ab + i * 4);
                uint32_t lx, ly;
                uint2 hi, lo;
                hi.x = pack_hilo(v.x, v.y, lx);
                hi.y = pack_hilo(v.z, v.w, ly);
                lo.x = lx; lo.y = ly;
                const int off = (ar * PADK + ac + i * 4) * 2;
                *reinterpret_cast<uint2*>(sm + SM_AH + off) = hi;
                *reinterpret_cast<uint2*>(sm + SM_AL + off) = lo;
            }
        }
        {
            const __nv_bfloat16* bhb = Bh + (size_t)(n0 + bn) * D_ + k0 + bk;
            const __nv_bfloat16* blb = Bl + (size_t)(n0 + bn) * D_ + k0 + bk;
            #pragma unroll
            for (int j = 0; j < 2; j++) {
                uint4 vh = *reinterpret_cast<const uint4*>(bhb + j * 8);
                uint4 vl = *reinterpret_cast<const uint4*>(blb + j * 8);
                const int off = (bn * PADK + bk + j * 8) * 2;
                *reinterpret_cast<uint4*>(sm + SM_BH + off) = vh;
                *reinterpret_cast<uint4*>(sm + SM_BL + off) = vl;
            }
        }
        __syncthreads();

        #pragma unroll
        for (int ks = 0; ks < 2; ks++) {
            const int kk = ks * 16 + 2 * tg;
            uint32_t ah[2][4], al[2][4];
            #pragma unroll
            for (int mt = 0; mt < 2; mt++) {
                const int r = (warp_m * 32 + mt * 16 + gid) * PADK;
                ah[mt][0] = *reinterpret_cast<const uint32_t*>(sm + SM_AH + (r + kk) * 2);
                ah[mt][1] = *reinterpret_cast<const uint32_t*>(sm + SM_AH + (r + PADK * 8 + kk) * 2);
                ah[mt][2] = *reinterpret_cast<const uint32_t*>(sm + SM_AH + (r + kk + 8) * 2);
                ah[mt][3] = *reinterpret_cast<const uint32_t*>(sm + SM_AH + (r + PADK * 8 + kk + 8) * 2);
                al[mt][0] = *reinterpret_cast<const uint32_t*>(sm + SM_AL + (r + kk) * 2);
                al[mt][1] = *reinterpret_cast<const uint32_t*>(sm + SM_AL + (r + PADK * 8 + kk) * 2);
                al[mt][2] = *reinterpret_cast<const uint32_t*>(sm + SM_AL + (r + kk + 8) * 2);
                al[mt][3] = *reinterpret_cast<const uint32_t*>(sm + SM_AL + (r + PADK * 8 + kk + 8) * 2);
            }
            #pragma unroll
            for (int nt = 0; nt < 8; nt++) {
                const int rb = (warp_n * 64 + nt * 8 + gid) * PADK;
                uint32_t bh0 = *reinterpret_cast<const uint32_t*>(sm + SM_BH + (rb + kk) * 2);
                uint32_t bh1 = *reinterpret_cast<const uint32_t*>(sm + SM_BH + (rb + kk + 8) * 2);
                uint32_t bl0 = *reinterpret_cast<const uint32_t*>(sm + SM_BL + (rb + kk) * 2);
                uint32_t bl1 = *reinterpret_cast<const uint32_t*>(sm + SM_BL + (rb + kk + 8) * 2);
                #pragma unroll
                for (int mt = 0; mt < 2; mt++) {
                    mma16816(acc[mt][nt], ah[mt], bh0, bh1);
                    mma16816(acc[mt][nt], ah[mt], bl0, bl1);
                    mma16816(acc[mt][nt], al[mt], bh0, bh1);
                }
            }
        }
    }

    #pragma unroll
    for (int mt = 0; mt < 2; mt++) {
        const int row = m0 + warp_m * 32 + mt * 16 + gid;
        #pragma unroll
        for (int nt = 0; nt < 8; nt++) {
            const int col = n0 + warp_n * 64 + nt * 8 + 2 * tg;
            const float bx = bias[col], by = bias[col + 1];
            float2 v0 = make_float2(acc[mt][nt][0] + bx, acc[mt][nt][1] + by);
            float2 v1 = make_float2(acc[mt][nt][2] + bx, acc[mt][nt][3] + by);
            *reinterpret_cast<float2*>(C + (size_t)row * D_ + col) = v0;
            *reinterpret_cast<float2*>(C + (size_t)(row + 8) * D_ + col) = v1;
        }
    }
}

// ===========================================================================
// mma.sync flash attention.
// Block = (b, h, 128-query tile). 8 warps x 16 query rows. KV tile = 64.
// K_eff = K + PE folded at load (fp32), hi/lo split. 3-pass mma everywhere.
// P stays in registers (S-accum fragment == A-operand fragment layout).
// ===========================================================================
#define APAD 72                                   // bf16 per smem row
#define AQT  128
#define AKT  64
#define SA_QH 0
#define SA_QL (SA_QH + AQT * APAD * 2)            // 18432
#define SA_KH (SA_QL + AQT * APAD * 2)            // 36864
#define SA_KL (SA_KH + AKT * APAD * 2)            // 46080
#define SA_VH (SA_KL + AKT * APAD * 2)            // 55296
#define SA_VL (SA_VH + AKT * APAD * 2)            // 64512
#define ATTN_SMEM (SA_VL + AKT * APAD * 2)        // 73728

__global__ __launch_bounds__(256, 1)
void attn_mma_kernel(const float* __restrict__ pe)   // k_pe [H, DK, S]
{
    extern __shared__ char sm[];
    const int b   = blockIdx.z;
    const int h   = blockIdx.y;
    const int q0  = blockIdx.x * AQT;
    const int tid = threadIdx.x;
    const int wid = tid >> 5;
    const int lane = tid & 31;
    const int g    = lane >> 2;     // 0..7
    const int tg   = lane & 3;      // 0..3

    const int d4   = (tid & 15) * 4;     // 0..60
    const int rowb = tid >> 4;           // 0..15

    // ---- load Q tile [128 x 64] fp32 -> hi/lo bf16 smem (once) ----
    {
        const float* qb = g_q + ((size_t)b * S_ + q0) * D_ + h * DK_;
        #pragma unroll
        for (int i = 0; i < 8; i++) {
            const int r = rowb + 16 * i;
            float4 v = *reinterpret_cast<const float4*>(qb + (size_t)r * D_ + d4);
            uint32_t lx, ly;
            uint2 hi, lo;
            hi.x = pack_hilo(v.x, v.y, lx);
            hi.y = pack_hilo(v.z, v.w, ly);
            lo.x = lx; lo.y = ly;
            const int off = (r * APAD + d4) * 2;
            *reinterpret_cast<uint2*>(sm + SA_QH + off) = hi;
            *reinterpret_cast<uint2*>(sm + SA_QL + off) = lo;
        }
    }

    float m_[2] = {-1e30f, -1e30f};
    float l_[2] = {0.f, 0.f};
    float o[8][4];
    #pragma unroll
    for (int nt = 0; nt < 8; nt++)
        #pragma unroll
        for (int i = 0; i < 4; i++) o[nt][i] = 0.f;

    const float* peb = pe + (size_t)h * DK_ * S_;

    for (int t0 = 0; t0 < S_; t0 += AKT) {
        __syncthreads();   // everyone done reading K/V from prev iter

        // ---- K_eff = K + PE, hi/lo -> smem ; V hi/lo -> smem ----
        {
            const float* kb = g_k + ((size_t)b * S_ + t0) * D_ + h * DK_;
            const float* vb = g_v + ((size_t)b * S_ + t0) * D_ + h * DK_;
            #pragma unroll
            for (int i = 0; i < 4; i++) {
                const int key = rowb + 16 * i;
                float4 kv = *reinterpret_cast<const float4*>(kb + (size_t)key * D_ + d4);
                kv.x += peb[(size_t)(d4 + 0) * S_ + t0 + key];
                kv.y += peb[(size_t)(d4 + 1) * S_ + t0 + key];
                kv.z += peb[(size_t)(d4 + 2) * S_ + t0 + key];
                kv.w += peb[(size_t)(d4 + 3) * S_ + t0 + key];
                uint32_t lx, ly;
                uint2 hi, lo;
                hi.x = pack_hilo(kv.x, kv.y, lx);
                hi.y = pack_hilo(kv.z, kv.w, ly);
                lo.x = lx; lo.y = ly;
                const int off = (key * APAD + d4) * 2;
                *reinterpret_cast<uint2*>(sm + SA_KH + off) = hi;
                *reinterpret_cast<uint2*>(sm + SA_KL + off) = lo;

                float4 vv = *reinterpret_cast<const float4*>(vb + (size_t)key * D_ + d4);
                hi.x = pack_hilo(vv.x, vv.y, lx);
                hi.y = pack_hilo(vv.z, vv.w, ly);
                lo.x = lx; lo.y = ly;
                *reinterpret_cast<uint2*>(sm + SA_VH + off) = hi;
                *reinterpret_cast<uint2*>(sm + SA_VL + off) = lo;
            }
        }
        __syncthreads();

        // ---- S = Q @ K_eff^T (3-pass hi/lo) ----
        float s[8][4];
        #pragma unroll
        for (int nt = 0; nt < 8; nt++)
            #pragma unroll
            for (int i = 0; i < 4; i++) s[nt][i] = 0.f;

        #pragma unroll
        for (int ks = 0; ks < 4; ks++) {
            const int kk = ks * 16 + 2 * tg;
            const int r = (wid * 16 + g) * APAD;
            uint32_t qh[4], ql[4];
            qh[0] = *reinterpret_cast<const uint32_t*>(sm + SA_QH + (r + kk) * 2);
            qh[1] = *reinterpret_cast<const uint32_t*>(sm + SA_QH + (r + APAD * 8 + kk) * 2);
            qh[2] = *reinterpret_cast<const uint32_t*>(sm + SA_QH + (r + kk + 8) * 2);
            qh[3] = *reinterpret_cast<const uint32_t*>(sm + SA_QH + (r + APAD * 8 + kk + 8) * 2);
            ql[0] = *reinterpret_cast<const uint32_t*>(sm + SA_QL + (r + kk) * 2);
            ql[1] = *reinterpret_cast<const uint32_t*>(sm + SA_QL + (r + APAD * 8 + kk) * 2);
            ql[2] = *reinterpret_cast<const uint32_t*>(sm + SA_QL + (r + kk + 8) * 2);
            ql[3] = *reinterpret_cast<const uint32_t*>(sm + SA_QL + (r + APAD * 8 + kk + 8) * 2);
            #pragma unroll
            for (int nt = 0; nt < 8; nt++) {
                const int rb = (nt * 8 + g) * APAD;
                uint32_t kh0 = *reinterpret_cast<const uint32_t*>(sm + SA_KH + (rb + kk) * 2);
                uint32_t kh1 = *reinterpret_cast<const uint32_t*>(sm + SA_KH + (rb + kk + 8) * 2);
                uint32_t kl0 = *reinterpret_cast<const uint32_t*>(sm + SA_KL + (rb + kk) * 2);
                uint32_t kl1 = *reinterpret_cast<const uint32_t*>(sm + SA_KL + (rb + kk + 8) * 2);
                mma16816(s[nt], qh, kh0, kh1);
                mma16816(s[nt], qh, kl0, kl1);
                mma16816(s[nt], ql, kh0, kh1);
            }
        }

        // ---- online softmax on fragments (rows g and g+8) ----
        float mx0 = -1e30f, mx1 = -1e30f;
        #pragma unroll
        for (int nt = 0; nt < 8; nt++) {
            #pragma unroll
            for (int i = 0; i < 4; i++) s[nt][i] *= 0.125f;
            mx0 = fmaxf(mx0, fmaxf(s[nt][0], s[nt][1]));
            mx1 = fmaxf(mx1, fmaxf(s[nt][2], s[nt][3]));
        }
        mx0 = fmaxf(mx0, __shfl_xor_sync(0xffffffffu, mx0, 1));
        mx0 = fmaxf(mx0, __shfl_xor_sync(0xffffffffu, mx0, 2));
        mx1 = fmaxf(mx1, __shfl_xor_sync(0xffffffffu, mx1, 1));
        mx1 = fmaxf(mx1, __shfl_xor_sync(0xffffffffu, mx1, 2));

        const float mn0 = fmaxf(m_[0], mx0);
        const float mn1 = fmaxf(m_[1], mx1);
        const float c0 = __expf(m_[0] - mn0);
        const float c1 = __expf(m_[1] - mn1);
        m_[0] = mn0; m_[1] = mn1;

        float r0 = 0.f, r1 = 0.f;
        #pragma unroll
        for (int nt = 0; nt < 8; nt++) {
            s[nt][0] = __expf(s[nt][0] - mn0);
            s[nt][1] = __expf(s[nt][1] - mn0);
            s[nt][2] = __expf(s[nt][2] - mn1);
            s[nt][3] = __expf(s[nt][3] - mn1);
            r0 += s[nt][0] + s[nt][1];
            r1 += s[nt][2] + s[nt][3];
        }
        r0 += __shfl_xor_sync(0xffffffffu, r0, 1);
        r0 += __shfl_xor_sync(0xffffffffu, r0, 2);
        r1 += __shfl_xor_sync(0xffffffffu, r1, 1);
        r1 += __shfl_xor_sync(0xffffffffu, r1, 2);
        l_[0] = l_[0] * c0 + r0;
        l_[1] = l_[1] * c1 + r1;

        #pragma unroll
        for (int nt = 0; nt < 8; nt++) {
            o[nt][0] *= c0; o[nt][1] *= c0;
            o[nt][2] *= c1; o[nt][3] *= c1;
        }

        // ---- O += P @ V  (P from regs, 3-pass hi/lo) ----
        #pragma unroll
        for (int jp = 0; jp < 4; jp++) {
            uint32_t ph[4], pl[4];
            ph[0] = pack_hilo(s[2 * jp][0],     s[2 * jp][1],     pl[0]);
            ph[1] = pack_hilo(s[2 * jp][2],     s[2 * jp][3],     pl[1]);
            ph[2] = pack_hilo(s[2 * jp + 1][0], s[2 * jp + 1][1], pl[2]);
            ph[3] = pack_hilo(s[2 * jp + 1][2], s[2 * jp + 1][3], pl[3]);
            const int k0 = jp * 16 + 2 * tg;
            #pragma unroll
            for (int nt = 0; nt < 8; nt++) {
                const int dim = nt * 8 + g;
                uint32_t a0 = *reinterpret_cast<const uint16_t*>(sm + SA_VH + ((k0 + 0) * APAD + dim) * 2);
                uint32_t a1 = *reinterpret_cast<const uint16_t*>(sm + SA_VH + ((k0 + 1) * APAD + dim) * 2);
                uint32_t a2 = *reinterpret_cast<const uint16_t*>(sm + SA_VH + ((k0 + 8) * APAD + dim) * 2);
                uint32_t a3 = *reinterpret_cast<const uint16_t*>(sm + SA_VH + ((k0 + 9) * APAD + dim) * 2);
                uint32_t vh0 = a0 | (a1 << 16);
                uint32_t vh1 = a2 | (a3 << 16);
                a0 = *reinterpret_cast<const uint16_t*>(sm + SA_VL + ((k0 + 0) * APAD + dim) * 2);
                a1 = *reinterpret_cast<const uint16_t*>(sm + SA_VL + ((k0 + 1) * APAD + dim) * 2);
                a2 = *reinterpret_cast<const uint16_t*>(sm + SA_VL + ((k0 + 8) * APAD + dim) * 2);
                a3 = *reinterpret_cast<const uint16_t*>(sm + SA_VL + ((k0 + 9) * APAD + dim) * 2);
                uint32_t vl0 = a0 | (a1 << 16);
                uint32_t vl1 = a2 | (a3 << 16);
                mma16816(o[nt], ph, vh0, vh1);
                mma16816(o[nt], ph, vl0, vl1);
                mma16816(o[nt], pl, vh0, vh1);
            }
        }
    }

    // ---- epilogue: normalize, store to g_ao [B,S,D] ----
    const float inv0 = 1.f / l_[0];
    const float inv1 = 1.f / l_[1];
    const int row = q0 + wid * 16 + g;
    float* ob = g_ao + ((size_t)b * S_ + row) * D_ + h * DK_;
    #pragma unroll
    for (int nt = 0; nt < 8; nt++) {
        const int col = nt * 8 + 2 * tg;
        *reinterpret_cast<float2*>(ob + col) =
            make_float2(o[nt][0] * inv0, o[nt][1] * inv0);
        *reinterpret_cast<float2*>(ob + (size_t)8 * D_ + col) =
            make_float2(o[nt][2] * inv1, o[nt][3] * inv1);
    }
}

// ===========================================================================
extern "C" void kernel_launch(void* const* d_in, const int* in_sizes, int n_in,
                              void* d_out, int out_size)
{
    const float* q  = (const float*)d_in[0];
    const float* k  = (const float*)d_in[1];
    const float* v  = (const float*)d_in[2];
    const float* pe = (const float*)d_in[3];
    const float* Wq = (const float*)d_in[4];
    const float* bq = (const float*)d_in[5];
    const float* Wk = (const float*)d_in[6];
    const float* bk = (const float*)d_in[7];
    const float* Wv = (const float*)d_in[8];
    const float* bv = (const float*)d_in[9];
    const float* Wo = (const float*)d_in[10];
    const float* bo = (const float*)d_in[11];
    float* out = (float*)d_out;

    float *pq, *pk, *pvv, *pao;
    __nv_bfloat16 *whi, *wlo;
    cudaGetSymbolAddress((void**)&pq,  g_q);
    cudaGetSymbolAddress((void**)&pk,  g_k);
    cudaGetSymbolAddress((void**)&pvv, g_v);
    cudaGetSymbolAddress((void**)&pao, g_ao);
    cudaGetSymbolAddress((void**)&whi, g_whi);
    cudaGetSymbolAddress((void**)&wlo, g_wlo);

    cudaFuncSetAttribute(gemm_mma_kernel,
                         cudaFuncAttributeMaxDynamicSharedMemorySize, GEMM_SMEM);
    cudaFuncSetAttribute(attn_mma_kernel,
                         cudaFuncAttributeMaxDynamicSharedMemorySize, ATTN_SMEM);

    // 1) weight transpose + hi/lo split
    dim3 tb(32, 8), tg(D_ / 32, D_ / 32);
    split_transpose_kernel<<<tg, tb>>>(Wq, whi + 0 * D_ * D_, wlo + 0 * D_ * D_);
    split_transpose_kernel<<<tg, tb>>>(Wk, whi + 1 * D_ * D_, wlo + 1 * D_ * D_);
    split_transpose_kernel<<<tg, tb>>>(Wv, whi + 2 * D_ * D_, wlo + 2 * D_ * D_);
    split_transpose_kernel<<<tg, tb>>>(Wo, whi + 3 * D_ * D_, wlo + 3 * D_ * D_);

    // 2) Q/K/V projections (mma.sync)
    dim3 gg(D_ / 128, M_ / 128);
    gemm_mma_kernel<<<gg, 256, GEMM_SMEM>>>(q, whi + 0 * D_ * D_, wlo + 0 * D_ * D_, bq, pq);
    gemm_mma_kernel<<<gg, 256, GEMM_SMEM>>>(k, whi + 1 * D_ * D_, wlo + 1 * D_ * D_, bk, pk);
    gemm_mma_kernel<<<gg, 256, GEMM_SMEM>>>(v, whi + 2 * D_ * D_, wlo + 2 * D_ * D_, bv, pvv);

    // 3) attention (mma.sync flash)
    attn_mma_kernel<<<dim3(S_ / AQT, H_, B_), 256, ATTN_SMEM>>>(pe);

    // 4) output projection (mma.sync)
    gemm_mma_kernel<<<gg, 256, GEMM_SMEM>>>(pao, whi + 3 * D_ * D_, wlo + 3 * D_ * D_, bo, out);
}

// round 7
// speedup vs baseline: 2.5213x; 1.5279x over previous
#include <cuda_runtime.h>
#include <cuda_bf16.h>
#include <cstdint>

#define B_  2
#define S_  2048
#define D_  1024
#define H_  16
#define DK_ 64
#define M_  (B_ * S_)   // 4096

// Scratch (allocation-free: __device__ globals)
__device__ float g_k  [M_ * D_];               // K projection (fp32, pre-PE)
__device__ float g_ao [M_ * D_];               // attention output (fp32)
__device__ __nv_bfloat16 g_qhi[M_ * D_], g_qlo[M_ * D_];
__device__ __nv_bfloat16 g_khi[M_ * D_], g_klo[M_ * D_];   // K_eff = K + PE
__device__ __nv_bfloat16 g_vhi[M_ * D_], g_vlo[M_ * D_];
__device__ __nv_bfloat16 g_whi[4 * D_ * D_];   // transposed weights [N,K], hi
__device__ __nv_bfloat16 g_wlo[4 * D_ * D_];   // transposed weights [N,K], lo

// ---------------------------------------------------------------------------
__device__ __forceinline__ uint32_t smem_u32(const void* p) {
    uint32_t a;
    asm("{ .reg .u64 t; cvta.to.shared.u64 t, %1; cvt.u32.u64 %0, t; }"
        : "=r"(a) : "l"(p));
    return a;
}
__device__ __forceinline__ uint32_t pack_bf(float a, float b) {
    uint32_t ha = __bfloat16_as_ushort(__float2bfloat16_rn(a));
    uint32_t hb = __bfloat16_as_ushort(__float2bfloat16_rn(b));
    return ha | (hb << 16);
}
__device__ __forceinline__ uint32_t pack_hilo(float a, float b, uint32_t& lo) {
    __nv_bfloat16 ha = __float2bfloat16_rn(a);
    __nv_bfloat16 hb = __float2bfloat16_rn(b);
    lo = pack_bf(a - __bfloat162float(ha), b - __bfloat162float(hb));
    return (uint32_t)__bfloat16_as_ushort(ha) |
           ((uint32_t)__bfloat16_as_ushort(hb) << 16);
}
__device__ __forceinline__ void mma16816(float c[4], const uint32_t a[4],
                                         uint32_t b0, uint32_t b1) {
    asm volatile(
        "mma.sync.aligned.m16n8k16.row.col.f32.bf16.bf16.f32 "
        "{%0,%1,%2,%3}, {%4,%5,%6,%7}, {%8,%9}, {%0,%1,%2,%3};"
        : "+f"(c[0]), "+f"(c[1]), "+f"(c[2]), "+f"(c[3])
        : "r"(a[0]), "r"(a[1]), "r"(a[2]), "r"(a[3]), "r"(b0), "r"(b1));
}
__device__ __forceinline__ void ldsm4(uint32_t r[4], uint32_t a) {
    asm volatile("ldmatrix.sync.aligned.m8n8.x4.shared.b16 {%0,%1,%2,%3}, [%4];"
        : "=r"(r[0]), "=r"(r[1]), "=r"(r[2]), "=r"(r[3]) : "r"(a));
}
__device__ __forceinline__ void ldsm4t(uint32_t r[4], uint32_t a) {
    asm volatile("ldmatrix.sync.aligned.m8n8.x4.trans.shared.b16 {%0,%1,%2,%3}, [%4];"
        : "=r"(r[0]), "=r"(r[1]), "=r"(r[2]), "=r"(r[3]) : "r"(a));
}
__device__ __forceinline__ void cp16(uint32_t dst, const void* src) {
    asm volatile("cp.async.cg.shared.global [%0], [%1], 16;"
                 :: "r"(dst), "l"(src) : "memory");
}
#define CP_COMMIT() asm volatile("cp.async.commit_group;" ::: "memory")

// ===========================================================================
// Weight preprocessing (all 4 weights in one launch)
// ===========================================================================
__global__ __launch_bounds__(256) void split_transpose4_kernel(
    const float* __restrict__ W0, const float* __restrict__ W1,
    const float* __restrict__ W2, const float* __restrict__ W3,
    __nv_bfloat16* __restrict__ Th, __nv_bfloat16* __restrict__ Tl)
{
    __shared__ float t[32][33];
    const int z = blockIdx.z;
    const float* W = (z == 0) ? W0 : (z == 1) ? W1 : (z == 2) ? W2 : W3;
    Th += (size_t)z * D_ * D_;
    Tl += (size_t)z * D_ * D_;
    const int tx = threadIdx.x, ty = threadIdx.y;
    const int n0 = blockIdx.x * 32, k0 = blockIdx.y * 32;
    #pragma unroll
    for (int i = 0; i < 4; i++)
        t[ty + i * 8][tx] = W[(size_t)(k0 + ty + i * 8) * D_ + n0 + tx];
    __syncthreads();
    #pragma unroll
    for (int i = 0; i < 4; i++) {
        float x = t[tx][ty + i * 8];
        __nv_bfloat16 hi = __float2bfloat16_rn(x);
        float lo = x - __bfloat162float(hi);
        size_t o = (size_t)(n0 + ty + i * 8) * D_ + k0 + tx;
        Th[o] = hi;
        Tl[o] = __float2bfloat16_rn(lo);
    }
}

// ===========================================================================
// K_eff prep: g_khi/g_klo = hilo( g_k + PE )   (PE folded in fp32)
// ===========================================================================
__global__ __launch_bounds__(256) void keff_kernel(const float* __restrict__ pe)
{
    const int s = blockIdx.x;
    const int b = blockIdx.y;
    const size_t base = ((size_t)b * S_ + s) * D_;
    #pragma unroll
    for (int i = 0; i < 4; i++) {
        const int dm = threadIdx.x + i * 256;
        const float val = g_k[base + dm] + pe[(size_t)dm * S_ + s];  // (h*64+dk)*S + s
        __nv_bfloat16 hi = __float2bfloat16_rn(val);
        g_khi[base + dm] = hi;
        g_klo[base + dm] = __float2bfloat16_rn(val - __bfloat162float(hi));
    }
}

// ===========================================================================
// mma.sync GEMM with ldmatrix + register prefetch.
// C = A[M,1024] @ Wt^T + bias. mode: Cf!=null -> fp32 out; else hi/lo bf16 out.
// ===========================================================================
#define PADK 56
#define TILE_BYTES (128 * PADK * 2)
#define SM_AH 0
#define SM_AL (1 * TILE_BYTES)
#define SM_BH (2 * TILE_BYTES)
#define SM_BL (3 * TILE_BYTES)
#define GEMM_SMEM (4 * TILE_BYTES)

__global__ __launch_bounds__(256, 1)
void gemm_mma_kernel(const float* __restrict__ A,
                     const __nv_bfloat16* __restrict__ Bh,
                     const __nv_bfloat16* __restrict__ Bl,
                     const float* __restrict__ bias,
                     float* __restrict__ Cf,
                     __nv_bfloat16* __restrict__ Chi,
                     __nv_bfloat16* __restrict__ Clo)
{
    extern __shared__ char sm[];
    const uint32_t smb = smem_u32(sm);
    const int tid    = threadIdx.x;
    const int wid    = tid >> 5;
    const int lane   = tid & 31;
    const int warp_m = wid & 3;
    const int warp_n = wid >> 2;
    const int n0 = blockIdx.x * 128;
    const int m0 = blockIdx.y * 128;

    // ldmatrix per-lane base offsets (bytes)
    const uint32_t a_off = smb +
        (uint32_t)((warp_m * 32 + (lane & 7) + (lane & 8)) * PADK +
                   ((lane >> 4) & 1) * 8) * 2;
    const uint32_t b_off = smb + SM_BH +
        (uint32_t)((warp_n * 64 + (lane & 7) + ((lane >> 4) & 1) * 8) * PADK +
                   ((lane >> 3) & 1) * 8) * 2;

    float acc[2][8][4];
    #pragma unroll
    for (int mt = 0; mt < 2; mt++)
        #pragma unroll
        for (int nt = 0; nt < 8; nt++)
            #pragma unroll
            for (int i = 0; i < 4; i++) acc[mt][nt][i] = 0.f;

    const int ar = tid >> 1;
    const int ac = (tid & 1) * 16;
    const int bk = (tid & 1) * 16;

    float4 av[4];
    uint4  bvh[2], bvl[2];
    {
        const float* ab = A + (size_t)(m0 + ar) * D_ + ac;
        #pragma unroll
        for (int i = 0; i < 4; i++) av[i] = *reinterpret_cast<const float4*>(ab + i * 4);
        const __nv_bfloat16* bhb = Bh + (size_t)(n0 + ar) * D_ + bk;
        const __nv_bfloat16* blb = Bl + (size_t)(n0 + ar) * D_ + bk;
        #pragma unroll
        for (int j = 0; j < 2; j++) {
            bvh[j] = *reinterpret_cast<const uint4*>(bhb + j * 8);
            bvl[j] = *reinterpret_cast<const uint4*>(blb + j * 8);
        }
    }

    for (int it = 0; it < D_ / 32; it++) {
        __syncthreads();
        // store prefetched tile -> smem (A converted to hi/lo)
        #pragma unroll
        for (int i = 0; i < 4; i++) {
            uint32_t lx, ly;
            uint2 hi, lo;
            hi.x = pack_hilo(av[i].x, av[i].y, lx);
            hi.y = pack_hilo(av[i].z, av[i].w, ly);
            lo.x = lx; lo.y = ly;
            const int off = (ar * PADK + ac + i * 4) * 2;
            *reinterpret_cast<uint2*>(sm + SM_AH + off) = hi;
            *reinterpret_cast<uint2*>(sm + SM_AL + off) = lo;
        }
        #pragma unroll
        for (int j = 0; j < 2; j++) {
            const int off = (ar * PADK + bk + j * 8) * 2;
            *reinterpret_cast<uint4*>(sm + SM_BH + off) = bvh[j];
            *reinterpret_cast<uint4*>(sm + SM_BL + off) = bvl[j];
        }
        __syncthreads();

        if (it + 1 < D_ / 32) {   // prefetch next tile (overlaps with mma)
            const int k0 = (it + 1) * 32;
            const float* ab = A + (size_t)(m0 + ar) * D_ + k0 + ac;
            #pragma unroll
            for (int i = 0; i < 4; i++) av[i] = *reinterpret_cast<const float4*>(ab + i * 4);
            const __nv_bfloat16* bhb = Bh + (size_t)(n0 + ar) * D_ + k0 + bk;
            const __nv_bfloat16* blb = Bl + (size_t)(n0 + ar) * D_ + k0 + bk;
            #pragma unroll
            for (int j = 0; j < 2; j++) {
                bvh[j] = *reinterpret_cast<const uint4*>(bhb + j * 8);
                bvl[j] = *reinterpret_cast<const uint4*>(blb + j * 8);
            }
        }

        #pragma unroll
        for (int ks = 0; ks < 2; ks++) {
            uint32_t ah[2][4], al[2][4];
            #pragma unroll
            for (int mt = 0; mt < 2; mt++) {
                const uint32_t d = (uint32_t)(mt * 16 * PADK + ks * 16) * 2;
                ldsm4(ah[mt], a_off + SM_AH + d);
                ldsm4(al[mt], a_off + SM_AL + d);
            }
            #pragma unroll
            for (int p = 0; p < 4; p++) {
                uint32_t bh[4], bl[4];
                const uint32_t d = (uint32_t)(p * 16 * PADK + ks * 16) * 2;
                ldsm4(bh, b_off + d);
                ldsm4(bl, b_off + TILE_BYTES + d);
                #pragma unroll
                for (int mt = 0; mt < 2; mt++) {
                    mma16816(acc[mt][2 * p],     ah[mt], bh[0], bh[1]);
                    mma16816(acc[mt][2 * p],     ah[mt], bl[0], bl[1]);
                    mma16816(acc[mt][2 * p],     al[mt], bh[0], bh[1]);
                    mma16816(acc[mt][2 * p + 1], ah[mt], bh[2], bh[3]);
                    mma16816(acc[mt][2 * p + 1], ah[mt], bl[2], bl[3]);
                    mma16816(acc[mt][2 * p + 1], al[mt], bh[2], bh[3]);
                }
            }
        }
    }

    // epilogue
    const int g  = lane >> 2;
    const int tg = lane & 3;
    #pragma unroll
    for (int mt = 0; mt < 2; mt++) {
        const int row = m0 + warp_m * 32 + mt * 16 + g;
        #pragma unroll
        for (int nt = 0; nt < 8; nt++) {
            const int col = n0 + warp_n * 64 + nt * 8 + 2 * tg;
            const float bx = bias[col], by = bias[col + 1];
            const float v00 = acc[mt][nt][0] + bx, v01 = acc[mt][nt][1] + by;
            const float v10 = acc[mt][nt][2] + bx, v11 = acc[mt][nt][3] + by;
            if (Cf) {
                *reinterpret_cast<float2*>(Cf + (size_t)row * D_ + col) = make_float2(v00, v01);
                *reinterpret_cast<float2*>(Cf + (size_t)(row + 8) * D_ + col) = make_float2(v10, v11);
            } else {
                uint32_t l0, l1;
                const uint32_t h0 = pack_hilo(v00, v01, l0);
                const uint32_t h1 = pack_hilo(v10, v11, l1);
                *reinterpret_cast<uint32_t*>(Chi + (size_t)row * D_ + col) = h0;
                *reinterpret_cast<uint32_t*>(Clo + (size_t)row * D_ + col) = l0;
                *reinterpret_cast<uint32_t*>(Chi + (size_t)(row + 8) * D_ + col) = h1;
                *reinterpret_cast<uint32_t*>(Clo + (size_t)(row + 8) * D_ + col) = l1;
            }
        }
    }
}

// ===========================================================================
// Flash attention: ldmatrix + cp.async double-buffered K/V, Q frags in regs.
// Block = (b, h, 128-query tile); 8 warps x 16 rows; KV tile 64.
// ===========================================================================
#define APAD 72
#define SQ_H 0
#define SQ_L (128 * APAD * 2)                 // 18432
#define SKV_OFF (2 * 128 * APAD * 2)          // 36864
#define HALF_BYTES (64 * APAD * 2)            // 9216
#define STAGE_BYTES (4 * HALF_BYTES)          // 36864 (KH,KL,VH,VL)
#define ATTN_SMEM (SKV_OFF + 2 * STAGE_BYTES) // 110592

__global__ __launch_bounds__(256, 1)
void attn_mma_kernel()
{
    extern __shared__ char sm[];
    const uint32_t smb = smem_u32(sm);
    const int b    = blockIdx.z;
    const int h    = blockIdx.y;
    const int q0   = blockIdx.x * 128;
    const int tid  = threadIdx.x;
    const int wid  = tid >> 5;
    const int lane = tid & 31;
    const int g    = lane >> 2;
    const int tg   = lane & 3;

    // per-lane ldmatrix base offsets (bytes)
    const uint32_t q_off = (uint32_t)((wid * 16 + (lane & 7) + (lane & 8)) * APAD +
                                      ((lane >> 4) & 1) * 8) * 2;
    const uint32_t k_off = (uint32_t)(((lane & 7) + ((lane >> 4) & 1) * 8) * APAD +
                                      ((lane >> 3) & 1) * 8) * 2;
    const uint32_t v_off = (uint32_t)(((lane & 7) + (lane & 8)) * APAD +
                                      ((lane >> 4) & 1) * 8) * 2;

    // ---- Q tile -> smem (hi/lo bf16, plain loads, once) ----
    {
        const size_t qg = ((size_t)b * S_ + q0) * D_ + h * DK_;
        #pragma unroll
        for (int i = 0; i < 4; i++) {
            const int chunk = tid + i * 256;          // 0..1023
            const int row = chunk >> 3, c8 = (chunk & 7) * 8;
            const size_t go = qg + (size_t)row * D_ + c8;
            const int so = (row * APAD + c8) * 2;
            *reinterpret_cast<uint4*>(sm + SQ_H + so) =
                *reinterpret_cast<const uint4*>(g_qhi + go);
            *reinterpret_cast<uint4*>(sm + SQ_L + so) =
                *reinterpret_cast<const uint4*>(g_qlo + go);
        }
    }

    const size_t kvg = ((size_t)b * S_) * D_ + h * DK_;
    // issue stage 0
    {
        const uint32_t sbase = smb + SKV_OFF;
        #pragma unroll
        for (int c = 0; c < 2; c++) {
            const int chunk = tid + c * 256;          // 0..511
            const int row = chunk >> 3, c8 = (chunk & 7) * 8;
            const uint32_t so = (uint32_t)(row * APAD + c8) * 2;
            const size_t go = kvg + (size_t)row * D_ + c8;
            cp16(sbase + 0 * HALF_BYTES + so, g_khi + go);
            cp16(sbase + 1 * HALF_BYTES + so, g_klo + go);
            cp16(sbase + 2 * HALF_BYTES + so, g_vhi + go);
            cp16(sbase + 3 * HALF_BYTES + so, g_vlo + go);
        }
    }
    CP_COMMIT();
    __syncthreads();

    // hoist Q fragments into registers
    uint32_t qh[4][4], ql[4][4];
    #pragma unroll
    for (int ks = 0; ks < 4; ks++) {
        ldsm4(qh[ks], smb + SQ_H + q_off + (uint32_t)(ks * 16) * 2);
        ldsm4(ql[ks], smb + SQ_L + q_off + (uint32_t)(ks * 16) * 2);
    }

    float m_[2] = {-1e30f, -1e30f};
    float l_[2] = {0.f, 0.f};
    float o[8][4];
    #pragma unroll
    for (int nt = 0; nt < 8; nt++)
        #pragma unroll
        for (int i = 0; i < 4; i++) o[nt][i] = 0.f;

    for (int it = 0; it < S_ / 64; it++) {
        if (it + 1 < S_ / 64) {    // issue next stage
            const uint32_t sbase = smb + SKV_OFF + ((it + 1) & 1) * STAGE_BYTES;
            const size_t tg0 = kvg + (size_t)(it + 1) * 64 * D_;
            #pragma unroll
            for (int c = 0; c < 2; c++) {
                const int chunk = tid + c * 256;
                const int row = chunk >> 3, c8 = (chunk & 7) * 8;
                const uint32_t so = (uint32_t)(row * APAD + c8) * 2;
                const size_t go = tg0 + (size_t)row * D_ + c8;
                cp16(sbase + 0 * HALF_BYTES + so, g_khi + go);
                cp16(sbase + 1 * HALF_BYTES + so, g_klo + go);
                cp16(sbase + 2 * HALF_BYTES + so, g_vhi + go);
                cp16(sbase + 3 * HALF_BYTES + so, g_vlo + go);
            }
            CP_COMMIT();
            asm volatile("cp.async.wait_group 1;" ::: "memory");
        } else {
            asm volatile("cp.async.wait_group 0;" ::: "memory");
        }
        __syncthreads();

        const uint32_t skv = smb + SKV_OFF + (it & 1) * STAGE_BYTES;

        // ---- S = Q @ K_eff^T ----
        float s[8][4];
        #pragma unroll
        for (int nt = 0; nt < 8; nt++)
            #pragma unroll
            for (int i = 0; i < 4; i++) s[nt][i] = 0.f;

        #pragma unroll
        for (int ks = 0; ks < 4; ks++) {
            #pragma unroll
            for (int p = 0; p < 4; p++) {
                uint32_t kh[4], kl[4];
                const uint32_t d = (uint32_t)(p * 16 * APAD + ks * 16) * 2;
                ldsm4(kh, skv + k_off + d);
                ldsm4(kl, skv + HALF_BYTES + k_off + d);
                mma16816(s[2 * p],     qh[ks], kh[0], kh[1]);
                mma16816(s[2 * p],     qh[ks], kl[0], kl[1]);
                mma16816(s[2 * p],     ql[ks], kh[0], kh[1]);
                mma16816(s[2 * p + 1], qh[ks], kh[2], kh[3]);
                mma16816(s[2 * p + 1], qh[ks], kl[2], kl[3]);
                mma16816(s[2 * p + 1], ql[ks], kh[2], kh[3]);
            }
        }

        // ---- online softmax ----
        float mx0 = -1e30f, mx1 = -1e30f;
        #pragma unroll
        for (int nt = 0; nt < 8; nt++) {
            #pragma unroll
            for (int i = 0; i < 4; i++) s[nt][i] *= 0.125f;
            mx0 = fmaxf(mx0, fmaxf(s[nt][0], s[nt][1]));
            mx1 = fmaxf(mx1, fmaxf(s[nt][2], s[nt][3]));
        }
        mx0 = fmaxf(mx0, __shfl_xor_sync(0xffffffffu, mx0, 1));
        mx0 = fmaxf(mx0, __shfl_xor_sync(0xffffffffu, mx0, 2));
        mx1 = fmaxf(mx1, __shfl_xor_sync(0xffffffffu, mx1, 1));
        mx1 = fmaxf(mx1, __shfl_xor_sync(0xffffffffu, mx1, 2));

        const float mn0 = fmaxf(m_[0], mx0);
        const float mn1 = fmaxf(m_[1], mx1);
        const float c0 = __expf(m_[0] - mn0);
        const float c1 = __expf(m_[1] - mn1);
        m_[0] = mn0; m_[1] = mn1;

        float r0 = 0.f, r1 = 0.f;
        #pragma unroll
        for (int nt = 0; nt < 8; nt++) {
            s[nt][0] = __expf(s[nt][0] - mn0);
            s[nt][1] = __expf(s[nt][1] - mn0);
            s[nt][2] = __expf(s[nt][2] - mn1);
            s[nt][3] = __expf(s[nt][3] - mn1);
            r0 += s[nt][0] + s[nt][1];
            r1 += s[nt][2] + s[nt][3];
        }
        r0 += __shfl_xor_sync(0xffffffffu, r0, 1);
        r0 += __shfl_xor_sync(0xffffffffu, r0, 2);
        r1 += __shfl_xor_sync(0xffffffffu, r1, 1);
        r1 += __shfl_xor_sync(0xffffffffu, r1, 2);
        l_[0] = l_[0] * c0 + r0;
        l_[1] = l_[1] * c1 + r1;

        #pragma unroll
        for (int nt = 0; nt < 8; nt++) {
            o[nt][0] *= c0; o[nt][1] *= c0;
            o[nt][2] *= c1; o[nt][3] *= c1;
        }

        // ---- O += P @ V  (V frags via ldmatrix.trans) ----
        #pragma unroll
        for (int jp = 0; jp < 4; jp++) {
            uint32_t ph[4], pl[4];
            ph[0] = pack_hilo(s[2 * jp][0],     s[2 * jp][1],     pl[0]);
            ph[1] = pack_hilo(s[2 * jp][2],     s[2 * jp][3],     pl[1]);
            ph[2] = pack_hilo(s[2 * jp + 1][0], s[2 * jp + 1][1], pl[2]);
            ph[3] = pack_hilo(s[2 * jp + 1][2], s[2 * jp + 1][3], pl[3]);
            #pragma unroll
            for (int p = 0; p < 4; p++) {
                uint32_t vh[4], vl[4];
                const uint32_t d = (uint32_t)(jp * 16 * APAD + p * 16) * 2;
                ldsm4t(vh, skv + 2 * HALF_BYTES + v_off + d);
                ldsm4t(vl, skv + 3 * HALF_BYTES + v_off + d);
                mma16816(o[2 * p],     ph, vh[0], vh[1]);
                mma16816(o[2 * p],     ph, vl[0], vl[1]);
                mma16816(o[2 * p],     pl, vh[0], vh[1]);
                mma16816(o[2 * p + 1], ph, vh[2], vh[3]);
                mma16816(o[2 * p + 1], ph, vl[2], vl[3]);
                mma16816(o[2 * p + 1], pl, vh[2], vh[3]);
            }
        }
        __syncthreads();
    }

    // ---- epilogue: normalize, store fp32 ----
    const float inv0 = 1.f / l_[0];
    const float inv1 = 1.f / l_[1];
    const int row = q0 + wid * 16 + g;
    float* ob = g_ao + ((size_t)b * S_ + row) * D_ + h * DK_;
    #pragma unroll
    for (int nt = 0; nt < 8; nt++) {
        const int col = nt * 8 + 2 * tg;
        *reinterpret_cast<float2*>(ob + col) =
            make_float2(o[nt][0] * inv0, o[nt][1] * inv0);
        *reinterpret_cast<float2*>(ob + (size_t)8 * D_ + col) =
            make_float2(o[nt][2] * inv1, o[nt][3] * inv1);
    }
}

// ===========================================================================
extern "C" void kernel_launch(void* const* d_in, const int* in_sizes, int n_in,
                              void* d_out, int out_size)
{
    const float* q  = (const float*)d_in[0];
    const float* k  = (const float*)d_in[1];
    const float* v  = (const float*)d_in[2];
    const float* pe = (const float*)d_in[3];
    const float* Wq = (const float*)d_in[4];
    const float* bq = (const float*)d_in[5];
    const float* Wk = (const float*)d_in[6];
    const float* bk = (const float*)d_in[7];
    const float* Wv = (const float*)d_in[8];
    const float* bv = (const float*)d_in[9];
    const float* Wo = (const float*)d_in[10];
    const float* bo = (const float*)d_in[11];
    float* out = (float*)d_out;

    float *pk, *pao;
    __nv_bfloat16 *whi, *wlo, *qhi, *qlo, *khi, *klo, *vhi, *vlo;
    cudaGetSymbolAddress((void**)&pk,  g_k);
    cudaGetSymbolAddress((void**)&pao, g_ao);
    cudaGetSymbolAddress((void**)&whi, g_whi);
    cudaGetSymbolAddress((void**)&wlo, g_wlo);
    cudaGetSymbolAddress((void**)&qhi, g_qhi);
    cudaGetSymbolAddress((void**)&qlo, g_qlo);
    cudaGetSymbolAddress((void**)&khi, g_khi);
    cudaGetSymbolAddress((void**)&klo, g_klo);
    cudaGetSymbolAddress((void**)&vhi, g_vhi);
    cudaGetSymbolAddress((void**)&vlo, g_vlo);

    cudaFuncSetAttribute(gemm_mma_kernel,
                         cudaFuncAttributeMaxDynamicSharedMemorySize, GEMM_SMEM);
    cudaFuncSetAttribute(attn_mma_kernel,
                         cudaFuncAttributeMaxDynamicSharedMemorySize, ATTN_SMEM);

    // 1) weight transpose + hi/lo split (all 4 weights)
    split_transpose4_kernel<<<dim3(D_ / 32, D_ / 32, 4), dim3(32, 8)>>>(
        Wq, Wk, Wv, Wo, whi, wlo);

    // 2) projections: Q,V -> hi/lo bf16 directly; K -> fp32 (PE added next)
    dim3 gg(D_ / 128, M_ / 128);
    gemm_mma_kernel<<<gg, 256, GEMM_SMEM>>>(q, whi + 0 * D_ * D_, wlo + 0 * D_ * D_,
                                            bq, nullptr, qhi, qlo);
    gemm_mma_kernel<<<gg, 256, GEMM_SMEM>>>(k, whi + 1 * D_ * D_, wlo + 1 * D_ * D_,
                                            bk, pk, nullptr, nullptr);
    gemm_mma_kernel<<<gg, 256, GEMM_SMEM>>>(v, whi + 2 * D_ * D_, wlo + 2 * D_ * D_,
                                            bv, nullptr, vhi, vlo);

    // 3) K_eff = K + PE -> hi/lo bf16
    keff_kernel<<<dim3(S_, B_), 256>>>(pe);

    // 4) attention
    attn_mma_kernel<<<dim3(S_ / 128, H_, B_), 256, ATTN_SMEM>>>();

    // 5) output projection -> fp32 out
    gemm_mma_kernel<<<gg, 256, GEMM_SMEM>>>(pao, whi + 3 * D_ * D_, wlo + 3 * D_ * D_,
                                            bo, out, nullptr, nullptr);
}

// round 9
// speedup vs baseline: 2.8061x; 1.1130x over previous
#include <cuda_runtime.h>
#include <cuda_bf16.h>
#include <cstdint>

#define B_  2
#define S_  2048
#define D_  1024
#define H_  16
#define DK_ 64
#define M_  (B_ * S_)   // 4096

// Scratch (allocation-free: __device__ globals)
__device__ float g_k  [M_ * D_];                         // K projection fp32 (pre-PE)
__device__ __nv_bfloat16 g_inhi[3 * M_ * D_], g_inlo[3 * M_ * D_];  // q,k,v inputs
__device__ __nv_bfloat16 g_qhi[M_ * D_], g_qlo[M_ * D_];
__device__ __nv_bfloat16 g_khi[M_ * D_], g_klo[M_ * D_];            // K_eff
__device__ __nv_bfloat16 g_vhi[M_ * D_], g_vlo[M_ * D_];
__device__ __nv_bfloat16 g_aohi[M_ * D_], g_aolo[M_ * D_];          // attn out
__device__ __nv_bfloat16 g_whi[4 * D_ * D_];             // Wt [N,K] hi
__device__ __nv_bfloat16 g_wlo[4 * D_ * D_];             // Wt [N,K] lo

// ---------------------------------------------------------------------------
__device__ __forceinline__ uint32_t smem_u32(const void* p) {
    uint32_t a;
    asm("{ .reg .u64 t; cvta.to.shared.u64 t, %1; cvt.u32.u64 %0, t; }"
        : "=r"(a) : "l"(p));
    return a;
}
__device__ __forceinline__ uint32_t pack_bf(float a, float b) {
    uint32_t ha = __bfloat16_as_ushort(__float2bfloat16_rn(a));
    uint32_t hb = __bfloat16_as_ushort(__float2bfloat16_rn(b));
    return ha | (hb << 16);
}
__device__ __forceinline__ uint32_t pack_hilo(float a, float b, uint32_t& lo) {
    __nv_bfloat16 ha = __float2bfloat16_rn(a);
    __nv_bfloat16 hb = __float2bfloat16_rn(b);
    lo = pack_bf(a - __bfloat162float(ha), b - __bfloat162float(hb));
    return (uint32_t)__bfloat16_as_ushort(ha) |
           ((uint32_t)__bfloat16_as_ushort(hb) << 16);
}
__device__ __forceinline__ void mma16816(float c[4], const uint32_t a[4],
                                         uint32_t b0, uint32_t b1) {
    asm volatile(
        "mma.sync.aligned.m16n8k16.row.col.f32.bf16.bf16.f32 "
        "{%0,%1,%2,%3}, {%4,%5,%6,%7}, {%8,%9}, {%0,%1,%2,%3};"
        : "+f"(c[0]), "+f"(c[1]), "+f"(c[2]), "+f"(c[3])
        : "r"(a[0]), "r"(a[1]), "r"(a[2]), "r"(a[3]), "r"(b0), "r"(b1));
}
__device__ __forceinline__ void ldsm4(uint32_t r[4], uint32_t a) {
    asm volatile("ldmatrix.sync.aligned.m8n8.x4.shared.b16 {%0,%1,%2,%3}, [%4];"
        : "=r"(r[0]), "=r"(r[1]), "=r"(r[2]), "=r"(r[3]) : "r"(a));
}
__device__ __forceinline__ void ldsm4t(uint32_t r[4], uint32_t a) {
    asm volatile("ldmatrix.sync.aligned.m8n8.x4.trans.shared.b16 {%0,%1,%2,%3}, [%4];"
        : "=r"(r[0]), "=r"(r[1]), "=r"(r[2]), "=r"(r[3]) : "r"(a));
}
__device__ __forceinline__ void cp16(uint32_t dst, const void* src) {
    asm volatile("cp.async.cg.shared.global [%0], [%1], 16;"
                 :: "r"(dst), "l"(src) : "memory");
}
#define CP_COMMIT() asm volatile("cp.async.commit_group;" ::: "memory")

// ===========================================================================
// Weight preprocessing (all 4 weights, one launch)
// ===========================================================================
__global__ __launch_bounds__(256) void split_transpose4_kernel(
    const float* __restrict__ W0, const float* __restrict__ W1,
    const float* __restrict__ W2, const float* __restrict__ W3,
    __nv_bfloat16* __restrict__ Th, __nv_bfloat16* __restrict__ Tl)
{
    __shared__ float t[32][33];
    const int z = blockIdx.z;
    const float* W = (z == 0) ? W0 : (z == 1) ? W1 : (z == 2) ? W2 : W3;
    Th += (size_t)z * D_ * D_;
    Tl += (size_t)z * D_ * D_;
    const int tx = threadIdx.x, ty = threadIdx.y;
    const int n0 = blockIdx.x * 32, k0 = blockIdx.y * 32;
    #pragma unroll
    for (int i = 0; i < 4; i++)
        t[ty + i * 8][tx] = W[(size_t)(k0 + ty + i * 8) * D_ + n0 + tx];
    __syncthreads();
    #pragma unroll
    for (int i = 0; i < 4; i++) {
        float x = t[tx][ty + i * 8];
        __nv_bfloat16 hi = __float2bfloat16_rn(x);
        float lo = x - __bfloat162float(hi);
        size_t o = (size_t)(n0 + ty + i * 8) * D_ + k0 + tx;
        Th[o] = hi;
        Tl[o] = __float2bfloat16_rn(lo);
    }
}

// ===========================================================================
// Input split: x fp32 -> hi/lo bf16 (z = 0,1,2 selects q,k,v)
// ===========================================================================
__global__ __launch_bounds__(256) void split_in_kernel(
    const float* __restrict__ x0, const float* __restrict__ x1,
    const float* __restrict__ x2)
{
    const int z = blockIdx.y;
    const float* x = (z == 0) ? x0 : (z == 1) ? x1 : x2;
    __nv_bfloat16* oh = g_inhi + (size_t)z * M_ * D_;
    __nv_bfloat16* ol = g_inlo + (size_t)z * M_ * D_;
    const size_t i4 = ((size_t)blockIdx.x * 256 + threadIdx.x) * 4;
    float4 v = *reinterpret_cast<const float4*>(x + i4);
    uint32_t lx, ly;
    uint2 hi, lo;
    hi.x = pack_hilo(v.x, v.y, lx);
    hi.y = pack_hilo(v.z, v.w, ly);
    lo.x = lx; lo.y = ly;
    *reinterpret_cast<uint2*>(oh + i4) = hi;
    *reinterpret_cast<uint2*>(ol + i4) = lo;
}

// ===========================================================================
// K_eff prep: g_khi/g_klo = hilo( g_k + PE )
// ===========================================================================
__global__ __launch_bounds__(256) void keff_kernel(const float* __restrict__ pe)
{
    const int s = blockIdx.x;
    const int b = blockIdx.y;
    const size_t base = ((size_t)b * S_ + s) * D_;
    #pragma unroll
    for (int i = 0; i < 4; i++) {
        const int dm = threadIdx.x + i * 256;
        const float val = g_k[base + dm] + pe[(size_t)dm * S_ + s];
        __nv_bfloat16 hi = __float2bfloat16_rn(val);
        g_khi[base + dm] = hi;
        g_klo[base + dm] = __float2bfloat16_rn(val - __bfloat162float(hi));
    }
}

// ===========================================================================
// All-bf16 mma.sync GEMM, cp.async 2-stage, 2 CTAs/SM.
// C[M,1024] = (Ah+Al) @ (Bh+Bl)^T + bias, 3-pass hi/lo.
// ===========================================================================
#define PK2 40                                // bf16 per smem row (80B stride)
#define GT_BYTES (128 * PK2 * 2)              // 10240
#define GSTAGE (4 * GT_BYTES)                 // 40960 (AH,AL,BH,BL)
#define GEMM_SMEM (2 * GSTAGE)                // 81920

__global__ __launch_bounds__(256, 2)
void gemm_bf_kernel(const __nv_bfloat16* __restrict__ Ah,
                    const __nv_bfloat16* __restrict__ Al,
                    const __nv_bfloat16* __restrict__ Bh,
                    const __nv_bfloat16* __restrict__ Bl,
                    const float* __restrict__ bias,
                    float* __restrict__ Cf,
                    __nv_bfloat16* __restrict__ Chi,
                    __nv_bfloat16* __restrict__ Clo)
{
    extern __shared__ char sm[];
    const uint32_t smb = smem_u32(sm);
    const int tid    = threadIdx.x;
    const int wid    = tid >> 5;
    const int lane   = tid & 31;
    const int warp_m = wid & 3;
    const int warp_n = wid >> 2;
    const int n0 = blockIdx.x * 128;
    const int m0 = blockIdx.y * 128;

    // cp.async mapping: 512 16B-chunks per tile; 2 per thread
    const int row0 = tid >> 2;                 // chunk c=0 -> rows 0..63
    const int c8_0 = (tid & 3) * 8;
    // ldmatrix per-lane offsets (bytes, within stage)
    const uint32_t a_off = (uint32_t)((warp_m * 32 + (lane & 7) + (lane & 8)) * PK2 +
                                      ((lane >> 4) & 1) * 8) * 2;
    const uint32_t b_off = (uint32_t)((warp_n * 64 + (lane & 7) + ((lane >> 4) & 1) * 8) * PK2 +
                                      ((lane >> 3) & 1) * 8) * 2;

    float acc[2][8][4];
    #pragma unroll
    for (int mt = 0; mt < 2; mt++)
        #pragma unroll
        for (int nt = 0; nt < 8; nt++)
            #pragma unroll
            for (int i = 0; i < 4; i++) acc[mt][nt][i] = 0.f;

    // stage issue: copies A/B hi/lo [128 x 32] bf16 tiles
    auto issue = [&](int it) {
        const uint32_t sb = smb + (uint32_t)(it & 1) * GSTAGE;
        const int k0 = it * 32;
        #pragma unroll
        for (int c = 0; c < 2; c++) {
            const int row = row0 + c * 64;
            const int c8  = c8_0;
            const uint32_t so = (uint32_t)(row * PK2 + c8) * 2;
            const size_t ga = (size_t)(m0 + row) * D_ + k0 + c8;
            const size_t gb = (size_t)(n0 + row) * D_ + k0 + c8;
            cp16(sb + 0 * GT_BYTES + so, Ah + ga);
            cp16(sb + 1 * GT_BYTES + so, Al + ga);
            cp16(sb + 2 * GT_BYTES + so, Bh + gb);
            cp16(sb + 3 * GT_BYTES + so, Bl + gb);
        }
        CP_COMMIT();
    };

    issue(0);

    for (int it = 0; it < D_ / 32; it++) {
        if (it + 1 < D_ / 32) {
            issue(it + 1);
            asm volatile("cp.async.wait_group 1;" ::: "memory");
        } else {
            asm volatile("cp.async.wait_group 0;" ::: "memory");
        }
        __syncthreads();

        const uint32_t sb = smb + (uint32_t)(it & 1) * GSTAGE;
        #pragma unroll
        for (int ks = 0; ks < 2; ks++) {
            uint32_t ah[2][4], al[2][4];
            #pragma unroll
            for (int mt = 0; mt < 2; mt++) {
                const uint32_t d = (uint32_t)(mt * 16 * PK2 + ks * 16) * 2;
                ldsm4(ah[mt], sb + 0 * GT_BYTES + a_off + d);
                ldsm4(al[mt], sb + 1 * GT_BYTES + a_off + d);
            }
            #pragma unroll
            for (int p = 0; p < 4; p++) {
                uint32_t bh[4], bl[4];
                const uint32_t d = (uint32_t)(p * 16 * PK2 + ks * 16) * 2;
                ldsm4(bh, sb + 2 * GT_BYTES + b_off + d);
                ldsm4(bl, sb + 3 * GT_BYTES + b_off + d);
                #pragma unroll
                for (int mt = 0; mt < 2; mt++) {
                    mma16816(acc[mt][2 * p],     ah[mt], bh[0], bh[1]);
                    mma16816(acc[mt][2 * p],     ah[mt], bl[0], bl[1]);
                    mma16816(acc[mt][2 * p],     al[mt], bh[0], bh[1]);
                    mma16816(acc[mt][2 * p + 1], ah[mt], bh[2], bh[3]);
                    mma16816(acc[mt][2 * p + 1], ah[mt], bl[2], bl[3]);
                    mma16816(acc[mt][2 * p + 1], al[mt], bh[2], bh[3]);
                }
            }
        }
        __syncthreads();
    }

    // epilogue
    const int g  = lane >> 2;
    const int tg = lane & 3;
    #pragma unroll
    for (int mt = 0; mt < 2; mt++) {
        const int row = m0 + warp_m * 32 + mt * 16 + g;
        #pragma unroll
        for (int nt = 0; nt < 8; nt++) {
            const int col = n0 + warp_n * 64 + nt * 8 + 2 * tg;
            const float bx = bias[col], by = bias[col + 1];
            const float v00 = acc[mt][nt][0] + bx, v01 = acc[mt][nt][1] + by;
            const float v10 = acc[mt][nt][2] + bx, v11 = acc[mt][nt][3] + by;
            if (Cf) {
                *reinterpret_cast<float2*>(Cf + (size_t)row * D_ + col) = make_float2(v00, v01);
                *reinterpret_cast<float2*>(Cf + (size_t)(row + 8) * D_ + col) = make_float2(v10, v11);
            } else {
                uint32_t l0, l1;
                const uint32_t h0 = pack_hilo(v00, v01, l0);
                const uint32_t h1 = pack_hilo(v10, v11, l1);
                *reinterpret_cast<uint32_t*>(Chi + (size_t)row * D_ + col) = h0;
                *reinterpret_cast<uint32_t*>(Clo + (size_t)row * D_ + col) = l0;
                *reinterpret_cast<uint32_t*>(Chi + (size_t)(row + 8) * D_ + col) = h1;
                *reinterpret_cast<uint32_t*>(Clo + (size_t)(row + 8) * D_ + col) = l1;
            }
        }
    }
}

// ===========================================================================
// Flash attention (round-7 proven core); epilogue now writes hi/lo bf16.
// ===========================================================================
#define APAD 72
#define SQ_H 0
#define SQ_L (128 * APAD * 2)
#define SKV_OFF (2 * 128 * APAD * 2)
#define HALF_BYTES (64 * APAD * 2)
#define STAGE_BYTES (4 * HALF_BYTES)
#define ATTN_SMEM (SKV_OFF + 2 * STAGE_BYTES)   // 110592

__global__ __launch_bounds__(256, 1)
void attn_mma_kernel()
{
    extern __shared__ char sm[];
    const uint32_t smb = smem_u32(sm);
    const int b    = blockIdx.z;
    const int h    = blockIdx.y;
    const int q0   = blockIdx.x * 128;
    const int tid  = threadIdx.x;
    const int wid  = tid >> 5;
    const int lane = tid & 31;
    const int g    = lane >> 2;
    const int tg   = lane & 3;

    const uint32_t q_off = (uint32_t)((wid * 16 + (lane & 7) + (lane & 8)) * APAD +
                                      ((lane >> 4) & 1) * 8) * 2;
    const uint32_t k_off = (uint32_t)(((lane & 7) + ((lane >> 4) & 1) * 8) * APAD +
                                      ((lane >> 3) & 1) * 8) * 2;
    const uint32_t v_off = (uint32_t)(((lane & 7) + (lane & 8)) * APAD +
                                      ((lane >> 4) & 1) * 8) * 2;

    {
        const size_t qg = ((size_t)b * S_ + q0) * D_ + h * DK_;
        #pragma unroll
        for (int i = 0; i < 4; i++) {
            const int chunk = tid + i * 256;
            const int row = chunk >> 3, c8 = (chunk & 7) * 8;
            const size_t go = qg + (size_t)row * D_ + c8;
            const int so = (row * APAD + c8) * 2;
            *reinterpret_cast<uint4*>(sm + SQ_H + so) =
                *reinterpret_cast<const uint4*>(g_qhi + go);
            *reinterpret_cast<uint4*>(sm + SQ_L + so) =
                *reinterpret_cast<const uint4*>(g_qlo + go);
        }
    }

    const size_t kvg = ((size_t)b * S_) * D_ + h * DK_;
    {
        const uint32_t sbase = smb + SKV_OFF;
        #pragma unroll
        for (int c = 0; c < 2; c++) {
            const int chunk = tid + c * 256;
            const int row = chunk >> 3, c8 = (chunk & 7) * 8;
            const uint32_t so = (uint32_t)(row * APAD + c8) * 2;
            const size_t go = kvg + (size_t)row * D_ + c8;
            cp16(sbase + 0 * HALF_BYTES + so, g_khi + go);
            cp16(sbase + 1 * HALF_BYTES + so, g_klo + go);
            cp16(sbase + 2 * HALF_BYTES + so, g_vhi + go);
            cp16(sbase + 3 * HALF_BYTES + so, g_vlo + go);
        }
    }
    CP_COMMIT();
    __syncthreads();

    uint32_t qh[4][4], ql[4][4];
    #pragma unroll
    for (int ks = 0; ks < 4; ks++) {
        ldsm4(qh[ks], smb + SQ_H + q_off + (uint32_t)(ks * 16) * 2);
        ldsm4(ql[ks], smb + SQ_L + q_off + (uint32_t)(ks * 16) * 2);
    }

    float m_[2] = {-1e30f, -1e30f};
    float l_[2] = {0.f, 0.f};
    float o[8][4];
    #pragma unroll
    for (int nt = 0; nt < 8; nt++)
        #pragma unroll
        for (int i = 0; i < 4; i++) o[nt][i] = 0.f;

    for (int it = 0; it < S_ / 64; it++) {
        if (it + 1 < S_ / 64) {
            const uint32_t sbase = smb + SKV_OFF + ((it + 1) & 1) * STAGE_BYTES;
            const size_t tg0 = kvg + (size_t)(it + 1) * 64 * D_;
            #pragma unroll
            for (int c = 0; c < 2; c++) {
                const int chunk = tid + c * 256;
                const int row = chunk >> 3, c8 = (chunk & 7) * 8;
                const uint32_t so = (uint32_t)(row * APAD + c8) * 2;
                const size_t go = tg0 + (size_t)row * D_ + c8;
                cp16(sbase + 0 * HALF_BYTES + so, g_khi + go);
                cp16(sbase + 1 * HALF_BYTES + so, g_klo + go);
                cp16(sbase + 2 * HALF_BYTES + so, g_vhi + go);
                cp16(sbase + 3 * HALF_BYTES + so, g_vlo + go);
            }
            CP_COMMIT();
            asm volatile("cp.async.wait_group 1;" ::: "memory");
        } else {
            asm volatile("cp.async.wait_group 0;" ::: "memory");
        }
        __syncthreads();

        const uint32_t skv = smb + SKV_OFF + (it & 1) * STAGE_BYTES;

        float s[8][4];
        #pragma unroll
        for (int nt = 0; nt < 8; nt++)
            #pragma unroll
            for (int i = 0; i < 4; i++) s[nt][i] = 0.f;

        #pragma unroll
        for (int ks = 0; ks < 4; ks++) {
            #pragma unroll
            for (int p = 0; p < 4; p++) {
                uint32_t kh[4], kl[4];
                const uint32_t d = (uint32_t)(p * 16 * APAD + ks * 16) * 2;
                ldsm4(kh, skv + k_off + d);
                ldsm4(kl, skv + HALF_BYTES + k_off + d);
                mma16816(s[2 * p],     qh[ks], kh[0], kh[1]);
                mma16816(s[2 * p],     qh[ks], kl[0], kl[1]);
                mma16816(s[2 * p],     ql[ks], kh[0], kh[1]);
                mma16816(s[2 * p + 1], qh[ks], kh[2], kh[3]);
                mma16816(s[2 * p + 1], qh[ks], kl[2], kl[3]);
                mma16816(s[2 * p + 1], ql[ks], kh[2], kh[3]);
            }
        }

        float mx0 = -1e30f, mx1 = -1e30f;
        #pragma unroll
        for (int nt = 0; nt < 8; nt++) {
            #pragma unroll
            for (int i = 0; i < 4; i++) s[nt][i] *= 0.125f;
            mx0 = fmaxf(mx0, fmaxf(s[nt][0], s[nt][1]));
            mx1 = fmaxf(mx1, fmaxf(s[nt][2], s[nt][3]));
        }
        mx0 = fmaxf(mx0, __shfl_xor_sync(0xffffffffu, mx0, 1));
        mx0 = fmaxf(mx0, __shfl_xor_sync(0xffffffffu, mx0, 2));
        mx1 = fmaxf(mx1, __shfl_xor_sync(0xffffffffu, mx1, 1));
        mx1 = fmaxf(mx1, __shfl_xor_sync(0xffffffffu, mx1, 2));

        const float mn0 = fmaxf(m_[0], mx0);
        const float mn1 = fmaxf(m_[1], mx1);
        const float c0 = __expf(m_[0] - mn0);
        const float c1 = __expf(m_[1] - mn1);
        m_[0] = mn0; m_[1] = mn1;

        float r0 = 0.f, r1 = 0.f;
        #pragma unroll
        for (int nt = 0; nt < 8; nt++) {
            s[nt][0] = __expf(s[nt][0] - mn0);
            s[nt][1] = __expf(s[nt][1] - mn0);
            s[nt][2] = __expf(s[nt][2] - mn1);
            s[nt][3] = __expf(s[nt][3] - mn1);
            r0 += s[nt][0] + s[nt][1];
            r1 += s[nt][2] + s[nt][3];
        }
        r0 += __shfl_xor_sync(0xffffffffu, r0, 1);
        r0 += __shfl_xor_sync(0xffffffffu, r0, 2);
        r1 += __shfl_xor_sync(0xffffffffu, r1, 1);
        r1 += __shfl_xor_sync(0xffffffffu, r1, 2);
        l_[0] = l_[0] * c0 + r0;
        l_[1] = l_[1] * c1 + r1;

        #pragma unroll
        for (int nt = 0; nt < 8; nt++) {
            o[nt][0] *= c0; o[nt][1] *= c0;
            o[nt][2] *= c1; o[nt][3] *= c1;
        }

        #pragma unroll
        for (int jp = 0; jp < 4; jp++) {
            uint32_t ph[4], pl[4];
            ph[0] = pack_hilo(s[2 * jp][0],     s[2 * jp][1],     pl[0]);
            ph[1] = pack_hilo(s[2 * jp][2],     s[2 * jp][3],     pl[1]);
            ph[2] = pack_hilo(s[2 * jp + 1][0], s[2 * jp + 1][1], pl[2]);
            ph[3] = pack_hilo(s[2 * jp + 1][2], s[2 * jp + 1][3], pl[3]);
            #pragma unroll
            for (int p = 0; p < 4; p++) {
                uint32_t vh[4], vl[4];
                const uint32_t d = (uint32_t)(jp * 16 * APAD + p * 16) * 2;
                ldsm4t(vh, skv + 2 * HALF_BYTES + v_off + d);
                ldsm4t(vl, skv + 3 * HALF_BYTES + v_off + d);
                mma16816(o[2 * p],     ph, vh[0], vh[1]);
                mma16816(o[2 * p],     ph, vl[0], vl[1]);
                mma16816(o[2 * p],     pl, vh[0], vh[1]);
                mma16816(o[2 * p + 1], ph, vh[2], vh[3]);
                mma16816(o[2 * p + 1], ph, vl[2], vl[3]);
                mma16816(o[2 * p + 1], pl, vh[2], vh[3]);
            }
        }
        __syncthreads();
    }

    // epilogue: normalize, write hi/lo bf16 (feeds O-projection)
    const float inv0 = 1.f / l_[0];
    const float inv1 = 1.f / l_[1];
    const int row = q0 + wid * 16 + g;
    const size_t ob = ((size_t)b * S_ + row) * D_ + h * DK_;
    #pragma unroll
    for (int nt = 0; nt < 8; nt++) {
        const int col = nt * 8 + 2 * tg;
        uint32_t l0, l1;
        const uint32_t h0 = pack_hilo(o[nt][0] * inv0, o[nt][1] * inv0, l0);
        const uint32_t h1 = pack_hilo(o[nt][2] * inv1, o[nt][3] * inv1, l1);
        *reinterpret_cast<uint32_t*>(g_aohi + ob + col) = h0;
        *reinterpret_cast<uint32_t*>(g_aolo + ob + col) = l0;
        *reinterpret_cast<uint32_t*>(g_aohi + ob + (size_t)8 * D_ + col) = h1;
        *reinterpret_cast<uint32_t*>(g_aolo + ob + (size_t)8 * D_ + col) = l1;
    }
}

// ===========================================================================
extern "C" void kernel_launch(void* const* d_in, const int* in_sizes, int n_in,
                              void* d_out, int out_size)
{
    const float* q  = (const float*)d_in[0];
    const float* k  = (const float*)d_in[1];
    const float* v  = (const float*)d_in[2];
    const float* pe = (const float*)d_in[3];
    const float* Wq = (const float*)d_in[4];
    const float* bq = (const float*)d_in[5];
    const float* Wk = (const float*)d_in[6];
    const float* bk = (const float*)d_in[7];
    const float* Wv = (const float*)d_in[8];
    const float* bv = (const float*)d_in[9];
    const float* Wo = (const float*)d_in[10];
    const float* bo = (const float*)d_in[11];
    float* out = (float*)d_out;

    float* pk;
    __nv_bfloat16 *whi, *wlo, *inhi, *inlo, *qhi, *qlo, *vhi, *vlo, *aohi, *aolo;
    cudaGetSymbolAddress((void**)&pk,   g_k);
    cudaGetSymbolAddress((void**)&whi,  g_whi);
    cudaGetSymbolAddress((void**)&wlo,  g_wlo);
    cudaGetSymbolAddress((void**)&inhi, g_inhi);
    cudaGetSymbolAddress((void**)&inlo, g_inlo);
    cudaGetSymbolAddress((void**)&qhi,  g_qhi);
    cudaGetSymbolAddress((void**)&qlo,  g_qlo);
    cudaGetSymbolAddress((void**)&vhi,  g_vhi);
    cudaGetSymbolAddress((void**)&vlo,  g_vlo);
    cudaGetSymbolAddress((void**)&aohi, g_aohi);
    cudaGetSymbolAddress((void**)&aolo, g_aolo);

    cudaFuncSetAttribute(gemm_bf_kernel,
                         cudaFuncAttributeMaxDynamicSharedMemorySize, GEMM_SMEM);
    cudaFuncSetAttribute(attn_mma_kernel,
                         cudaFuncAttributeMaxDynamicSharedMemorySize, ATTN_SMEM);

    // 1) preprocessing
    split_transpose4_kernel<<<dim3(D_ / 32, D_ / 32, 4), dim3(32, 8)>>>(
        Wq, Wk, Wv, Wo, whi, wlo);
    split_in_kernel<<<dim3((M_ * D_) / 1024, 3), 256>>>(q, k, v);

    // 2) projections (all-bf16 GEMM, 2 CTA/SM)
    dim3 gg(D_ / 128, M_ / 128);
    const size_t off = (size_t)M_ * D_;
    gemm_bf_kernel<<<gg, 256, GEMM_SMEM>>>(inhi + 0 * off, inlo + 0 * off,
                                           whi + 0 * D_ * D_, wlo + 0 * D_ * D_,
                                           bq, nullptr, qhi, qlo);
    gemm_bf_kernel<<<gg, 256, GEMM_SMEM>>>(inhi + 1 * off, inlo + 1 * off,
                                           whi + 1 * D_ * D_, wlo + 1 * D_ * D_,
                                           bk, pk, nullptr, nullptr);
    gemm_bf_kernel<<<gg, 256, GEMM_SMEM>>>(inhi + 2 * off, inlo + 2 * off,
                                           whi + 2 * D_ * D_, wlo + 2 * D_ * D_,
                                           bv, nullptr, vhi, vlo);

    // 3) K_eff = K + PE
    keff_kernel<<<dim3(S_, B_), 256>>>(pe);

    // 4) attention
    attn_mma_kernel<<<dim3(S_ / 128, H_, B_), 256, ATTN_SMEM>>>();

    // 5) output projection -> fp32 out
    gemm_bf_kernel<<<gg, 256, GEMM_SMEM>>>(aohi, aolo,
                                           whi + 3 * D_ * D_, wlo + 3 * D_ * D_,
                                           bo, out, nullptr, nullptr);
}

// round 10
// speedup vs baseline: 2.9541x; 1.0527x over previous
#include <cuda_runtime.h>
#include <cuda_bf16.h>
#include <cstdint>

#define B_  2
#define S_  2048
#define D_  1024
#define H_  16
#define DK_ 64
#define M_  (B_ * S_)   // 4096

// Scratch (allocation-free: __device__ globals)
__device__ float g_pet[S_ * D_];                          // PE transposed [s, h*64+dk]
__device__ __nv_bfloat16 g_inhi[3 * M_ * D_], g_inlo[3 * M_ * D_];
__device__ __nv_bfloat16 g_qhi[M_ * D_], g_qlo[M_ * D_];
__device__ __nv_bfloat16 g_khi[M_ * D_], g_klo[M_ * D_];  // K_eff = K + PE
__device__ __nv_bfloat16 g_vhi[M_ * D_], g_vlo[M_ * D_];
__device__ __nv_bfloat16 g_aohi[M_ * D_], g_aolo[M_ * D_];
__device__ __nv_bfloat16 g_whi[4 * D_ * D_];
__device__ __nv_bfloat16 g_wlo[4 * D_ * D_];

// ---------------------------------------------------------------------------
__device__ __forceinline__ uint32_t smem_u32(const void* p) {
    uint32_t a;
    asm("{ .reg .u64 t; cvta.to.shared.u64 t, %1; cvt.u32.u64 %0, t; }"
        : "=r"(a) : "l"(p));
    return a;
}
__device__ __forceinline__ uint32_t pack_bf(float a, float b) {
    uint32_t ha = __bfloat16_as_ushort(__float2bfloat16_rn(a));
    uint32_t hb = __bfloat16_as_ushort(__float2bfloat16_rn(b));
    return ha | (hb << 16);
}
__device__ __forceinline__ uint32_t pack_hilo(float a, float b, uint32_t& lo) {
    __nv_bfloat16 ha = __float2bfloat16_rn(a);
    __nv_bfloat16 hb = __float2bfloat16_rn(b);
    lo = pack_bf(a - __bfloat162float(ha), b - __bfloat162float(hb));
    return (uint32_t)__bfloat16_as_ushort(ha) |
           ((uint32_t)__bfloat16_as_ushort(hb) << 16);
}
__device__ __forceinline__ void mma16816(float c[4], const uint32_t a[4],
                                         uint32_t b0, uint32_t b1) {
    asm volatile(
        "mma.sync.aligned.m16n8k16.row.col.f32.bf16.bf16.f32 "
        "{%0,%1,%2,%3}, {%4,%5,%6,%7}, {%8,%9}, {%0,%1,%2,%3};"
        : "+f"(c[0]), "+f"(c[1]), "+f"(c[2]), "+f"(c[3])
        : "r"(a[0]), "r"(a[1]), "r"(a[2]), "r"(a[3]), "r"(b0), "r"(b1));
}
__device__ __forceinline__ void ldsm4(uint32_t r[4], uint32_t a) {
    asm volatile("ldmatrix.sync.aligned.m8n8.x4.shared.b16 {%0,%1,%2,%3}, [%4];"
        : "=r"(r[0]), "=r"(r[1]), "=r"(r[2]), "=r"(r[3]) : "r"(a));
}
__device__ __forceinline__ void ldsm4t(uint32_t r[4], uint32_t a) {
    asm volatile("ldmatrix.sync.aligned.m8n8.x4.trans.shared.b16 {%0,%1,%2,%3}, [%4];"
        : "=r"(r[0]), "=r"(r[1]), "=r"(r[2]), "=r"(r[3]) : "r"(a));
}
__device__ __forceinline__ void cp16(uint32_t dst, const void* src) {
    asm volatile("cp.async.cg.shared.global [%0], [%1], 16;"
                 :: "r"(dst), "l"(src) : "memory");
}
#define CP_COMMIT() asm volatile("cp.async.commit_group;" ::: "memory")
#define CP_WAIT0()  asm volatile("cp.async.wait_group 0;" ::: "memory")

// ===========================================================================
// Weight preprocessing (all 4 weights, one launch)
// ===========================================================================
__global__ __launch_bounds__(256) void split_transpose4_kernel(
    const float* __restrict__ W0, const float* __restrict__ W1,
    const float* __restrict__ W2, const float* __restrict__ W3,
    __nv_bfloat16* __restrict__ Th, __nv_bfloat16* __restrict__ Tl)
{
    __shared__ float t[32][33];
    const int z = blockIdx.z;
    const float* W = (z == 0) ? W0 : (z == 1) ? W1 : (z == 2) ? W2 : W3;
    Th += (size_t)z * D_ * D_;
    Tl += (size_t)z * D_ * D_;
    const int tx = threadIdx.x, ty = threadIdx.y;
    const int n0 = blockIdx.x * 32, k0 = blockIdx.y * 32;
    #pragma unroll
    for (int i = 0; i < 4; i++)
        t[ty + i * 8][tx] = W[(size_t)(k0 + ty + i * 8) * D_ + n0 + tx];
    __syncthreads();
    #pragma unroll
    for (int i = 0; i < 4; i++) {
        float x = t[tx][ty + i * 8];
        __nv_bfloat16 hi = __float2bfloat16_rn(x);
        float lo = x - __bfloat162float(hi);
        size_t o = (size_t)(n0 + ty + i * 8) * D_ + k0 + tx;
        Th[o] = hi;
        Tl[o] = __float2bfloat16_rn(lo);
    }
}

// ===========================================================================
// PE transpose: pe [D_(=h*64+dk) rows, S_ cols] -> pet [S_, D_]  (coalesced)
// ===========================================================================
__global__ __launch_bounds__(256) void pet_kernel(const float* __restrict__ pe)
{
    __shared__ float t[32][33];
    const int tx = threadIdx.x, ty = threadIdx.y;
    const int s0 = blockIdx.x * 32, d0 = blockIdx.y * 32;
    #pragma unroll
    for (int i = 0; i < 4; i++)
        t[ty + i * 8][tx] = pe[(size_t)(d0 + ty + i * 8) * S_ + s0 + tx];
    __syncthreads();
    #pragma unroll
    for (int i = 0; i < 4; i++)
        g_pet[(size_t)(s0 + ty + i * 8) * D_ + d0 + tx] = t[tx][ty + i * 8];
}

// ===========================================================================
// Input split: x fp32 -> hi/lo bf16 (z = 0,1,2 -> q,k,v)
// ===========================================================================
__global__ __launch_bounds__(256) void split_in_kernel(
    const float* __restrict__ x0, const float* __restrict__ x1,
    const float* __restrict__ x2)
{
    const int z = blockIdx.y;
    const float* x = (z == 0) ? x0 : (z == 1) ? x1 : x2;
    __nv_bfloat16* oh = g_inhi + (size_t)z * M_ * D_;
    __nv_bfloat16* ol = g_inlo + (size_t)z * M_ * D_;
    const size_t i4 = ((size_t)blockIdx.x * 256 + threadIdx.x) * 4;
    float4 v = *reinterpret_cast<const float4*>(x + i4);
    uint32_t lx, ly;
    uint2 hi, lo;
    hi.x = pack_hilo(v.x, v.y, lx);
    hi.y = pack_hilo(v.z, v.w, ly);
    lo.x = lx; lo.y = ly;
    *reinterpret_cast<uint2*>(oh + i4) = hi;
    *reinterpret_cast<uint2*>(ol + i4) = lo;
}

// ===========================================================================
// All-bf16 mma.sync GEMM, cp.async 2-stage, 2 CTAs/SM, 1 barrier/stage.
// Output modes: Cf fp32 | hi/lo bf16 (optionally adding PE from g_pet).
// ===========================================================================
#define PK2 40
#define GT_BYTES (128 * PK2 * 2)
#define GSTAGE (4 * GT_BYTES)
#define GEMM_SMEM (2 * GSTAGE)   // 81920

__global__ __launch_bounds__(256, 2)
void gemm_bf_kernel(const __nv_bfloat16* __restrict__ Ah,
                    const __nv_bfloat16* __restrict__ Al,
                    const __nv_bfloat16* __restrict__ Bh,
                    const __nv_bfloat16* __restrict__ Bl,
                    const float* __restrict__ bias,
                    float* __restrict__ Cf,
                    __nv_bfloat16* __restrict__ Chi,
                    __nv_bfloat16* __restrict__ Clo,
                    int add_pe)
{
    extern __shared__ char sm[];
    const uint32_t smb = smem_u32(sm);
    const int tid    = threadIdx.x;
    const int wid    = tid >> 5;
    const int lane   = tid & 31;
    const int warp_m = wid & 3;
    const int warp_n = wid >> 2;
    const int n0 = blockIdx.x * 128;
    const int m0 = blockIdx.y * 128;

    const int row0 = tid >> 2;
    const int c8_0 = (tid & 3) * 8;
    const uint32_t a_off = (uint32_t)((warp_m * 32 + (lane & 7) + (lane & 8)) * PK2 +
                                      ((lane >> 4) & 1) * 8) * 2;
    const uint32_t b_off = (uint32_t)((warp_n * 64 + (lane & 7) + ((lane >> 4) & 1) * 8) * PK2 +
                                      ((lane >> 3) & 1) * 8) * 2;

    float acc[2][8][4];
    #pragma unroll
    for (int mt = 0; mt < 2; mt++)
        #pragma unroll
        for (int nt = 0; nt < 8; nt++)
            #pragma unroll
            for (int i = 0; i < 4; i++) acc[mt][nt][i] = 0.f;

    auto issue = [&](int it) {
        const uint32_t sb = smb + (uint32_t)(it & 1) * GSTAGE;
        const int k0 = it * 32;
        #pragma unroll
        for (int c = 0; c < 2; c++) {
            const int row = row0 + c * 64;
            const uint32_t so = (uint32_t)(row * PK2 + c8_0) * 2;
            const size_t ga = (size_t)(m0 + row) * D_ + k0 + c8_0;
            const size_t gb = (size_t)(n0 + row) * D_ + k0 + c8_0;
            cp16(sb + 0 * GT_BYTES + so, Ah + ga);
            cp16(sb + 1 * GT_BYTES + so, Al + ga);
            cp16(sb + 2 * GT_BYTES + so, Bh + gb);
            cp16(sb + 3 * GT_BYTES + so, Bl + gb);
        }
        CP_COMMIT();
    };

    issue(0);

    for (int it = 0; it < D_ / 32; it++) {
        CP_WAIT0();
        __syncthreads();
        if (it + 1 < D_ / 32) issue(it + 1);

        const uint32_t sb = smb + (uint32_t)(it & 1) * GSTAGE;
        #pragma unroll
        for (int ks = 0; ks < 2; ks++) {
            uint32_t ah[2][4], al[2][4];
            #pragma unroll
            for (int mt = 0; mt < 2; mt++) {
                const uint32_t d = (uint32_t)(mt * 16 * PK2 + ks * 16) * 2;
                ldsm4(ah[mt], sb + 0 * GT_BYTES + a_off + d);
                ldsm4(al[mt], sb + 1 * GT_BYTES + a_off + d);
            }
            #pragma unroll
            for (int p = 0; p < 4; p++) {
                uint32_t bh[4], bl[4];
                const uint32_t d = (uint32_t)(p * 16 * PK2 + ks * 16) * 2;
                ldsm4(bh, sb + 2 * GT_BYTES + b_off + d);
                ldsm4(bl, sb + 3 * GT_BYTES + b_off + d);
                #pragma unroll
                for (int mt = 0; mt < 2; mt++) {
                    mma16816(acc[mt][2 * p],     ah[mt], bh[0], bh[1]);
                    mma16816(acc[mt][2 * p],     ah[mt], bl[0], bl[1]);
                    mma16816(acc[mt][2 * p],     al[mt], bh[0], bh[1]);
                    mma16816(acc[mt][2 * p + 1], ah[mt], bh[2], bh[3]);
                    mma16816(acc[mt][2 * p + 1], ah[mt], bl[2], bl[3]);
                    mma16816(acc[mt][2 * p + 1], al[mt], bh[2], bh[3]);
                }
            }
        }
        __syncthreads();
    }

    const int g  = lane >> 2;
    const int tg = lane & 3;
    #pragma unroll
    for (int mt = 0; mt < 2; mt++) {
        const int row = m0 + warp_m * 32 + mt * 16 + g;
        #pragma unroll
        for (int nt = 0; nt < 8; nt++) {
            const int col = n0 + warp_n * 64 + nt * 8 + 2 * tg;
            const float bx = bias[col], by = bias[col + 1];
            float v00 = acc[mt][nt][0] + bx, v01 = acc[mt][nt][1] + by;
            float v10 = acc[mt][nt][2] + bx, v11 = acc[mt][nt][3] + by;
            if (add_pe) {
                const float* p0 = g_pet + (size_t)(row & (S_ - 1)) * D_ + col;
                const float* p1 = g_pet + (size_t)((row + 8) & (S_ - 1)) * D_ + col;
                float2 e0 = *reinterpret_cast<const float2*>(p0);
                float2 e1 = *reinterpret_cast<const float2*>(p1);
                v00 += e0.x; v01 += e0.y;
                v10 += e1.x; v11 += e1.y;
            }
            if (Cf) {
                *reinterpret_cast<float2*>(Cf + (size_t)row * D_ + col) = make_float2(v00, v01);
                *reinterpret_cast<float2*>(Cf + (size_t)(row + 8) * D_ + col) = make_float2(v10, v11);
            } else {
                uint32_t l0, l1;
                const uint32_t h0 = pack_hilo(v00, v01, l0);
                const uint32_t h1 = pack_hilo(v10, v11, l1);
                *reinterpret_cast<uint32_t*>(Chi + (size_t)row * D_ + col) = h0;
                *reinterpret_cast<uint32_t*>(Clo + (size_t)row * D_ + col) = l0;
                *reinterpret_cast<uint32_t*>(Chi + (size_t)(row + 8) * D_ + col) = h1;
                *reinterpret_cast<uint32_t*>(Clo + (size_t)(row + 8) * D_ + col) = l1;
            }
        }
    }
}

// ===========================================================================
// Flash attention: 2 CTAs/SM, 1 barrier/stage.
// ===========================================================================
#define APAD 72
#define SQ_H 0
#define SQ_L (128 * APAD * 2)
#define SKV_OFF (2 * 128 * APAD * 2)
#define HALF_BYTES (64 * APAD * 2)
#define STAGE_BYTES (4 * HALF_BYTES)
#define ATTN_SMEM (SKV_OFF + 2 * STAGE_BYTES)   // 110592

__global__ __launch_bounds__(256, 2)
void attn_mma_kernel()
{
    extern __shared__ char sm[];
    const uint32_t smb = smem_u32(sm);
    const int b    = blockIdx.z;
    const int h    = blockIdx.y;
    const int q0   = blockIdx.x * 128;
    const int tid  = threadIdx.x;
    const int wid  = tid >> 5;
    const int lane = tid & 31;
    const int g    = lane >> 2;
    const int tg   = lane & 3;

    const uint32_t q_off = (uint32_t)((wid * 16 + (lane & 7) + (lane & 8)) * APAD +
                                      ((lane >> 4) & 1) * 8) * 2;
    const uint32_t k_off = (uint32_t)(((lane & 7) + ((lane >> 4) & 1) * 8) * APAD +
                                      ((lane >> 3) & 1) * 8) * 2;
    const uint32_t v_off = (uint32_t)(((lane & 7) + (lane & 8)) * APAD +
                                      ((lane >> 4) & 1) * 8) * 2;

    const size_t kvg = ((size_t)b * S_) * D_ + h * DK_;

    // Q tile -> smem
    {
        const size_t qg = ((size_t)b * S_ + q0) * D_ + h * DK_;
        #pragma unroll
        for (int i = 0; i < 4; i++) {
            const int chunk = tid + i * 256;
            const int row = chunk >> 3, c8 = (chunk & 7) * 8;
            const size_t go = qg + (size_t)row * D_ + c8;
            const int so = (row * APAD + c8) * 2;
            *reinterpret_cast<uint4*>(sm + SQ_H + so) =
                *reinterpret_cast<const uint4*>(g_qhi + go);
            *reinterpret_cast<uint4*>(sm + SQ_L + so) =
                *reinterpret_cast<const uint4*>(g_qlo + go);
        }
    }

    auto issue = [&](int it) {
        const uint32_t sbase = smb + SKV_OFF + (uint32_t)(it & 1) * STAGE_BYTES;
        const size_t tg0 = kvg + (size_t)it * 64 * D_;
        #pragma unroll
        for (int c = 0; c < 2; c++) {
            const int chunk = tid + c * 256;
            const int row = chunk >> 3, c8 = (chunk & 7) * 8;
            const uint32_t so = (uint32_t)(row * APAD + c8) * 2;
            const size_t go = tg0 + (size_t)row * D_ + c8;
            cp16(sbase + 0 * HALF_BYTES + so, g_khi + go);
            cp16(sbase + 1 * HALF_BYTES + so, g_klo + go);
            cp16(sbase + 2 * HALF_BYTES + so, g_vhi + go);
            cp16(sbase + 3 * HALF_BYTES + so, g_vlo + go);
        }
        CP_COMMIT();
    };

    issue(0);
    CP_WAIT0();
    __syncthreads();

    // Q hi fragments resident; lo reloaded per stage (register relief)
    uint32_t qh[4][4];
    #pragma unroll
    for (int ks = 0; ks < 4; ks++)
        ldsm4(qh[ks], smb + SQ_H + q_off + (uint32_t)(ks * 16) * 2);

    float m_[2] = {-1e30f, -1e30f};
    float l_[2] = {0.f, 0.f};
    float o[8][4];
    #pragma unroll
    for (int nt = 0; nt < 8; nt++)
        #pragma unroll
        for (int i = 0; i < 4; i++) o[nt][i] = 0.f;

    for (int it = 0; it < S_ / 64; it++) {
        if (it > 0) {
            CP_WAIT0();
            __syncthreads();
        }
        if (it + 1 < S_ / 64) issue(it + 1);

        const uint32_t skv = smb + SKV_OFF + (it & 1) * STAGE_BYTES;

        float s[8][4];
        #pragma unroll
        for (int nt = 0; nt < 8; nt++)
            #pragma unroll
            for (int i = 0; i < 4; i++) s[nt][i] = 0.f;

        #pragma unroll
        for (int ks = 0; ks < 4; ks++) {
            uint32_t ql[4];
            ldsm4(ql, smb + SQ_L + q_off + (uint32_t)(ks * 16) * 2);
            #pragma unroll
            for (int p = 0; p < 4; p++) {
                uint32_t kh[4], kl[4];
                const uint32_t d = (uint32_t)(p * 16 * APAD + ks * 16) * 2;
                ldsm4(kh, skv + k_off + d);
                ldsm4(kl, skv + HALF_BYTES + k_off + d);
                mma16816(s[2 * p],     qh[ks], kh[0], kh[1]);
                mma16816(s[2 * p],     qh[ks], kl[0], kl[1]);
                mma16816(s[2 * p],     ql,     kh[0], kh[1]);
                mma16816(s[2 * p + 1], qh[ks], kh[2], kh[3]);
                mma16816(s[2 * p + 1], qh[ks], kl[2], kl[3]);
                mma16816(s[2 * p + 1], ql,     kh[2], kh[3]);
            }
        }

        float mx0 = -1e30f, mx1 = -1e30f;
        #pragma unroll
        for (int nt = 0; nt < 8; nt++) {
            #pragma unroll
            for (int i = 0; i < 4; i++) s[nt][i] *= 0.125f;
            mx0 = fmaxf(mx0, fmaxf(s[nt][0], s[nt][1]));
            mx1 = fmaxf(mx1, fmaxf(s[nt][2], s[nt][3]));
        }
        mx0 = fmaxf(mx0, __shfl_xor_sync(0xffffffffu, mx0, 1));
        mx0 = fmaxf(mx0, __shfl_xor_sync(0xffffffffu, mx0, 2));
        mx1 = fmaxf(mx1, __shfl_xor_sync(0xffffffffu, mx1, 1));
        mx1 = fmaxf(mx1, __shfl_xor_sync(0xffffffffu, mx1, 2));

        const float mn0 = fmaxf(m_[0], mx0);
        const float mn1 = fmaxf(m_[1], mx1);
        const float c0 = __expf(m_[0] - mn0);
        const float c1 = __expf(m_[1] - mn1);
        m_[0] = mn0; m_[1] = mn1;

        float r0 = 0.f, r1 = 0.f;
        #pragma unroll
        for (int nt = 0; nt < 8; nt++) {
            s[nt][0] = __expf(s[nt][0] - mn0);
            s[nt][1] = __expf(s[nt][1] - mn0);
            s[nt][2] = __expf(s[nt][2] - mn1);
            s[nt][3] = __expf(s[nt][3] - mn1);
            r0 += s[nt][0] + s[nt][1];
            r1 += s[nt][2] + s[nt][3];
        }
        r0 += __shfl_xor_sync(0xffffffffu, r0, 1);
        r0 += __shfl_xor_sync(0xffffffffu, r0, 2);
        r1 += __shfl_xor_sync(0xffffffffu, r1, 1);
        r1 += __shfl_xor_sync(0xffffffffu, r1, 2);
        l_[0] = l_[0] * c0 + r0;
        l_[1] = l_[1] * c1 + r1;

        #pragma unroll
        for (int nt = 0; nt < 8; nt++) {
            o[nt][0] *= c0; o[nt][1] *= c0;
            o[nt][2] *= c1; o[nt][3] *= c1;
        }

        #pragma unroll
        for (int jp = 0; jp < 4; jp++) {
            uint32_t ph[4], pl[4];
            ph[0] = pack_hilo(s[2 * jp][0],     s[2 * jp][1],     pl[0]);
            ph[1] = pack_hilo(s[2 * jp][2],     s[2 * jp][3],     pl[1]);
            ph[2] = pack_hilo(s[2 * jp + 1][0], s[2 * jp + 1][1], pl[2]);
            ph[3] = pack_hilo(s[2 * jp + 1][2], s[2 * jp + 1][3], pl[3]);
            #pragma unroll
            for (int p = 0; p < 4; p++) {
                uint32_t vh[4], vl[4];
                const uint32_t d = (uint32_t)(jp * 16 * APAD + p * 16) * 2;
                ldsm4t(vh, skv + 2 * HALF_BYTES + v_off + d);
                ldsm4t(vl, skv + 3 * HALF_BYTES + v_off + d);
                mma16816(o[2 * p],     ph, vh[0], vh[1]);
                mma16816(o[2 * p],     ph, vl[0], vl[1]);
                mma16816(o[2 * p],     pl, vh[0], vh[1]);
                mma16816(o[2 * p + 1], ph, vh[2], vh[3]);
                mma16816(o[2 * p + 1], ph, vl[2], vl[3]);
                mma16816(o[2 * p + 1], pl, vh[2], vh[3]);
            }
        }
        __syncthreads();   // all warps done with buffer (it&1) before reuse
    }

    const float inv0 = 1.f / l_[0];
    const float inv1 = 1.f / l_[1];
    const int row = q0 + wid * 16 + g;
    const size_t ob = ((size_t)b * S_ + row) * D_ + h * DK_;
    #pragma unroll
    for (int nt = 0; nt < 8; nt++) {
        const int col = nt * 8 + 2 * tg;
        uint32_t l0, l1;
        const uint32_t h0 = pack_hilo(o[nt][0] * inv0, o[nt][1] * inv0, l0);
        const uint32_t h1 = pack_hilo(o[nt][2] * inv1, o[nt][3] * inv1, l1);
        *reinterpret_cast<uint32_t*>(g_aohi + ob + col) = h0;
        *reinterpret_cast<uint32_t*>(g_aolo + ob + col) = l0;
        *reinterpret_cast<uint32_t*>(g_aohi + ob + (size_t)8 * D_ + col) = h1;
        *reinterpret_cast<uint32_t*>(g_aolo + ob + (size_t)8 * D_ + col) = l1;
    }
}

// ===========================================================================
extern "C" void kernel_launch(void* const* d_in, const int* in_sizes, int n_in,
                              void* d_out, int out_size)
{
    const float* q  = (const float*)d_in[0];
    const float* k  = (const float*)d_in[1];
    const float* v  = (const float*)d_in[2];
    const float* pe = (const float*)d_in[3];
    const float* Wq = (const float*)d_in[4];
    const float* bq = (const float*)d_in[5];
    const float* Wk = (const float*)d_in[6];
    const float* bk = (const float*)d_in[7];
    const float* Wv = (const float*)d_in[8];
    const float* bv = (const float*)d_in[9];
    const float* Wo = (const float*)d_in[10];
    const float* bo = (const float*)d_in[11];
    float* out = (float*)d_out;

    __nv_bfloat16 *whi, *wlo, *inhi, *inlo, *qhi, *qlo, *khi, *klo, *vhi, *vlo, *aohi, *aolo;
    cudaGetSymbolAddress((void**)&whi,  g_whi);
    cudaGetSymbolAddress((void**)&wlo,  g_wlo);
    cudaGetSymbolAddress((void**)&inhi, g_inhi);
    cudaGetSymbolAddress((void**)&inlo, g_inlo);
    cudaGetSymbolAddress((void**)&qhi,  g_qhi);
    cudaGetSymbolAddress((void**)&qlo,  g_qlo);
    cudaGetSymbolAddress((void**)&khi,  g_khi);
    cudaGetSymbolAddress((void**)&klo,  g_klo);
    cudaGetSymbolAddress((void**)&vhi,  g_vhi);
    cudaGetSymbolAddress((void**)&vlo,  g_vlo);
    cudaGetSymbolAddress((void**)&aohi, g_aohi);
    cudaGetSymbolAddress((void**)&aolo, g_aolo);

    cudaFuncSetAttribute(gemm_bf_kernel,
                         cudaFuncAttributeMaxDynamicSharedMemorySize, GEMM_SMEM);
    cudaFuncSetAttribute(attn_mma_kernel,
                         cudaFuncAttributeMaxDynamicSharedMemorySize, ATTN_SMEM);

    // 1) preprocessing
    split_transpose4_kernel<<<dim3(D_ / 32, D_ / 32, 4), dim3(32, 8)>>>(
        Wq, Wk, Wv, Wo, whi, wlo);
    pet_kernel<<<dim3(S_ / 32, D_ / 32), dim3(32, 8)>>>(pe);
    split_in_kernel<<<dim3((M_ * D_) / 1024, 3), 256>>>(q, k, v);

    // 2) projections (K writes K_eff = K + PE directly)
    dim3 gg(D_ / 128, M_ / 128);
    const size_t off = (size_t)M_ * D_;
    gemm_bf_kernel<<<gg, 256, GEMM_SMEM>>>(inhi + 0 * off, inlo + 0 * off,
                                           whi + 0 * D_ * D_, wlo + 0 * D_ * D_,
                                           bq, nullptr, qhi, qlo, 0);
    gemm_bf_kernel<<<gg, 256, GEMM_SMEM>>>(inhi + 1 * off, inlo + 1 * off,
                                           whi + 1 * D_ * D_, wlo + 1 * D_ * D_,
                                           bk, nullptr, khi, klo, 1);
    gemm_bf_kernel<<<gg, 256, GEMM_SMEM>>>(inhi + 2 * off, inlo + 2 * off,
                                           whi + 2 * D_ * D_, wlo + 2 * D_ * D_,
                                           bv, nullptr, vhi, vlo, 0);

    // 3) attention
    attn_mma_kernel<<<dim3(S_ / 128, H_, B_), 256, ATTN_SMEM>>>();

    // 4) output projection -> fp32 out
    gemm_bf_kernel<<<gg, 256, GEMM_SMEM>>>(aohi, aolo,
                                           whi + 3 * D_ * D_, wlo + 3 * D_ * D_,
                                           bo, out, nullptr, nullptr, 0);
}

// round 11
// speedup vs baseline: 3.0070x; 1.0179x over previous
#include <cuda_runtime.h>
#include <cuda_bf16.h>
#include <cstdint>

#define B_  2
#define S_  2048
#define D_  1024
#define H_  16
#define DK_ 64
#define M_  (B_ * S_)   // 4096

// Scratch (allocation-free: __device__ globals)
__device__ float g_pet[S_ * D_];                          // PE transposed [s, h*64+dk]
__device__ __nv_bfloat16 g_inhi[3 * M_ * D_], g_inlo[3 * M_ * D_];
__device__ __nv_bfloat16 g_qhi[M_ * D_], g_qlo[M_ * D_];
__device__ __nv_bfloat16 g_khi[M_ * D_], g_klo[M_ * D_];  // K_eff = K + PE
__device__ __nv_bfloat16 g_vhi[M_ * D_], g_vlo[M_ * D_];
__device__ __nv_bfloat16 g_aohi[M_ * D_], g_aolo[M_ * D_];
__device__ __nv_bfloat16 g_whi[4 * D_ * D_];
__device__ __nv_bfloat16 g_wlo[4 * D_ * D_];

// ---------------------------------------------------------------------------
__device__ __forceinline__ uint32_t smem_u32(const void* p) {
    uint32_t a;
    asm("{ .reg .u64 t; cvta.to.shared.u64 t, %1; cvt.u32.u64 %0, t; }"
        : "=r"(a) : "l"(p));
    return a;
}
__device__ __forceinline__ uint32_t pack_bf(float a, float b) {
    uint32_t ha = __bfloat16_as_ushort(__float2bfloat16_rn(a));
    uint32_t hb = __bfloat16_as_ushort(__float2bfloat16_rn(b));
    return ha | (hb << 16);
}
__device__ __forceinline__ uint32_t pack_hilo(float a, float b, uint32_t& lo) {
    __nv_bfloat16 ha = __float2bfloat16_rn(a);
    __nv_bfloat16 hb = __float2bfloat16_rn(b);
    lo = pack_bf(a - __bfloat162float(ha), b - __bfloat162float(hb));
    return (uint32_t)__bfloat16_as_ushort(ha) |
           ((uint32_t)__bfloat16_as_ushort(hb) << 16);
}
__device__ __forceinline__ void mma16816(float c[4], const uint32_t a[4],
                                         uint32_t b0, uint32_t b1) {
    asm volatile(
        "mma.sync.aligned.m16n8k16.row.col.f32.bf16.bf16.f32 "
        "{%0,%1,%2,%3}, {%4,%5,%6,%7}, {%8,%9}, {%0,%1,%2,%3};"
        : "+f"(c[0]), "+f"(c[1]), "+f"(c[2]), "+f"(c[3])
        : "r"(a[0]), "r"(a[1]), "r"(a[2]), "r"(a[3]), "r"(b0), "r"(b1));
}
__device__ __forceinline__ void ldsm4(uint32_t r[4], uint32_t a) {
    asm volatile("ldmatrix.sync.aligned.m8n8.x4.shared.b16 {%0,%1,%2,%3}, [%4];"
        : "=r"(r[0]), "=r"(r[1]), "=r"(r[2]), "=r"(r[3]) : "r"(a));
}
__device__ __forceinline__ void ldsm4t(uint32_t r[4], uint32_t a) {
    asm volatile("ldmatrix.sync.aligned.m8n8.x4.trans.shared.b16 {%0,%1,%2,%3}, [%4];"
        : "=r"(r[0]), "=r"(r[1]), "=r"(r[2]), "=r"(r[3]) : "r"(a));
}
__device__ __forceinline__ void cp16(uint32_t dst, const void* src) {
    asm volatile("cp.async.cg.shared.global [%0], [%1], 16;"
                 :: "r"(dst), "l"(src) : "memory");
}
#define CP_COMMIT() asm volatile("cp.async.commit_group;" ::: "memory")
#define CP_WAIT0()  asm volatile("cp.async.wait_group 0;" ::: "memory")

// ===========================================================================
// Weight preprocessing (all 4 weights, one launch)
// ===========================================================================
__global__ __launch_bounds__(256) void split_transpose4_kernel(
    const float* __restrict__ W0, const float* __restrict__ W1,
    const float* __restrict__ W2, const float* __restrict__ W3,
    __nv_bfloat16* __restrict__ Th, __nv_bfloat16* __restrict__ Tl)
{
    __shared__ float t[32][33];
    const int z = blockIdx.z;
    const float* W = (z == 0) ? W0 : (z == 1) ? W1 : (z == 2) ? W2 : W3;
    Th += (size_t)z * D_ * D_;
    Tl += (size_t)z * D_ * D_;
    const int tx = threadIdx.x, ty = threadIdx.y;
    const int n0 = blockIdx.x * 32, k0 = blockIdx.y * 32;
    #pragma unroll
    for (int i = 0; i < 4; i++)
        t[ty + i * 8][tx] = W[(size_t)(k0 + ty + i * 8) * D_ + n0 + tx];
    __syncthreads();
    #pragma unroll
    for (int i = 0; i < 4; i++) {
        float x = t[tx][ty + i * 8];
        __nv_bfloat16 hi = __float2bfloat16_rn(x);
        float lo = x - __bfloat162float(hi);
        size_t o = (size_t)(n0 + ty + i * 8) * D_ + k0 + tx;
        Th[o] = hi;
        Tl[o] = __float2bfloat16_rn(lo);
    }
}

// ===========================================================================
// PE transpose: pe [D_, S_] -> pet [S_, D_]
// ===========================================================================
__global__ __launch_bounds__(256) void pet_kernel(const float* __restrict__ pe)
{
    __shared__ float t[32][33];
    const int tx = threadIdx.x, ty = threadIdx.y;
    const int s0 = blockIdx.x * 32, d0 = blockIdx.y * 32;
    #pragma unroll
    for (int i = 0; i < 4; i++)
        t[ty + i * 8][tx] = pe[(size_t)(d0 + ty + i * 8) * S_ + s0 + tx];
    __syncthreads();
    #pragma unroll
    for (int i = 0; i < 4; i++)
        g_pet[(size_t)(s0 + ty + i * 8) * D_ + d0 + tx] = t[tx][ty + i * 8];
}

// ===========================================================================
// Input split: x fp32 -> hi/lo bf16
// ===========================================================================
__global__ __launch_bounds__(256) void split_in_kernel(
    const float* __restrict__ x0, const float* __restrict__ x1,
    const float* __restrict__ x2)
{
    const int z = blockIdx.y;
    const float* x = (z == 0) ? x0 : (z == 1) ? x1 : x2;
    __nv_bfloat16* oh = g_inhi + (size_t)z * M_ * D_;
    __nv_bfloat16* ol = g_inlo + (size_t)z * M_ * D_;
    const size_t i4 = ((size_t)blockIdx.x * 256 + threadIdx.x) * 4;
    float4 v = *reinterpret_cast<const float4*>(x + i4);
    uint32_t lx, ly;
    uint2 hi, lo;
    hi.x = pack_hilo(v.x, v.y, lx);
    hi.y = pack_hilo(v.z, v.w, ly);
    lo.x = lx; lo.y = ly;
    *reinterpret_cast<uint2*>(oh + i4) = hi;
    *reinterpret_cast<uint2*>(ol + i4) = lo;
}

// ===========================================================================
// GEMM core (inlined): cp.async 2-stage, pass-major mma emission.
// ===========================================================================
#define PK2 40
#define GT_BYTES (128 * PK2 * 2)
#define GSTAGE (4 * GT_BYTES)
#define GEMM_SMEM (2 * GSTAGE)   // 81920

__device__ __forceinline__ void gemm_core(
    const __nv_bfloat16* __restrict__ Ah, const __nv_bfloat16* __restrict__ Al,
    const __nv_bfloat16* __restrict__ Bh, const __nv_bfloat16* __restrict__ Bl,
    const float* __restrict__ bias,
    float* __restrict__ Cf,
    __nv_bfloat16* __restrict__ Chi, __nv_bfloat16* __restrict__ Clo,
    int add_pe, char* sm, int m0, int n0)
{
    const uint32_t smb = smem_u32(sm);
    const int tid    = threadIdx.x;
    const int wid    = tid >> 5;
    const int lane   = tid & 31;
    const int warp_m = wid & 3;
    const int warp_n = wid >> 2;

    const int row0 = tid >> 2;
    const int c8_0 = (tid & 3) * 8;
    const uint32_t a_off = (uint32_t)((warp_m * 32 + (lane & 7) + (lane & 8)) * PK2 +
                                      ((lane >> 4) & 1) * 8) * 2;
    const uint32_t b_off = (uint32_t)((warp_n * 64 + (lane & 7) + ((lane >> 4) & 1) * 8) * PK2 +
                                      ((lane >> 3) & 1) * 8) * 2;

    float acc[2][8][4];
    #pragma unroll
    for (int mt = 0; mt < 2; mt++)
        #pragma unroll
        for (int nt = 0; nt < 8; nt++)
            #pragma unroll
            for (int i = 0; i < 4; i++) acc[mt][nt][i] = 0.f;

    auto issue = [&](int it) {
        const uint32_t sb = smb + (uint32_t)(it & 1) * GSTAGE;
        const int k0 = it * 32;
        #pragma unroll
        for (int c = 0; c < 2; c++) {
            const int row = row0 + c * 64;
            const uint32_t so = (uint32_t)(row * PK2 + c8_0) * 2;
            const size_t ga = (size_t)(m0 + row) * D_ + k0 + c8_0;
            const size_t gb = (size_t)(n0 + row) * D_ + k0 + c8_0;
            cp16(sb + 0 * GT_BYTES + so, Ah + ga);
            cp16(sb + 1 * GT_BYTES + so, Al + ga);
            cp16(sb + 2 * GT_BYTES + so, Bh + gb);
            cp16(sb + 3 * GT_BYTES + so, Bl + gb);
        }
        CP_COMMIT();
    };

    issue(0);

    for (int it = 0; it < D_ / 32; it++) {
        CP_WAIT0();
        __syncthreads();
        if (it + 1 < D_ / 32) issue(it + 1);

        const uint32_t sb = smb + (uint32_t)(it & 1) * GSTAGE;
        #pragma unroll
        for (int ks = 0; ks < 2; ks++) {
            uint32_t ah[2][4], al[2][4];
            #pragma unroll
            for (int mt = 0; mt < 2; mt++) {
                const uint32_t d = (uint32_t)(mt * 16 * PK2 + ks * 16) * 2;
                ldsm4(ah[mt], sb + 0 * GT_BYTES + a_off + d);
                ldsm4(al[mt], sb + 1 * GT_BYTES + a_off + d);
            }
            #pragma unroll
            for (int p = 0; p < 4; p++) {
                uint32_t bh[4], bl[4];
                const uint32_t d = (uint32_t)(p * 16 * PK2 + ks * 16) * 2;
                ldsm4(bh, sb + 2 * GT_BYTES + b_off + d);
                ldsm4(bl, sb + 3 * GT_BYTES + b_off + d);
                // pass-major emission: dependent hits on each acc spaced by 4
                #pragma unroll
                for (int mt = 0; mt < 2; mt++) {
                    mma16816(acc[mt][2 * p],     ah[mt], bh[0], bh[1]);
                    mma16816(acc[mt][2 * p + 1], ah[mt], bh[2], bh[3]);
                }
                #pragma unroll
                for (int mt = 0; mt < 2; mt++) {
                    mma16816(acc[mt][2 * p],     ah[mt], bl[0], bl[1]);
                    mma16816(acc[mt][2 * p + 1], ah[mt], bl[2], bl[3]);
                }
                #pragma unroll
                for (int mt = 0; mt < 2; mt++) {
                    mma16816(acc[mt][2 * p],     al[mt], bh[0], bh[1]);
                    mma16816(acc[mt][2 * p + 1], al[mt], bh[2], bh[3]);
                }
            }
        }
        __syncthreads();
    }

    const int g  = lane >> 2;
    const int tg = lane & 3;
    #pragma unroll
    for (int mt = 0; mt < 2; mt++) {
        const int row = m0 + warp_m * 32 + mt * 16 + g;
        #pragma unroll
        for (int nt = 0; nt < 8; nt++) {
            const int col = n0 + warp_n * 64 + nt * 8 + 2 * tg;
            const float bx = bias[col], by = bias[col + 1];
            float v00 = acc[mt][nt][0] + bx, v01 = acc[mt][nt][1] + by;
            float v10 = acc[mt][nt][2] + bx, v11 = acc[mt][nt][3] + by;
            if (add_pe) {
                const float* p0 = g_pet + (size_t)(row & (S_ - 1)) * D_ + col;
                const float* p1 = g_pet + (size_t)((row + 8) & (S_ - 1)) * D_ + col;
                float2 e0 = *reinterpret_cast<const float2*>(p0);
                float2 e1 = *reinterpret_cast<const float2*>(p1);
                v00 += e0.x; v01 += e0.y;
                v10 += e1.x; v11 += e1.y;
            }
            if (Cf) {
                *reinterpret_cast<float2*>(Cf + (size_t)row * D_ + col) = make_float2(v00, v01);
                *reinterpret_cast<float2*>(Cf + (size_t)(row + 8) * D_ + col) = make_float2(v10, v11);
            } else {
                uint32_t l0, l1;
                const uint32_t h0 = pack_hilo(v00, v01, l0);
                const uint32_t h1 = pack_hilo(v10, v11, l1);
                *reinterpret_cast<uint32_t*>(Chi + (size_t)row * D_ + col) = h0;
                *reinterpret_cast<uint32_t*>(Clo + (size_t)row * D_ + col) = l0;
                *reinterpret_cast<uint32_t*>(Chi + (size_t)(row + 8) * D_ + col) = h1;
                *reinterpret_cast<uint32_t*>(Clo + (size_t)(row + 8) * D_ + col) = l1;
            }
        }
    }
}

// Batched Q/K/V projection: blockIdx.z selects tensor.
__global__ __launch_bounds__(256, 2)
void qkv_gemm_kernel(const float* __restrict__ bq,
                     const float* __restrict__ bk,
                     const float* __restrict__ bv)
{
    extern __shared__ char sm[];
    const int z = blockIdx.z;
    const size_t off = (size_t)M_ * D_;
    const __nv_bfloat16* Ah = g_inhi + z * off;
    const __nv_bfloat16* Al = g_inlo + z * off;
    const __nv_bfloat16* Bh = g_whi + (size_t)z * D_ * D_;
    const __nv_bfloat16* Bl = g_wlo + (size_t)z * D_ * D_;
    const float* bias = (z == 0) ? bq : (z == 1) ? bk : bv;
    __nv_bfloat16* Chi = (z == 0) ? g_qhi : (z == 1) ? g_khi : g_vhi;
    __nv_bfloat16* Clo = (z == 0) ? g_qlo : (z == 1) ? g_klo : g_vlo;
    gemm_core(Ah, Al, Bh, Bl, bias, nullptr, Chi, Clo, (z == 1),
              sm, blockIdx.y * 128, blockIdx.x * 128);
}

// Output projection -> fp32.
__global__ __launch_bounds__(256, 2)
void oproj_gemm_kernel(const float* __restrict__ bo, float* __restrict__ out)
{
    extern __shared__ char sm[];
    gemm_core(g_aohi, g_aolo, g_whi + 3 * D_ * D_, g_wlo + 3 * D_ * D_,
              bo, out, nullptr, nullptr, 0,
              sm, blockIdx.y * 128, blockIdx.x * 128);
}

// ===========================================================================
// Flash attention: 2 CTAs/SM, pass-major mma emission.
// ===========================================================================
#define APAD 72
#define SQ_H 0
#define SQ_L (128 * APAD * 2)
#define SKV_OFF (2 * 128 * APAD * 2)
#define HALF_BYTES (64 * APAD * 2)
#define STAGE_BYTES (4 * HALF_BYTES)
#define ATTN_SMEM (SKV_OFF + 2 * STAGE_BYTES)   // 110592

__global__ __launch_bounds__(256, 2)
void attn_mma_kernel()
{
    extern __shared__ char sm[];
    const uint32_t smb = smem_u32(sm);
    const int b    = blockIdx.z;
    const int h    = blockIdx.y;
    const int q0   = blockIdx.x * 128;
    const int tid  = threadIdx.x;
    const int wid  = tid >> 5;
    const int lane = tid & 31;
    const int g    = lane >> 2;
    const int tg   = lane & 3;

    const uint32_t q_off = (uint32_t)((wid * 16 + (lane & 7) + (lane & 8)) * APAD +
                                      ((lane >> 4) & 1) * 8) * 2;
    const uint32_t k_off = (uint32_t)(((lane & 7) + ((lane >> 4) & 1) * 8) * APAD +
                                      ((lane >> 3) & 1) * 8) * 2;
    const uint32_t v_off = (uint32_t)(((lane & 7) + (lane & 8)) * APAD +
                                      ((lane >> 4) & 1) * 8) * 2;

    const size_t kvg = ((size_t)b * S_) * D_ + h * DK_;

    {
        const size_t qg = ((size_t)b * S_ + q0) * D_ + h * DK_;
        #pragma unroll
        for (int i = 0; i < 4; i++) {
            const int chunk = tid + i * 256;
            const int row = chunk >> 3, c8 = (chunk & 7) * 8;
            const size_t go = qg + (size_t)row * D_ + c8;
            const int so = (row * APAD + c8) * 2;
            *reinterpret_cast<uint4*>(sm + SQ_H + so) =
                *reinterpret_cast<const uint4*>(g_qhi + go);
            *reinterpret_cast<uint4*>(sm + SQ_L + so) =
                *reinterpret_cast<const uint4*>(g_qlo + go);
        }
    }

    auto issue = [&](int it) {
        const uint32_t sbase = smb + SKV_OFF + (uint32_t)(it & 1) * STAGE_BYTES;
        const size_t tg0 = kvg + (size_t)it * 64 * D_;
        #pragma unroll
        for (int c = 0; c < 2; c++) {
            const int chunk = tid + c * 256;
            const int row = chunk >> 3, c8 = (chunk & 7) * 8;
            const uint32_t so = (uint32_t)(row * APAD + c8) * 2;
            const size_t go = tg0 + (size_t)row * D_ + c8;
            cp16(sbase + 0 * HALF_BYTES + so, g_khi + go);
            cp16(sbase + 1 * HALF_BYTES + so, g_klo + go);
            cp16(sbase + 2 * HALF_BYTES + so, g_vhi + go);
            cp16(sbase + 3 * HALF_BYTES + so, g_vlo + go);
        }
        CP_COMMIT();
    };

    issue(0);
    CP_WAIT0();
    __syncthreads();

    uint32_t qh[4][4];
    #pragma unroll
    for (int ks = 0; ks < 4; ks++)
        ldsm4(qh[ks], smb + SQ_H + q_off + (uint32_t)(ks * 16) * 2);

    float m_[2] = {-1e30f, -1e30f};
    float l_[2] = {0.f, 0.f};
    float o[8][4];
    #pragma unroll
    for (int nt = 0; nt < 8; nt++)
        #pragma unroll
        for (int i = 0; i < 4; i++) o[nt][i] = 0.f;

    for (int it = 0; it < S_ / 64; it++) {
        if (it > 0) {
            CP_WAIT0();
            __syncthreads();
        }
        if (it + 1 < S_ / 64) issue(it + 1);

        const uint32_t skv = smb + SKV_OFF + (it & 1) * STAGE_BYTES;

        float s[8][4];
        #pragma unroll
        for (int nt = 0; nt < 8; nt++)
            #pragma unroll
            for (int i = 0; i < 4; i++) s[nt][i] = 0.f;

        #pragma unroll
        for (int ks = 0; ks < 4; ks++) {
            uint32_t ql[4];
            ldsm4(ql, smb + SQ_L + q_off + (uint32_t)(ks * 16) * 2);
            #pragma unroll
            for (int p = 0; p < 4; p++) {
                uint32_t kh[4], kl[4];
                const uint32_t d = (uint32_t)(p * 16 * APAD + ks * 16) * 2;
                ldsm4(kh, skv + k_off + d);
                ldsm4(kl, skv + HALF_BYTES + k_off + d);
                // pass-major within p: chain spacing 2
                mma16816(s[2 * p],     qh[ks], kh[0], kh[1]);
                mma16816(s[2 * p + 1], qh[ks], kh[2], kh[3]);
                mma16816(s[2 * p],     qh[ks], kl[0], kl[1]);
                mma16816(s[2 * p + 1], qh[ks], kl[2], kl[3]);
                mma16816(s[2 * p],     ql,     kh[0], kh[1]);
                mma16816(s[2 * p + 1], ql,     kh[2], kh[3]);
            }
        }

        float mx0 = -1e30f, mx1 = -1e30f;
        #pragma unroll
        for (int nt = 0; nt < 8; nt++) {
            #pragma unroll
            for (int i = 0; i < 4; i++) s[nt][i] *= 0.125f;
            mx0 = fmaxf(mx0, fmaxf(s[nt][0], s[nt][1]));
            mx1 = fmaxf(mx1, fmaxf(s[nt][2], s[nt][3]));
        }
        mx0 = fmaxf(mx0, __shfl_xor_sync(0xffffffffu, mx0, 1));
        mx0 = fmaxf(mx0, __shfl_xor_sync(0xffffffffu, mx0, 2));
        mx1 = fmaxf(mx1, __shfl_xor_sync(0xffffffffu, mx1, 1));
        mx1 = fmaxf(mx1, __shfl_xor_sync(0xffffffffu, mx1, 2));

        const float mn0 = fmaxf(m_[0], mx0);
        const float mn1 = fmaxf(m_[1], mx1);
        const float c0 = __expf(m_[0] - mn0);
        const float c1 = __expf(m_[1] - mn1);
        m_[0] = mn0; m_[1] = mn1;

        float r0 = 0.f, r1 = 0.f;
        #pragma unroll
        for (int nt = 0; nt < 8; nt++) {
            s[nt][0] = __expf(s[nt][0] - mn0);
            s[nt][1] = __expf(s[nt][1] - mn0);
            s[nt][2] = __expf(s[nt][2] - mn1);
            s[nt][3] = __expf(s[nt][3] - mn1);
            r0 += s[nt][0] + s[nt][1];
            r1 += s[nt][2] + s[nt][3];
        }
        r0 += __shfl_xor_sync(0xffffffffu, r0, 1);
        r0 += __shfl_xor_sync(0xffffffffu, r0, 2);
        r1 += __shfl_xor_sync(0xffffffffu, r1, 1);
        r1 += __shfl_xor_sync(0xffffffffu, r1, 2);
        l_[0] = l_[0] * c0 + r0;
        l_[1] = l_[1] * c1 + r1;

        #pragma unroll
        for (int nt = 0; nt < 8; nt++) {
            o[nt][0] *= c0; o[nt][1] *= c0;
            o[nt][2] *= c1; o[nt][3] *= c1;
        }

        #pragma unroll
        for (int jp = 0; jp < 4; jp++) {
            uint32_t ph[4], pl[4];
            ph[0] = pack_hilo(s[2 * jp][0],     s[2 * jp][1],     pl[0]);
            ph[1] = pack_hilo(s[2 * jp][2],     s[2 * jp][3],     pl[1]);
            ph[2] = pack_hilo(s[2 * jp + 1][0], s[2 * jp + 1][1], pl[2]);
            ph[3] = pack_hilo(s[2 * jp + 1][2], s[2 * jp + 1][3], pl[3]);
            #pragma unroll
            for (int p = 0; p < 4; p++) {
                uint32_t vh[4], vl[4];
                const uint32_t d = (uint32_t)(jp * 16 * APAD + p * 16) * 2;
                ldsm4t(vh, skv + 2 * HALF_BYTES + v_off + d);
                ldsm4t(vl, skv + 3 * HALF_BYTES + v_off + d);
                // pass-major within p: chain spacing 2
                mma16816(o[2 * p],     ph, vh[0], vh[1]);
                mma16816(o[2 * p + 1], ph, vh[2], vh[3]);
                mma16816(o[2 * p],     ph, vl[0], vl[1]);
                mma16816(o[2 * p + 1], ph, vl[2], vl[3]);
                mma16816(o[2 * p],     pl, vh[0], vh[1]);
                mma16816(o[2 * p + 1], pl, vh[2], vh[3]);
            }
        }
        __syncthreads();
    }

    const float inv0 = 1.f / l_[0];
    const float inv1 = 1.f / l_[1];
    const int row = q0 + wid * 16 + g;
    const size_t ob = ((size_t)b * S_ + row) * D_ + h * DK_;
    #pragma unroll
    for (int nt = 0; nt < 8; nt++) {
        const int col = nt * 8 + 2 * tg;
        uint32_t l0, l1;
        const uint32_t h0 = pack_hilo(o[nt][0] * inv0, o[nt][1] * inv0, l0);
        const uint32_t h1 = pack_hilo(o[nt][2] * inv1, o[nt][3] * inv1, l1);
        *reinterpret_cast<uint32_t*>(g_aohi + ob + col) = h0;
        *reinterpret_cast<uint32_t*>(g_aolo + ob + col) = l0;
        *reinterpret_cast<uint32_t*>(g_aohi + ob + (size_t)8 * D_ + col) = h1;
        *reinterpret_cast<uint32_t*>(g_aolo + ob + (size_t)8 * D_ + col) = l1;
    }
}

// ===========================================================================
extern "C" void kernel_launch(void* const* d_in, const int* in_sizes, int n_in,
                              void* d_out, int out_size)
{
    const float* q  = (const float*)d_in[0];
    const float* k  = (const float*)d_in[1];
    const float* v  = (const float*)d_in[2];
    const float* pe = (const float*)d_in[3];
    const float* Wq = (const float*)d_in[4];
    const float* bq = (const float*)d_in[5];
    const float* Wk = (const float*)d_in[6];
    const float* bk = (const float*)d_in[7];
    const float* Wv = (const float*)d_in[8];
    const float* bv = (const float*)d_in[9];
    const float* Wo = (const float*)d_in[10];
    const float* bo = (const float*)d_in[11];
    float* out = (float*)d_out;

    __nv_bfloat16 *whi, *wlo;
    cudaGetSymbolAddress((void**)&whi, g_whi);
    cudaGetSymbolAddress((void**)&wlo, g_wlo);

    cudaFuncSetAttribute(qkv_gemm_kernel,
                         cudaFuncAttributeMaxDynamicSharedMemorySize, GEMM_SMEM);
    cudaFuncSetAttribute(oproj_gemm_kernel,
                         cudaFuncAttributeMaxDynamicSharedMemorySize, GEMM_SMEM);
    cudaFuncSetAttribute(attn_mma_kernel,
                         cudaFuncAttributeMaxDynamicSharedMemorySize, ATTN_SMEM);

    // 1) preprocessing
    split_transpose4_kernel<<<dim3(D_ / 32, D_ / 32, 4), dim3(32, 8)>>>(
        Wq, Wk, Wv, Wo, whi, wlo);
    pet_kernel<<<dim3(S_ / 32, D_ / 32), dim3(32, 8)>>>(pe);
    split_in_kernel<<<dim3((M_ * D_) / 1024, 3), 256>>>(q, k, v);

    // 2) batched Q/K/V projections (K gets +PE in epilogue)
    qkv_gemm_kernel<<<dim3(D_ / 128, M_ / 128, 3), 256, GEMM_SMEM>>>(bq, bk, bv);

    // 3) attention
    attn_mma_kernel<<<dim3(S_ / 128, H_, B_), 256, ATTN_SMEM>>>();

    // 4) output projection -> fp32 out
    oproj_gemm_kernel<<<dim3(D_ / 128, M_ / 128), 256, GEMM_SMEM>>>(bo, out);
}

// round 13
// speedup vs baseline: 3.0491x; 1.0140x over previous
#include <cuda_runtime.h>
#include <cuda_bf16.h>
#include <cstdint>

#define B_  2
#define S_  2048
#define D_  1024
#define H_  16
#define DK_ 64
#define M_  (B_ * S_)   // 4096

// Scratch (allocation-free: __device__ globals)
__device__ float g_pet[S_ * D_];                          // PE transposed [s, h*64+dk]
__device__ __nv_bfloat16 g_inhi[3 * M_ * D_], g_inlo[3 * M_ * D_];
__device__ __nv_bfloat16 g_qhi[M_ * D_], g_qlo[M_ * D_];
__device__ __nv_bfloat16 g_khi[M_ * D_], g_klo[M_ * D_];  // K_eff = K + PE
__device__ __nv_bfloat16 g_vhi[M_ * D_], g_vlo[M_ * D_];
__device__ __nv_bfloat16 g_aohi[M_ * D_], g_aolo[M_ * D_];
__device__ __nv_bfloat16 g_whi[4 * D_ * D_];
__device__ __nv_bfloat16 g_wlo[4 * D_ * D_];

// ---------------------------------------------------------------------------
__device__ __forceinline__ uint32_t smem_u32(const void* p) {
    uint32_t a;
    asm("{ .reg .u64 t; cvta.to.shared.u64 t, %1; cvt.u32.u64 %0, t; }"
        : "=r"(a) : "l"(p));
    return a;
}
__device__ __forceinline__ float ex2f(float x) {
    float r;
    asm("ex2.approx.f32 %0, %1;" : "=f"(r) : "f"(x));
    return r;
}
__device__ __forceinline__ uint32_t pack_bf(float a, float b) {
    uint32_t ha = __bfloat16_as_ushort(__float2bfloat16_rn(a));
    uint32_t hb = __bfloat16_as_ushort(__float2bfloat16_rn(b));
    return ha | (hb << 16);
}
__device__ __forceinline__ uint32_t pack_hilo(float a, float b, uint32_t& lo) {
    __nv_bfloat16 ha = __float2bfloat16_rn(a);
    __nv_bfloat16 hb = __float2bfloat16_rn(b);
    lo = pack_bf(a - __bfloat162float(ha), b - __bfloat162float(hb));
    return (uint32_t)__bfloat16_as_ushort(ha) |
           ((uint32_t)__bfloat16_as_ushort(hb) << 16);
}
__device__ __forceinline__ void mma16816(float c[4], const uint32_t a[4],
                                         uint32_t b0, uint32_t b1) {
    asm volatile(
        "mma.sync.aligned.m16n8k16.row.col.f32.bf16.bf16.f32 "
        "{%0,%1,%2,%3}, {%4,%5,%6,%7}, {%8,%9}, {%0,%1,%2,%3};"
        : "+f"(c[0]), "+f"(c[1]), "+f"(c[2]), "+f"(c[3])
        : "r"(a[0]), "r"(a[1]), "r"(a[2]), "r"(a[3]), "r"(b0), "r"(b1));
}
__device__ __forceinline__ void ldsm4(uint32_t r[4], uint32_t a) {
    asm volatile("ldmatrix.sync.aligned.m8n8.x4.shared.b16 {%0,%1,%2,%3}, [%4];"
        : "=r"(r[0]), "=r"(r[1]), "=r"(r[2]), "=r"(r[3]) : "r"(a));
}
__device__ __forceinline__ void ldsm4t(uint32_t r[4], uint32_t a) {
    asm volatile("ldmatrix.sync.aligned.m8n8.x4.trans.shared.b16 {%0,%1,%2,%3}, [%4];"
        : "=r"(r[0]), "=r"(r[1]), "=r"(r[2]), "=r"(r[3]) : "r"(a));
}
__device__ __forceinline__ void cp16(uint32_t dst, const void* src) {
    asm volatile("cp.async.cg.shared.global [%0], [%1], 16;"
                 :: "r"(dst), "l"(src) : "memory");
}
#define CP_COMMIT() asm volatile("cp.async.commit_group;" ::: "memory")
#define CP_WAIT0()  asm volatile("cp.async.wait_group 0;" ::: "memory")

// ===========================================================================
// Weight preprocessing (all 4 weights, one launch)
// ===========================================================================
__global__ __launch_bounds__(256) void split_transpose4_kernel(
    const float* __restrict__ W0, const float* __restrict__ W1,
    const float* __restrict__ W2, const float* __restrict__ W3,
    __nv_bfloat16* __restrict__ Th, __nv_bfloat16* __restrict__ Tl)
{
    __shared__ float t[32][33];
    const int z = blockIdx.z;
    const float* W = (z == 0) ? W0 : (z == 1) ? W1 : (z == 2) ? W2 : W3;
    Th += (size_t)z * D_ * D_;
    Tl += (size_t)z * D_ * D_;
    const int tx = threadIdx.x, ty = threadIdx.y;
    const int n0 = blockIdx.x * 32, k0 = blockIdx.y * 32;
    #pragma unroll
    for (int i = 0; i < 4; i++)
        t[ty + i * 8][tx] = W[(size_t)(k0 + ty + i * 8) * D_ + n0 + tx];
    __syncthreads();
    #pragma unroll
    for (int i = 0; i < 4; i++) {
        float x = t[tx][ty + i * 8];
        __nv_bfloat16 hi = __float2bfloat16_rn(x);
        float lo = x - __bfloat162float(hi);
        size_t o = (size_t)(n0 + ty + i * 8) * D_ + k0 + tx;
        Th[o] = hi;
        Tl[o] = __float2bfloat16_rn(lo);
    }
}

// ===========================================================================
// PE transpose: pe [D_, S_] -> pet [S_, D_]
// ===========================================================================
__global__ __launch_bounds__(256) void pet_kernel(const float* __restrict__ pe)
{
    __shared__ float t[32][33];
    const int tx = threadIdx.x, ty = threadIdx.y;
    const int s0 = blockIdx.x * 32, d0 = blockIdx.y * 32;
    #pragma unroll
    for (int i = 0; i < 4; i++)
        t[ty + i * 8][tx] = pe[(size_t)(d0 + ty + i * 8) * S_ + s0 + tx];
    __syncthreads();
    #pragma unroll
    for (int i = 0; i < 4; i++)
        g_pet[(size_t)(s0 + ty + i * 8) * D_ + d0 + tx] = t[tx][ty + i * 8];
}

// ===========================================================================
// Input split: x fp32 -> hi/lo bf16
// ===========================================================================
__global__ __launch_bounds__(256) void split_in_kernel(
    const float* __restrict__ x0, const float* __restrict__ x1,
    const float* __restrict__ x2)
{
    const int z = blockIdx.y;
    const float* x = (z == 0) ? x0 : (z == 1) ? x1 : x2;
    __nv_bfloat16* oh = g_inhi + (size_t)z * M_ * D_;
    __nv_bfloat16* ol = g_inlo + (size_t)z * M_ * D_;
    const size_t i4 = ((size_t)blockIdx.x * 256 + threadIdx.x) * 4;
    float4 v = *reinterpret_cast<const float4*>(x + i4);
    uint32_t lx, ly;
    uint2 hi, lo;
    hi.x = pack_hilo(v.x, v.y, lx);
    hi.y = pack_hilo(v.z, v.w, ly);
    lo.x = lx; lo.y = ly;
    *reinterpret_cast<uint2*>(oh + i4) = hi;
    *reinterpret_cast<uint2*>(ol + i4) = lo;
}

// ===========================================================================
// GEMM core: cp.async 2-stage, ONE barrier per K-iter, pass-major mma.
// ===========================================================================
#define PK2 40
#define GT_BYTES (128 * PK2 * 2)
#define GSTAGE (4 * GT_BYTES)
#define GEMM_SMEM (2 * GSTAGE)   // 81920

__device__ __forceinline__ void gemm_core(
    const __nv_bfloat16* __restrict__ Ah, const __nv_bfloat16* __restrict__ Al,
    const __nv_bfloat16* __restrict__ Bh, const __nv_bfloat16* __restrict__ Bl,
    const float* __restrict__ bias,
    float* __restrict__ Cf,
    __nv_bfloat16* __restrict__ Chi, __nv_bfloat16* __restrict__ Clo,
    int add_pe, char* sm, int m0, int n0)
{
    const uint32_t smb = smem_u32(sm);
    const int tid    = threadIdx.x;
    const int wid    = tid >> 5;
    const int lane   = tid & 31;
    const int warp_m = wid & 3;
    const int warp_n = wid >> 2;

    const int row0 = tid >> 2;
    const int c8_0 = (tid & 3) * 8;
    const uint32_t a_off = (uint32_t)((warp_m * 32 + (lane & 7) + (lane & 8)) * PK2 +
                                      ((lane >> 4) & 1) * 8) * 2;
    const uint32_t b_off = (uint32_t)((warp_n * 64 + (lane & 7) + ((lane >> 4) & 1) * 8) * PK2 +
                                      ((lane >> 3) & 1) * 8) * 2;

    float acc[2][8][4];
    #pragma unroll
    for (int mt = 0; mt < 2; mt++)
        #pragma unroll
        for (int nt = 0; nt < 8; nt++)
            #pragma unroll
            for (int i = 0; i < 4; i++) acc[mt][nt][i] = 0.f;

    auto issue = [&](int it) {
        const uint32_t sb = smb + (uint32_t)(it & 1) * GSTAGE;
        const int k0 = it * 32;
        #pragma unroll
        for (int c = 0; c < 2; c++) {
            const int row = row0 + c * 64;
            const uint32_t so = (uint32_t)(row * PK2 + c8_0) * 2;
            const size_t ga = (size_t)(m0 + row) * D_ + k0 + c8_0;
            const size_t gb = (size_t)(n0 + row) * D_ + k0 + c8_0;
            cp16(sb + 0 * GT_BYTES + so, Ah + ga);
            cp16(sb + 1 * GT_BYTES + so, Al + ga);
            cp16(sb + 2 * GT_BYTES + so, Bh + gb);
            cp16(sb + 3 * GT_BYTES + so, Bl + gb);
        }
        CP_COMMIT();
    };

    issue(0);

    for (int it = 0; it < D_ / 32; it++) {
        // Single barrier per iter: orders (a) this stage's cp.async arrival
        // CTA-wide and (b) all warps' compute(it-1) before issue(it+1)
        // overwrites buffer (it+1)&1 == (it-1)&1.
        CP_WAIT0();
        __syncthreads();
        if (it + 1 < D_ / 32) issue(it + 1);

        const uint32_t sb = smb + (uint32_t)(it & 1) * GSTAGE;
        #pragma unroll
        for (int ks = 0; ks < 2; ks++) {
            uint32_t ah[2][4], al[2][4];
            #pragma unroll
            for (int mt = 0; mt < 2; mt++) {
                const uint32_t d = (uint32_t)(mt * 16 * PK2 + ks * 16) * 2;
                ldsm4(ah[mt], sb + 0 * GT_BYTES + a_off + d);
                ldsm4(al[mt], sb + 1 * GT_BYTES + a_off + d);
            }
            #pragma unroll
            for (int p = 0; p < 4; p++) {
                uint32_t bh[4], bl[4];
                const uint32_t d = (uint32_t)(p * 16 * PK2 + ks * 16) * 2;
                ldsm4(bh, sb + 2 * GT_BYTES + b_off + d);
                ldsm4(bl, sb + 3 * GT_BYTES + b_off + d);
                #pragma unroll
                for (int mt = 0; mt < 2; mt++) {
                    mma16816(acc[mt][2 * p],     ah[mt], bh[0], bh[1]);
                    mma16816(acc[mt][2 * p + 1], ah[mt], bh[2], bh[3]);
                }
                #pragma unroll
                for (int mt = 0; mt < 2; mt++) {
                    mma16816(acc[mt][2 * p],     ah[mt], bl[0], bl[1]);
                    mma16816(acc[mt][2 * p + 1], ah[mt], bl[2], bl[3]);
                }
                #pragma unroll
                for (int mt = 0; mt < 2; mt++) {
                    mma16816(acc[mt][2 * p],     al[mt], bh[0], bh[1]);
                    mma16816(acc[mt][2 * p + 1], al[mt], bh[2], bh[3]);
                }
            }
        }
    }

    const int g  = lane >> 2;
    const int tg = lane & 3;
    #pragma unroll
    for (int mt = 0; mt < 2; mt++) {
        const int row = m0 + warp_m * 32 + mt * 16 + g;
        #pragma unroll
        for (int nt = 0; nt < 8; nt++) {
            const int col = n0 + warp_n * 64 + nt * 8 + 2 * tg;
            const float bx = bias[col], by = bias[col + 1];
            float v00 = acc[mt][nt][0] + bx, v01 = acc[mt][nt][1] + by;
            float v10 = acc[mt][nt][2] + bx, v11 = acc[mt][nt][3] + by;
            if (add_pe) {
                const float* p0 = g_pet + (size_t)(row & (S_ - 1)) * D_ + col;
                const float* p1 = g_pet + (size_t)((row + 8) & (S_ - 1)) * D_ + col;
                float2 e0 = *reinterpret_cast<const float2*>(p0);
                float2 e1 = *reinterpret_cast<const float2*>(p1);
                v00 += e0.x; v01 += e0.y;
                v10 += e1.x; v11 += e1.y;
            }
            if (Cf) {
                *reinterpret_cast<float2*>(Cf + (size_t)row * D_ + col) = make_float2(v00, v01);
                *reinterpret_cast<float2*>(Cf + (size_t)(row + 8) * D_ + col) = make_float2(v10, v11);
            } else {
                uint32_t l0, l1;
                const uint32_t h0 = pack_hilo(v00, v01, l0);
                const uint32_t h1 = pack_hilo(v10, v11, l1);
                *reinterpret_cast<uint32_t*>(Chi + (size_t)row * D_ + col) = h0;
                *reinterpret_cast<uint32_t*>(Clo + (size_t)row * D_ + col) = l0;
                *reinterpret_cast<uint32_t*>(Chi + (size_t)(row + 8) * D_ + col) = h1;
                *reinterpret_cast<uint32_t*>(Clo + (size_t)(row + 8) * D_ + col) = l1;
            }
        }
    }
}

__global__ __launch_bounds__(256, 2)
void qkv_gemm_kernel(const float* __restrict__ bq,
                     const float* __restrict__ bk,
                     const float* __restrict__ bv)
{
    extern __shared__ char sm[];
    const int z = blockIdx.z;
    const size_t off = (size_t)M_ * D_;
    const __nv_bfloat16* Ah = g_inhi + z * off;
    const __nv_bfloat16* Al = g_inlo + z * off;
    const __nv_bfloat16* Bh = g_whi + (size_t)z * D_ * D_;
    const __nv_bfloat16* Bl = g_wlo + (size_t)z * D_ * D_;
    const float* bias = (z == 0) ? bq : (z == 1) ? bk : bv;
    __nv_bfloat16* Chi = (z == 0) ? g_qhi : (z == 1) ? g_khi : g_vhi;
    __nv_bfloat16* Clo = (z == 0) ? g_qlo : (z == 1) ? g_klo : g_vlo;
    gemm_core(Ah, Al, Bh, Bl, bias, nullptr, Chi, Clo, (z == 1),
              sm, blockIdx.y * 128, blockIdx.x * 128);
}

__global__ __launch_bounds__(256, 2)
void oproj_gemm_kernel(const float* __restrict__ bo, float* __restrict__ out)
{
    extern __shared__ char sm[];
    gemm_core(g_aohi, g_aolo, g_whi + 3 * D_ * D_, g_wlo + 3 * D_ * D_,
              bo, out, nullptr, nullptr, 0,
              sm, blockIdx.y * 128, blockIdx.x * 128);
}

// ===========================================================================
// Flash attention: 2 CTAs/SM, ONE barrier per KV-iter, ex2-domain softmax.
// ===========================================================================
#define APAD 72
#define SQ_H 0
#define SQ_L (128 * APAD * 2)
#define SKV_OFF (2 * 128 * APAD * 2)
#define HALF_BYTES (64 * APAD * 2)
#define STAGE_BYTES (4 * HALF_BYTES)
#define ATTN_SMEM (SKV_OFF + 2 * STAGE_BYTES)   // 110592

// scores scaled by (1/sqrt(dk)) * log2(e) so softmax runs in exp2 domain
#define QK_SCALE (0.125f * 1.4426950408889634f)

__global__ __launch_bounds__(256, 2)
void attn_mma_kernel()
{
    extern __shared__ char sm[];
    const uint32_t smb = smem_u32(sm);
    const int b    = blockIdx.z;
    const int h    = blockIdx.y;
    const int q0   = blockIdx.x * 128;
    const int tid  = threadIdx.x;
    const int wid  = tid >> 5;
    const int lane = tid & 31;
    const int g    = lane >> 2;
    const int tg   = lane & 3;

    const uint32_t q_off = (uint32_t)((wid * 16 + (lane & 7) + (lane & 8)) * APAD +
                                      ((lane >> 4) & 1) * 8) * 2;
    const uint32_t k_off = (uint32_t)(((lane & 7) + ((lane >> 4) & 1) * 8) * APAD +
                                      ((lane >> 3) & 1) * 8) * 2;
    const uint32_t v_off = (uint32_t)(((lane & 7) + (lane & 8)) * APAD +
                                      ((lane >> 4) & 1) * 8) * 2;

    const size_t kvg = ((size_t)b * S_) * D_ + h * DK_;

    {
        const size_t qg = ((size_t)b * S_ + q0) * D_ + h * DK_;
        #pragma unroll
        for (int i = 0; i < 4; i++) {
            const int chunk = tid + i * 256;
            const int row = chunk >> 3, c8 = (chunk & 7) * 8;
            const size_t go = qg + (size_t)row * D_ + c8;
            const int so = (row * APAD + c8) * 2;
            *reinterpret_cast<uint4*>(sm + SQ_H + so) =
                *reinterpret_cast<const uint4*>(g_qhi + go);
            *reinterpret_cast<uint4*>(sm + SQ_L + so) =
                *reinterpret_cast<const uint4*>(g_qlo + go);
        }
    }

    auto issue = [&](int it) {
        const uint32_t sbase = smb + SKV_OFF + (uint32_t)(it & 1) * STAGE_BYTES;
        const size_t tg0 = kvg + (size_t)it * 64 * D_;
        #pragma unroll
        for (int c = 0; c < 2; c++) {
            const int chunk = tid + c * 256;
            const int row = chunk >> 3, c8 = (chunk & 7) * 8;
            const uint32_t so = (uint32_t)(row * APAD + c8) * 2;
            const size_t go = tg0 + (size_t)row * D_ + c8;
            cp16(sbase + 0 * HALF_BYTES + so, g_khi + go);
            cp16(sbase + 1 * HALF_BYTES + so, g_klo + go);
            cp16(sbase + 2 * HALF_BYTES + so, g_vhi + go);
            cp16(sbase + 3 * HALF_BYTES + so, g_vlo + go);
        }
        CP_COMMIT();
    };

    issue(0);
    CP_WAIT0();
    __syncthreads();

    uint32_t qh[4][4];
    #pragma unroll
    for (int ks = 0; ks < 4; ks++)
        ldsm4(qh[ks], smb + SQ_H + q_off + (uint32_t)(ks * 16) * 2);

    float m_[2] = {-1e30f, -1e30f};
    float l_[2] = {0.f, 0.f};
    float o[8][4];
    #pragma unroll
    for (int nt = 0; nt < 8; nt++)
        #pragma unroll
        for (int i = 0; i < 4; i++) o[nt][i] = 0.f;

    for (int it = 0; it < S_ / 64; it++) {
        if (it > 0) {
            // Single barrier per iter (see gemm_core comment).
            CP_WAIT0();
            __syncthreads();
        }
        if (it + 1 < S_ / 64) issue(it + 1);

        const uint32_t skv = smb + SKV_OFF + (it & 1) * STAGE_BYTES;

        float s[8][4];
        #pragma unroll
        for (int nt = 0; nt < 8; nt++)
            #pragma unroll
            for (int i = 0; i < 4; i++) s[nt][i] = 0.f;

        #pragma unroll
        for (int ks = 0; ks < 4; ks++) {
            uint32_t ql[4];
            ldsm4(ql, smb + SQ_L + q_off + (uint32_t)(ks * 16) * 2);
            #pragma unroll
            for (int p = 0; p < 4; p++) {
                uint32_t kh[4], kl[4];
                const uint32_t d = (uint32_t)(p * 16 * APAD + ks * 16) * 2;
                ldsm4(kh, skv + k_off + d);
                ldsm4(kl, skv + HALF_BYTES + k_off + d);
                mma16816(s[2 * p],     qh[ks], kh[0], kh[1]);
                mma16816(s[2 * p + 1], qh[ks], kh[2], kh[3]);
                mma16816(s[2 * p],     qh[ks], kl[0], kl[1]);
                mma16816(s[2 * p + 1], qh[ks], kl[2], kl[3]);
                mma16816(s[2 * p],     ql,     kh[0], kh[1]);
                mma16816(s[2 * p + 1], ql,     kh[2], kh[3]);
            }
        }

        float mx0 = -1e30f, mx1 = -1e30f;
        #pragma unroll
        for (int nt = 0; nt < 8; nt++) {
            #pragma unroll
            for (int i = 0; i < 4; i++) s[nt][i] *= QK_SCALE;
            mx0 = fmaxf(mx0, fmaxf(s[nt][0], s[nt][1]));
            mx1 = fmaxf(mx1, fmaxf(s[nt][2], s[nt][3]));
        }
        mx0 = fmaxf(mx0, __shfl_xor_sync(0xffffffffu, mx0, 1));
        mx0 = fmaxf(mx0, __shfl_xor_sync(0xffffffffu, mx0, 2));
        mx1 = fmaxf(mx1, __shfl_xor_sync(0xffffffffu, mx1, 1));
        mx1 = fmaxf(mx1, __shfl_xor_sync(0xffffffffu, mx1, 2));

        const float mn0 = fmaxf(m_[0], mx0);
        const float mn1 = fmaxf(m_[1], mx1);
        const float c0 = ex2f(m_[0] - mn0);
        const float c1 = ex2f(m_[1] - mn1);
        m_[0] = mn0; m_[1] = mn1;

        float r0 = 0.f, r1 = 0.f;
        #pragma unroll
        for (int nt = 0; nt < 8; nt++) {
            s[nt][0] = ex2f(s[nt][0] - mn0);
            s[nt][1] = ex2f(s[nt][1] - mn0);
            s[nt][2] = ex2f(s[nt][2] - mn1);
            s[nt][3] = ex2f(s[nt][3] - mn1);
            r0 += s[nt][0] + s[nt][1];
            r1 += s[nt][2] + s[nt][3];
        }
        r0 += __shfl_xor_sync(0xffffffffu, r0, 1);
        r0 += __shfl_xor_sync(0xffffffffu, r0, 2);
        r1 += __shfl_xor_sync(0xffffffffu, r1, 1);
        r1 += __shfl_xor_sync(0xffffffffu, r1, 2);
        l_[0] = l_[0] * c0 + r0;
        l_[1] = l_[1] * c1 + r1;

        #pragma unroll
        for (int nt = 0; nt < 8; nt++) {
            o[nt][0] *= c0; o[nt][1] *= c0;
            o[nt][2] *= c1; o[nt][3] *= c1;
        }

        #pragma unroll
        for (int jp = 0; jp < 4; jp++) {
            uint32_t ph[4], pl[4];
            ph[0] = pack_hilo(s[2 * jp][0],     s[2 * jp][1],     pl[0]);
            ph[1] = pack_hilo(s[2 * jp][2],     s[2 * jp][3],     pl[1]);
            ph[2] = pack_hilo(s[2 * jp + 1][0], s[2 * jp + 1][1], pl[2]);
            ph[3] = pack_hilo(s[2 * jp + 1][2], s[2 * jp + 1][3], pl[3]);
            #pragma unroll
            for (int p = 0; p < 4; p++) {
                uint32_t vh[4], vl[4];
                const uint32_t d = (uint32_t)(jp * 16 * APAD + p * 16) * 2;
                ldsm4t(vh, skv + 2 * HALF_BYTES + v_off + d);
                ldsm4t(vl, skv + 3 * HALF_BYTES + v_off + d);
                mma16816(o[2 * p],     ph, vh[0], vh[1]);
                mma16816(o[2 * p + 1], ph, vh[2], vh[3]);
                mma16816(o[2 * p],     ph, vl[0], vl[1]);
                mma16816(o[2 * p + 1], ph, vl[2], vl[3]);
                mma16816(o[2 * p],     pl, vh[0], vh[1]);
                mma16816(o[2 * p + 1], pl, vh[2], vh[3]);
            }
        }
    }

    const float inv0 = 1.f / l_[0];
    const float inv1 = 1.f / l_[1];
    const int row = q0 + wid * 16 + g;
    const size_t ob = ((size_t)b * S_ + row) * D_ + h * DK_;
    #pragma unroll
    for (int nt = 0; nt < 8; nt++) {
        const int col = nt * 8 + 2 * tg;
        uint32_t l0, l1;
        const uint32_t h0 = pack_hilo(o[nt][0] * inv0, o[nt][1] * inv0, l0);
        const uint32_t h1 = pack_hilo(o[nt][2] * inv1, o[nt][3] * inv1, l1);
        *reinterpret_cast<uint32_t*>(g_aohi + ob + col) = h0;
        *reinterpret_cast<uint32_t*>(g_aolo + ob + col) = l0;
        *reinterpret_cast<uint32_t*>(g_aohi + ob + (size_t)8 * D_ + col) = h1;
        *reinterpret_cast<uint32_t*>(g_aolo + ob + (size_t)8 * D_ + col) = l1;
    }
}

// ===========================================================================
extern "C" void kernel_launch(void* const* d_in, const int* in_sizes, int n_in,
                              void* d_out, int out_size)
{
    const float* q  = (const float*)d_in[0];
    const float* k  = (const float*)d_in[1];
    const float* v  = (const float*)d_in[2];
    const float* pe = (const float*)d_in[3];
    const float* Wq = (const float*)d_in[4];
    const float* bq = (const float*)d_in[5];
    const float* Wk = (const float*)d_in[6];
    const float* bk = (const float*)d_in[7];
    const float* Wv = (const float*)d_in[8];
    const float* bv = (const float*)d_in[9];
    const float* Wo = (const float*)d_in[10];
    const float* bo = (const float*)d_in[11];
    float* out = (float*)d_out;

    __nv_bfloat16 *whi, *wlo;
    cudaGetSymbolAddress((void**)&whi, g_whi);
    cudaGetSymbolAddress((void**)&wlo, g_wlo);

    cudaFuncSetAttribute(qkv_gemm_kernel,
                         cudaFuncAttributeMaxDynamicSharedMemorySize, GEMM_SMEM);
    cudaFuncSetAttribute(oproj_gemm_kernel,
                         cudaFuncAttributeMaxDynamicSharedMemorySize, GEMM_SMEM);
    cudaFuncSetAttribute(attn_mma_kernel,
                         cudaFuncAttributeMaxDynamicSharedMemorySize, ATTN_SMEM);

    // 1) preprocessing
    split_transpose4_kernel<<<dim3(D_ / 32, D_ / 32, 4), dim3(32, 8)>>>(
        Wq, Wk, Wv, Wo, whi, wlo);
    pet_kernel<<<dim3(S_ / 32, D_ / 32), dim3(32, 8)>>>(pe);
    split_in_kernel<<<dim3((M_ * D_) / 1024, 3), 256>>>(q, k, v);

    // 2) batched Q/K/V projections (K gets +PE in epilogue)
    qkv_gemm_kernel<<<dim3(D_ / 128, M_ / 128, 3), 256, GEMM_SMEM>>>(bq, bk, bv);

    // 3) attention
    attn_mma_kernel<<<dim3(S_ / 128, H_, B_), 256, ATTN_SMEM>>>();

    // 4) output projection -> fp32 out
    oproj_gemm_kernel<<<dim3(D_ / 128, M_ / 128), 256, GEMM_SMEM>>>(bo, out);
}

// round 16
// speedup vs baseline: 4.1893x; 1.3739x over previous
#include <cuda_runtime.h>
#include <cuda_fp16.h>
#include <cstdint>

#define B_  2
#define S_  2048
#define D_  1024
#define H_  16
#define DK_ 64
#define M_  (B_ * S_)   // 4096

// Scratch (allocation-free: __device__ globals) — fp16 operand scheme:
//   activations/Q/P: single fp16 ; weights/K_eff/V: fp16 hi+lo split
__device__ float  g_pet[S_ * D_];                 // PE transposed [s, h*64+dk]
__device__ __half g_in [3 * M_ * D_];             // q,k,v inputs (single)
__device__ __half g_q  [M_ * D_];                 // Q proj (single)
__device__ __half g_khi[M_ * D_], g_klo[M_ * D_]; // K_eff = K + PE (split)
__device__ __half g_vhi[M_ * D_], g_vlo[M_ * D_]; // V (split)
__device__ __half g_ao [M_ * D_];                 // attention out (single)
__device__ __half g_whi[4 * D_ * D_];             // Wt [N,K] hi
__device__ __half g_wlo[4 * D_ * D_];             // Wt [N,K] lo

// ---------------------------------------------------------------------------
__device__ __forceinline__ uint32_t smem_u32(const void* p) {
    uint32_t a;
    asm("{ .reg .u64 t; cvta.to.shared.u64 t, %1; cvt.u32.u64 %0, t; }"
        : "=r"(a) : "l"(p));
    return a;
}
__device__ __forceinline__ float ex2f(float x) {
    float r;
    asm("ex2.approx.f32 %0, %1;" : "=f"(r) : "f"(x));
    return r;
}
__device__ __forceinline__ uint32_t pack_h(float a, float b) {
    __half2 h = __floats2half2_rn(a, b);
    return *reinterpret_cast<uint32_t*>(&h);
}
__device__ __forceinline__ uint32_t pack_hilo_h(float a, float b, uint32_t& lo) {
    __half ha = __float2half_rn(a);
    __half hb = __float2half_rn(b);
    lo = pack_h(a - __half2float(ha), b - __half2float(hb));
    __half2 h2 = __halves2half2(ha, hb);
    return *reinterpret_cast<uint32_t*>(&h2);
}
__device__ __forceinline__ void mma16816(float c[4], const uint32_t a[4],
                                         uint32_t b0, uint32_t b1) {
    asm volatile(
        "mma.sync.aligned.m16n8k16.row.col.f32.f16.f16.f32 "
        "{%0,%1,%2,%3}, {%4,%5,%6,%7}, {%8,%9}, {%0,%1,%2,%3};"
        : "+f"(c[0]), "+f"(c[1]), "+f"(c[2]), "+f"(c[3])
        : "r"(a[0]), "r"(a[1]), "r"(a[2]), "r"(a[3]), "r"(b0), "r"(b1));
}
__device__ __forceinline__ void ldsm4(uint32_t r[4], uint32_t a) {
    asm volatile("ldmatrix.sync.aligned.m8n8.x4.shared.b16 {%0,%1,%2,%3}, [%4];"
        : "=r"(r[0]), "=r"(r[1]), "=r"(r[2]), "=r"(r[3]) : "r"(a));
}
__device__ __forceinline__ void ldsm4t(uint32_t r[4], uint32_t a) {
    asm volatile("ldmatrix.sync.aligned.m8n8.x4.trans.shared.b16 {%0,%1,%2,%3}, [%4];"
        : "=r"(r[0]), "=r"(r[1]), "=r"(r[2]), "=r"(r[3]) : "r"(a));
}
__device__ __forceinline__ void cp16(uint32_t dst, const void* src) {
    asm volatile("cp.async.cg.shared.global [%0], [%1], 16;"
                 :: "r"(dst), "l"(src) : "memory");
}
#define CP_COMMIT() asm volatile("cp.async.commit_group;" ::: "memory")
#define CP_WAIT0()  asm volatile("cp.async.wait_group 0;" ::: "memory")

// ===========================================================================
// Weight preprocessing: W[K,N] fp32 -> Wt_hi/Wt_lo [N,K] fp16
// ===========================================================================
__global__ __launch_bounds__(256) void split_transpose4_kernel(
    const float* __restrict__ W0, const float* __restrict__ W1,
    const float* __restrict__ W2, const float* __restrict__ W3,
    __half* __restrict__ Th, __half* __restrict__ Tl)
{
    __shared__ float t[32][33];
    const int z = blockIdx.z;
    const float* W = (z == 0) ? W0 : (z == 1) ? W1 : (z == 2) ? W2 : W3;
    Th += (size_t)z * D_ * D_;
    Tl += (size_t)z * D_ * D_;
    const int tx = threadIdx.x, ty = threadIdx.y;
    const int n0 = blockIdx.x * 32, k0 = blockIdx.y * 32;
    #pragma unroll
    for (int i = 0; i < 4; i++)
        t[ty + i * 8][tx] = W[(size_t)(k0 + ty + i * 8) * D_ + n0 + tx];
    __syncthreads();
    #pragma unroll
    for (int i = 0; i < 4; i++) {
        float x = t[tx][ty + i * 8];
        __half hi = __float2half_rn(x);
        size_t o = (size_t)(n0 + ty + i * 8) * D_ + k0 + tx;
        Th[o] = hi;
        Tl[o] = __float2half_rn(x - __half2float(hi));
    }
}

// ===========================================================================
// PE transpose: pe [D_, S_] -> pet [S_, D_]
// ===========================================================================
__global__ __launch_bounds__(256) void pet_kernel(const float* __restrict__ pe)
{
    __shared__ float t[32][33];
    const int tx = threadIdx.x, ty = threadIdx.y;
    const int s0 = blockIdx.x * 32, d0 = blockIdx.y * 32;
    #pragma unroll
    for (int i = 0; i < 4; i++)
        t[ty + i * 8][tx] = pe[(size_t)(d0 + ty + i * 8) * S_ + s0 + tx];
    __syncthreads();
    #pragma unroll
    for (int i = 0; i < 4; i++)
        g_pet[(size_t)(s0 + ty + i * 8) * D_ + d0 + tx] = t[tx][ty + i * 8];
}

// ===========================================================================
// Input convert: x fp32 -> single fp16
// ===========================================================================
__global__ __launch_bounds__(256) void split_in_kernel(
    const float* __restrict__ x0, const float* __restrict__ x1,
    const float* __restrict__ x2)
{
    const int z = blockIdx.y;
    const float* x = (z == 0) ? x0 : (z == 1) ? x1 : x2;
    __half* oh = g_in + (size_t)z * M_ * D_;
    const size_t i4 = ((size_t)blockIdx.x * 256 + threadIdx.x) * 4;
    float4 v = *reinterpret_cast<const float4*>(x + i4);
    uint2 h;
    h.x = pack_h(v.x, v.y);
    h.y = pack_h(v.z, v.w);
    *reinterpret_cast<uint2*>(oh + i4) = h;
}

// ===========================================================================
// GEMM core: C = A(single fp16) @ (Bh+Bl)^T + bias — 2-pass fp16.
// Output: Cf fp32 | Chi single fp16 | Chi/Clo split fp16 (+optional PE).
// ===========================================================================
#define PK2 40
#define GT_BYTES (128 * PK2 * 2)   // 10240
#define GSTAGE (3 * GT_BYTES)      // 30720 (A, BH, BL)
#define GEMM_SMEM (2 * GSTAGE)     // 61440

__device__ __forceinline__ void gemm_core(
    const __half* __restrict__ A,
    const __half* __restrict__ Bh, const __half* __restrict__ Bl,
    const float* __restrict__ bias,
    float* __restrict__ Cf,
    __half* __restrict__ Chi, __half* __restrict__ Clo,
    int add_pe, char* sm, int m0, int n0)
{
    const uint32_t smb = smem_u32(sm);
    const int tid    = threadIdx.x;
    const int wid    = tid >> 5;
    const int lane   = tid & 31;
    const int warp_m = wid & 3;
    const int warp_n = wid >> 2;

    const int row0 = tid >> 2;
    const int c8_0 = (tid & 3) * 8;
    const uint32_t a_off = (uint32_t)((warp_m * 32 + (lane & 7) + (lane & 8)) * PK2 +
                                      ((lane >> 4) & 1) * 8) * 2;
    const uint32_t b_off = (uint32_t)((warp_n * 64 + (lane & 7) + ((lane >> 4) & 1) * 8) * PK2 +
                                      ((lane >> 3) & 1) * 8) * 2;

    float acc[2][8][4];
    #pragma unroll
    for (int mt = 0; mt < 2; mt++)
        #pragma unroll
        for (int nt = 0; nt < 8; nt++)
            #pragma unroll
            for (int i = 0; i < 4; i++) acc[mt][nt][i] = 0.f;

    auto issue = [&](int it) {
        const uint32_t sb = smb + (uint32_t)(it & 1) * GSTAGE;
        const int k0 = it * 32;
        #pragma unroll
        for (int c = 0; c < 2; c++) {
            const int row = row0 + c * 64;
            const uint32_t so = (uint32_t)(row * PK2 + c8_0) * 2;
            const size_t ga = (size_t)(m0 + row) * D_ + k0 + c8_0;
            const size_t gb = (size_t)(n0 + row) * D_ + k0 + c8_0;
            cp16(sb + 0 * GT_BYTES + so, A  + ga);
            cp16(sb + 1 * GT_BYTES + so, Bh + gb);
            cp16(sb + 2 * GT_BYTES + so, Bl + gb);
        }
        CP_COMMIT();
    };

    issue(0);

    for (int it = 0; it < D_ / 32; it++) {
        CP_WAIT0();
        __syncthreads();
        if (it + 1 < D_ / 32) issue(it + 1);

        const uint32_t sb = smb + (uint32_t)(it & 1) * GSTAGE;
        #pragma unroll
        for (int ks = 0; ks < 2; ks++) {
            uint32_t ah[2][4];
            #pragma unroll
            for (int mt = 0; mt < 2; mt++) {
                const uint32_t d = (uint32_t)(mt * 16 * PK2 + ks * 16) * 2;
                ldsm4(ah[mt], sb + a_off + d);
            }
            #pragma unroll
            for (int p = 0; p < 4; p++) {
                uint32_t bh[4], bl[4];
                const uint32_t d = (uint32_t)(p * 16 * PK2 + ks * 16) * 2;
                ldsm4(bh, sb + 1 * GT_BYTES + b_off + d);
                ldsm4(bl, sb + 2 * GT_BYTES + b_off + d);
                #pragma unroll
                for (int mt = 0; mt < 2; mt++) {
                    mma16816(acc[mt][2 * p],     ah[mt], bh[0], bh[1]);
                    mma16816(acc[mt][2 * p + 1], ah[mt], bh[2], bh[3]);
                }
                #pragma unroll
                for (int mt = 0; mt < 2; mt++) {
                    mma16816(acc[mt][2 * p],     ah[mt], bl[0], bl[1]);
                    mma16816(acc[mt][2 * p + 1], ah[mt], bl[2], bl[3]);
                }
            }
        }
    }

    const int g  = lane >> 2;
    const int tg = lane & 3;
    #pragma unroll
    for (int mt = 0; mt < 2; mt++) {
        const int row = m0 + warp_m * 32 + mt * 16 + g;
        #pragma unroll
        for (int nt = 0; nt < 8; nt++) {
            const int col = n0 + warp_n * 64 + nt * 8 + 2 * tg;
            const float bx = bias[col], by = bias[col + 1];
            float v00 = acc[mt][nt][0] + bx, v01 = acc[mt][nt][1] + by;
            float v10 = acc[mt][nt][2] + bx, v11 = acc[mt][nt][3] + by;
            if (add_pe) {
                const float* p0 = g_pet + (size_t)(row & (S_ - 1)) * D_ + col;
                const float* p1 = g_pet + (size_t)((row + 8) & (S_ - 1)) * D_ + col;
                float2 e0 = *reinterpret_cast<const float2*>(p0);
                float2 e1 = *reinterpret_cast<const float2*>(p1);
                v00 += e0.x; v01 += e0.y;
                v10 += e1.x; v11 += e1.y;
            }
            if (Cf) {
                *reinterpret_cast<float2*>(Cf + (size_t)row * D_ + col) = make_float2(v00, v01);
                *reinterpret_cast<float2*>(Cf + (size_t)(row + 8) * D_ + col) = make_float2(v10, v11);
            } else if (Clo) {
                uint32_t l0, l1;
                const uint32_t h0 = pack_hilo_h(v00, v01, l0);
                const uint32_t h1 = pack_hilo_h(v10, v11, l1);
                *reinterpret_cast<uint32_t*>(Chi + (size_t)row * D_ + col) = h0;
                *reinterpret_cast<uint32_t*>(Clo + (size_t)row * D_ + col) = l0;
                *reinterpret_cast<uint32_t*>(Chi + (size_t)(row + 8) * D_ + col) = h1;
                *reinterpret_cast<uint32_t*>(Clo + (size_t)(row + 8) * D_ + col) = l1;
            } else {
                *reinterpret_cast<uint32_t*>(Chi + (size_t)row * D_ + col) = pack_h(v00, v01);
                *reinterpret_cast<uint32_t*>(Chi + (size_t)(row + 8) * D_ + col) = pack_h(v10, v11);
            }
        }
    }
}

__global__ __launch_bounds__(256, 2)
void qkv_gemm_kernel(const float* __restrict__ bq,
                     const float* __restrict__ bk,
                     const float* __restrict__ bv)
{
    extern __shared__ char sm[];
    const int z = blockIdx.z;
    const size_t off = (size_t)M_ * D_;
    const __half* A  = g_in + z * off;
    const __half* Bh = g_whi + (size_t)z * D_ * D_;
    const __half* Bl = g_wlo + (size_t)z * D_ * D_;
    const float* bias = (z == 0) ? bq : (z == 1) ? bk : bv;
    __half* Chi = (z == 0) ? g_q   : (z == 1) ? g_khi : g_vhi;
    __half* Clo = (z == 0) ? nullptr : (z == 1) ? g_klo : g_vlo;
    gemm_core(A, Bh, Bl, bias, nullptr, Chi, Clo, (z == 1),
              sm, blockIdx.y * 128, blockIdx.x * 128);
}

__global__ __launch_bounds__(256, 2)
void oproj_gemm_kernel(const float* __restrict__ bo, float* __restrict__ out)
{
    extern __shared__ char sm[];
    gemm_core(g_ao, g_whi + 3 * D_ * D_, g_wlo + 3 * D_ * D_,
              bo, out, nullptr, nullptr, 0,
              sm, blockIdx.y * 128, blockIdx.x * 128);
}

// ===========================================================================
// Flash attention: fp16, Q/P single, K_eff/V split (2-pass mma).
// ===========================================================================
#define APAD 72
#define SQ 0
#define SKV_OFF (128 * APAD * 2)               // 18432 (Q single)
#define HALF_BYTES (64 * APAD * 2)             // 9216
#define STAGE_BYTES (4 * HALF_BYTES)           // 36864 (KH,KL,VH,VL)
#define ATTN_SMEM (SKV_OFF + 2 * STAGE_BYTES)  // 92160

#define QK_SCALE (0.125f * 1.4426950408889634f)

__global__ __launch_bounds__(256, 2)
void attn_mma_kernel()
{
    extern __shared__ char sm[];
    const uint32_t smb = smem_u32(sm);
    const int b    = blockIdx.z;
    const int h    = blockIdx.y;
    const int q0   = blockIdx.x * 128;
    const int tid  = threadIdx.x;
    const int wid  = tid >> 5;
    const int lane = tid & 31;
    const int g    = lane >> 2;
    const int tg   = lane & 3;

    const uint32_t q_off = (uint32_t)((wid * 16 + (lane & 7) + (lane & 8)) * APAD +
                                      ((lane >> 4) & 1) * 8) * 2;
    const uint32_t k_off = (uint32_t)(((lane & 7) + ((lane >> 4) & 1) * 8) * APAD +
                                      ((lane >> 3) & 1) * 8) * 2;
    const uint32_t v_off = (uint32_t)(((lane & 7) + (lane & 8)) * APAD +
                                      ((lane >> 4) & 1) * 8) * 2;

    const size_t kvg = ((size_t)b * S_) * D_ + h * DK_;

    // Q tile (single fp16) -> smem
    {
        const size_t qg = ((size_t)b * S_ + q0) * D_ + h * DK_;
        #pragma unroll
        for (int i = 0; i < 4; i++) {
            const int chunk = tid + i * 256;
            const int row = chunk >> 3, c8 = (chunk & 7) * 8;
            *reinterpret_cast<uint4*>(sm + SQ + (row * APAD + c8) * 2) =
                *reinterpret_cast<const uint4*>(g_q + qg + (size_t)row * D_ + c8);
        }
    }

    auto issue = [&](int it) {
        const uint32_t sbase = smb + SKV_OFF + (uint32_t)(it & 1) * STAGE_BYTES;
        const size_t tg0 = kvg + (size_t)it * 64 * D_;
        #pragma unroll
        for (int c = 0; c < 2; c++) {
            const int chunk = tid + c * 256;
            const int row = chunk >> 3, c8 = (chunk & 7) * 8;
            const uint32_t so = (uint32_t)(row * APAD + c8) * 2;
            const size_t go = tg0 + (size_t)row * D_ + c8;
            cp16(sbase + 0 * HALF_BYTES + so, g_khi + go);
            cp16(sbase + 1 * HALF_BYTES + so, g_klo + go);
            cp16(sbase + 2 * HALF_BYTES + so, g_vhi + go);
            cp16(sbase + 3 * HALF_BYTES + so, g_vlo + go);
        }
        CP_COMMIT();
    };

    issue(0);
    CP_WAIT0();
    __syncthreads();

    uint32_t qh[4][4];
    #pragma unroll
    for (int ks = 0; ks < 4; ks++)
        ldsm4(qh[ks], smb + SQ + q_off + (uint32_t)(ks * 16) * 2);

    float m_[2] = {-1e30f, -1e30f};
    float l_[2] = {0.f, 0.f};
    float o[8][4];
    #pragma unroll
    for (int nt = 0; nt < 8; nt++)
        #pragma unroll
        for (int i = 0; i < 4; i++) o[nt][i] = 0.f;

    for (int it = 0; it < S_ / 64; it++) {
        if (it > 0) {
            CP_WAIT0();
            __syncthreads();
        }
        if (it + 1 < S_ / 64) issue(it + 1);

        const uint32_t skv = smb + SKV_OFF + (it & 1) * STAGE_BYTES;

        float s[8][4];
        #pragma unroll
        for (int nt = 0; nt < 8; nt++)
            #pragma unroll
            for (int i = 0; i < 4; i++) s[nt][i] = 0.f;

        #pragma unroll
        for (int ks = 0; ks < 4; ks++) {
            #pragma unroll
            for (int p = 0; p < 4; p++) {
                uint32_t kh[4], kl[4];
                const uint32_t d = (uint32_t)(p * 16 * APAD + ks * 16) * 2;
                ldsm4(kh, skv + k_off + d);
                ldsm4(kl, skv + HALF_BYTES + k_off + d);
                mma16816(s[2 * p],     qh[ks], kh[0], kh[1]);
                mma16816(s[2 * p + 1], qh[ks], kh[2], kh[3]);
                mma16816(s[2 * p],     qh[ks], kl[0], kl[1]);
                mma16816(s[2 * p + 1], qh[ks], kl[2], kl[3]);
            }
        }

        float mx0 = -1e30f, mx1 = -1e30f;
        #pragma unroll
        for (int nt = 0; nt < 8; nt++) {
            #pragma unroll
            for (int i = 0; i < 4; i++) s[nt][i] *= QK_SCALE;
            mx0 = fmaxf(mx0, fmaxf(s[nt][0], s[nt][1]));
            mx1 = fmaxf(mx1, fmaxf(s[nt][2], s[nt][3]));
        }
        mx0 = fmaxf(mx0, __shfl_xor_sync(0xffffffffu, mx0, 1));
        mx0 = fmaxf(mx0, __shfl_xor_sync(0xffffffffu, mx0, 2));
        mx1 = fmaxf(mx1, __shfl_xor_sync(0xffffffffu, mx1, 1));
        mx1 = fmaxf(mx1, __shfl_xor_sync(0xffffffffu, mx1, 2));

        const float mn0 = fmaxf(m_[0], mx0);
        const float mn1 = fmaxf(m_[1], mx1);
        const float c0 = ex2f(m_[0] - mn0);
        const float c1 = ex2f(m_[1] - mn1);
        m_[0] = mn0; m_[1] = mn1;

        float r0 = 0.f, r1 = 0.f;
        #pragma unroll
        for (int nt = 0; nt < 8; nt++) {
            s[nt][0] = ex2f(s[nt][0] - mn0);
            s[nt][1] = ex2f(s[nt][1] - mn0);
            s[nt][2] = ex2f(s[nt][2] - mn1);
            s[nt][3] = ex2f(s[nt][3] - mn1);
            r0 += s[nt][0] + s[nt][1];
            r1 += s[nt][2] + s[nt][3];
        }
        r0 += __shfl_xor_sync(0xffffffffu, r0, 1);
        r0 += __shfl_xor_sync(0xffffffffu, r0, 2);
        r1 += __shfl_xor_sync(0xffffffffu, r1, 1);
        r1 += __shfl_xor_sync(0xffffffffu, r1, 2);
        l_[0] = l_[0] * c0 + r0;
        l_[1] = l_[1] * c1 + r1;

        #pragma unroll
        for (int nt = 0; nt < 8; nt++) {
            o[nt][0] *= c0; o[nt][1] *= c0;
            o[nt][2] *= c1; o[nt][3] *= c1;
        }

        // O += P @ V  (P single fp16; V split)
        #pragma unroll
        for (int jp = 0; jp < 4; jp++) {
            uint32_t ph[4];
            ph[0] = pack_h(s[2 * jp][0],     s[2 * jp][1]);
            ph[1] = pack_h(s[2 * jp][2],     s[2 * jp][3]);
            ph[2] = pack_h(s[2 * jp + 1][0], s[2 * jp + 1][1]);
            ph[3] = pack_h(s[2 * jp + 1][2], s[2 * jp + 1][3]);
            #pragma unroll
            for (int p = 0; p < 4; p++) {
                uint32_t vh[4], vl[4];
                const uint32_t d = (uint32_t)(jp * 16 * APAD + p * 16) * 2;
                ldsm4t(vh, skv + 2 * HALF_BYTES + v_off + d);
                ldsm4t(vl, skv + 3 * HALF_BYTES + v_off + d);
                mma16816(o[2 * p],     ph, vh[0], vh[1]);
                mma16816(o[2 * p + 1], ph, vh[2], vh[3]);
                mma16816(o[2 * p],     ph, vl[0], vl[1]);
                mma16816(o[2 * p + 1], ph, vl[2], vl[3]);
            }
        }
    }

    const float inv0 = 1.f / l_[0];
    const float inv1 = 1.f / l_[1];
    const int row = q0 + wid * 16 + g;
    const size_t ob = ((size_t)b * S_ + row) * D_ + h * DK_;
    #pragma unroll
    for (int nt = 0; nt < 8; nt++) {
        const int col = nt * 8 + 2 * tg;
        *reinterpret_cast<uint32_t*>(g_ao + ob + col) =
            pack_h(o[nt][0] * inv0, o[nt][1] * inv0);
        *reinterpret_cast<uint32_t*>(g_ao + ob + (size_t)8 * D_ + col) =
            pack_h(o[nt][2] * inv1, o[nt][3] * inv1);
    }
}

// ===========================================================================
extern "C" void kernel_launch(void* const* d_in, const int* in_sizes, int n_in,
                              void* d_out, int out_size)
{
    const float* q  = (const float*)d_in[0];
    const float* k  = (const float*)d_in[1];
    const float* v  = (const float*)d_in[2];
    const float* pe = (const float*)d_in[3];
    const float* Wq = (const float*)d_in[4];
    const float* bq = (const float*)d_in[5];
    const float* Wk = (const float*)d_in[6];
    const float* bk = (const float*)d_in[7];
    const float* Wv = (const float*)d_in[8];
    const float* bv = (const float*)d_in[9];
    const float* Wo = (const float*)d_in[10];
    const float* bo = (const float*)d_in[11];
    float* out = (float*)d_out;

    __half *whi, *wlo;
    cudaGetSymbolAddress((void**)&whi, g_whi);
    cudaGetSymbolAddress((void**)&wlo, g_wlo);

    cudaFuncSetAttribute(qkv_gemm_kernel,
                         cudaFuncAttributeMaxDynamicSharedMemorySize, GEMM_SMEM);
    cudaFuncSetAttribute(oproj_gemm_kernel,
                         cudaFuncAttributeMaxDynamicSharedMemorySize, GEMM_SMEM);
    cudaFuncSetAttribute(attn_mma_kernel,
                         cudaFuncAttributeMaxDynamicSharedMemorySize, ATTN_SMEM);

    // 1) preprocessing
    split_transpose4_kernel<<<dim3(D_ / 32, D_ / 32, 4), dim3(32, 8)>>>(
        Wq, Wk, Wv, Wo, whi, wlo);
    pet_kernel<<<dim3(S_ / 32, D_ / 32), dim3(32, 8)>>>(pe);
    split_in_kernel<<<dim3((M_ * D_) / 1024, 3), 256>>>(q, k, v);

    // 2) batched Q/K/V projections (K gets +PE in epilogue)
    qkv_gemm_kernel<<<dim3(D_ / 128, M_ / 128, 3), 256, GEMM_SMEM>>>(bq, bk, bv);

    // 3) attention
    attn_mma_kernel<<<dim3(S_ / 128, H_, B_), 256, ATTN_SMEM>>>();

    // 4) output projection -> fp32 out
    oproj_gemm_kernel<<<dim3(D_ / 128, M_ / 128), 256, GEMM_SMEM>>>(bo, out);
}

// round 17
// speedup vs baseline: 4.3651x; 1.0420x over previous
#include <cuda_runtime.h>
#include <cuda_fp16.h>
#include <cstdint>

#define B_  2
#define S_  2048
#define D_  1024
#define H_  16
#define DK_ 64
#define M_  (B_ * S_)   // 4096

// Scratch (allocation-free: __device__ globals) — fp16 operand scheme:
//   activations/Q/P: single fp16 ; weights/K_eff/V: fp16 hi+lo split
__device__ float  g_pet[S_ * D_];                 // PE transposed [s, h*64+dk]
__device__ __half g_in [3 * M_ * D_];             // q,k,v inputs (single)
__device__ __half g_q  [M_ * D_];                 // Q proj (single)
__device__ __half g_khi[M_ * D_], g_klo[M_ * D_]; // K_eff = K + PE (split)
__device__ __half g_vhi[M_ * D_], g_vlo[M_ * D_]; // V (split)
__device__ __half g_ao [M_ * D_];                 // attention out (single)
__device__ __half g_whi[4 * D_ * D_];             // Wt [N,K] hi
__device__ __half g_wlo[4 * D_ * D_];             // Wt [N,K] lo

// ---------------------------------------------------------------------------
__device__ __forceinline__ uint32_t smem_u32(const void* p) {
    uint32_t a;
    asm("{ .reg .u64 t; cvta.to.shared.u64 t, %1; cvt.u32.u64 %0, t; }"
        : "=r"(a) : "l"(p));
    return a;
}
__device__ __forceinline__ float ex2f(float x) {
    float r;
    asm("ex2.approx.f32 %0, %1;" : "=f"(r) : "f"(x));
    return r;
}
__device__ __forceinline__ uint32_t pack_h(float a, float b) {
    __half2 h = __floats2half2_rn(a, b);
    return *reinterpret_cast<uint32_t*>(&h);
}
__device__ __forceinline__ uint32_t pack_hilo_h(float a, float b, uint32_t& lo) {
    __half ha = __float2half_rn(a);
    __half hb = __float2half_rn(b);
    lo = pack_h(a - __half2float(ha), b - __half2float(hb));
    __half2 h2 = __halves2half2(ha, hb);
    return *reinterpret_cast<uint32_t*>(&h2);
}
__device__ __forceinline__ void mma16816(float c[4], const uint32_t a[4],
                                         uint32_t b0, uint32_t b1) {
    asm volatile(
        "mma.sync.aligned.m16n8k16.row.col.f32.f16.f16.f32 "
        "{%0,%1,%2,%3}, {%4,%5,%6,%7}, {%8,%9}, {%0,%1,%2,%3};"
        : "+f"(c[0]), "+f"(c[1]), "+f"(c[2]), "+f"(c[3])
        : "r"(a[0]), "r"(a[1]), "r"(a[2]), "r"(a[3]), "r"(b0), "r"(b1));
}
__device__ __forceinline__ void ldsm4(uint32_t r[4], uint32_t a) {
    asm volatile("ldmatrix.sync.aligned.m8n8.x4.shared.b16 {%0,%1,%2,%3}, [%4];"
        : "=r"(r[0]), "=r"(r[1]), "=r"(r[2]), "=r"(r[3]) : "r"(a));
}
__device__ __forceinline__ void ldsm4t(uint32_t r[4], uint32_t a) {
    asm volatile("ldmatrix.sync.aligned.m8n8.x4.trans.shared.b16 {%0,%1,%2,%3}, [%4];"
        : "=r"(r[0]), "=r"(r[1]), "=r"(r[2]), "=r"(r[3]) : "r"(a));
}
__device__ __forceinline__ void cp16(uint32_t dst, const void* src) {
    asm volatile("cp.async.cg.shared.global [%0], [%1], 16;"
                 :: "r"(dst), "l"(src) : "memory");
}
#define CP_COMMIT() asm volatile("cp.async.commit_group;" ::: "memory")
#define CP_WAIT0()  asm volatile("cp.async.wait_group 0;" ::: "memory")

// ===========================================================================
// Weight preprocessing: W[K,N] fp32 -> Wt_hi/Wt_lo [N,K] fp16
// ===========================================================================
__global__ __launch_bounds__(256) void split_transpose4_kernel(
    const float* __restrict__ W0, const float* __restrict__ W1,
    const float* __restrict__ W2, const float* __restrict__ W3,
    __half* __restrict__ Th, __half* __restrict__ Tl)
{
    __shared__ float t[32][33];
    const int z = blockIdx.z;
    const float* W = (z == 0) ? W0 : (z == 1) ? W1 : (z == 2) ? W2 : W3;
    Th += (size_t)z * D_ * D_;
    Tl += (size_t)z * D_ * D_;
    const int tx = threadIdx.x, ty = threadIdx.y;
    const int n0 = blockIdx.x * 32, k0 = blockIdx.y * 32;
    #pragma unroll
    for (int i = 0; i < 4; i++)
        t[ty + i * 8][tx] = W[(size_t)(k0 + ty + i * 8) * D_ + n0 + tx];
    __syncthreads();
    #pragma unroll
    for (int i = 0; i < 4; i++) {
        float x = t[tx][ty + i * 8];
        __half hi = __float2half_rn(x);
        size_t o = (size_t)(n0 + ty + i * 8) * D_ + k0 + tx;
        Th[o] = hi;
        Tl[o] = __float2half_rn(x - __half2float(hi));
    }
}

// ===========================================================================
// PE transpose: pe [D_, S_] -> pet [S_, D_]
// ===========================================================================
__global__ __launch_bounds__(256) void pet_kernel(const float* __restrict__ pe)
{
    __shared__ float t[32][33];
    const int tx = threadIdx.x, ty = threadIdx.y;
    const int s0 = blockIdx.x * 32, d0 = blockIdx.y * 32;
    #pragma unroll
    for (int i = 0; i < 4; i++)
        t[ty + i * 8][tx] = pe[(size_t)(d0 + ty + i * 8) * S_ + s0 + tx];
    __syncthreads();
    #pragma unroll
    for (int i = 0; i < 4; i++)
        g_pet[(size_t)(s0 + ty + i * 8) * D_ + d0 + tx] = t[tx][ty + i * 8];
}

// ===========================================================================
// Input convert: x fp32 -> single fp16
// ===========================================================================
__global__ __launch_bounds__(256) void split_in_kernel(
    const float* __restrict__ x0, const float* __restrict__ x1,
    const float* __restrict__ x2)
{
    const int z = blockIdx.y;
    const float* x = (z == 0) ? x0 : (z == 1) ? x1 : x2;
    __half* oh = g_in + (size_t)z * M_ * D_;
    const size_t i4 = ((size_t)blockIdx.x * 256 + threadIdx.x) * 4;
    float4 v = *reinterpret_cast<const float4*>(x + i4);
    uint2 h;
    h.x = pack_h(v.x, v.y);
    h.y = pack_h(v.z, v.w);
    *reinterpret_cast<uint2*>(oh + i4) = h;
}

// ===========================================================================
// GEMM core: C = A(single fp16) @ (Bh+Bl)^T + bias — 2-pass fp16.
// CTA 128x128, K-stage 64, warp tile 64x32 (2m x 4n warps).
// ===========================================================================
#define PADK 72
#define GT_BYTES (128 * PADK * 2)   // 18432
#define GSTAGE (3 * GT_BYTES)       // 55296 (A, BH, BL)
#define GEMM_SMEM (2 * GSTAGE)      // 110592

__device__ __forceinline__ void gemm_core(
    const __half* __restrict__ A,
    const __half* __restrict__ Bh, const __half* __restrict__ Bl,
    const float* __restrict__ bias,
    float* __restrict__ Cf,
    __half* __restrict__ Chi, __half* __restrict__ Clo,
    int add_pe, char* sm, int m0, int n0)
{
    const uint32_t smb = smem_u32(sm);
    const int tid    = threadIdx.x;
    const int wid    = tid >> 5;
    const int lane   = tid & 31;
    const int warp_m = wid & 1;      // 2 warps over M (64 rows each)
    const int warp_n = wid >> 1;     // 4 warps over N (32 cols each)

    const int row0 = tid >> 3;           // 0..31
    const int c8_0 = (tid & 7) * 8;      // 0..56
    const uint32_t a_off = (uint32_t)((warp_m * 64 + (lane & 7) + (lane & 8)) * PADK +
                                      ((lane >> 4) & 1) * 8) * 2;
    const uint32_t b_off = (uint32_t)((warp_n * 32 + (lane & 7) + ((lane >> 4) & 1) * 8) * PADK +
                                      ((lane >> 3) & 1) * 8) * 2;

    float acc[4][4][4];
    #pragma unroll
    for (int mt = 0; mt < 4; mt++)
        #pragma unroll
        for (int nt = 0; nt < 4; nt++)
            #pragma unroll
            for (int i = 0; i < 4; i++) acc[mt][nt][i] = 0.f;

    auto issue = [&](int it) {
        const uint32_t sb = smb + (uint32_t)(it & 1) * GSTAGE;
        const int k0 = it * 64;
        #pragma unroll
        for (int c = 0; c < 4; c++) {
            const int row = row0 + c * 32;
            const uint32_t so = (uint32_t)(row * PADK + c8_0) * 2;
            const size_t ga = (size_t)(m0 + row) * D_ + k0 + c8_0;
            const size_t gb = (size_t)(n0 + row) * D_ + k0 + c8_0;
            cp16(sb + 0 * GT_BYTES + so, A  + ga);
            cp16(sb + 1 * GT_BYTES + so, Bh + gb);
            cp16(sb + 2 * GT_BYTES + so, Bl + gb);
        }
        CP_COMMIT();
    };

    issue(0);

    for (int it = 0; it < D_ / 64; it++) {
        CP_WAIT0();
        __syncthreads();
        if (it + 1 < D_ / 64) issue(it + 1);

        const uint32_t sb = smb + (uint32_t)(it & 1) * GSTAGE;
        #pragma unroll
        for (int ks = 0; ks < 4; ks++) {
            uint32_t ah[4][4];
            #pragma unroll
            for (int mt = 0; mt < 4; mt++)
                ldsm4(ah[mt], sb + a_off + (uint32_t)(mt * 16 * PADK + ks * 16) * 2);
            #pragma unroll
            for (int p = 0; p < 2; p++) {
                uint32_t bh[4], bl[4];
                const uint32_t d = (uint32_t)(p * 16 * PADK + ks * 16) * 2;
                ldsm4(bh, sb + 1 * GT_BYTES + b_off + d);
                ldsm4(bl, sb + 2 * GT_BYTES + b_off + d);
                #pragma unroll
                for (int mt = 0; mt < 4; mt++) {
                    mma16816(acc[mt][2 * p],     ah[mt], bh[0], bh[1]);
                    mma16816(acc[mt][2 * p + 1], ah[mt], bh[2], bh[3]);
                }
                #pragma unroll
                for (int mt = 0; mt < 4; mt++) {
                    mma16816(acc[mt][2 * p],     ah[mt], bl[0], bl[1]);
                    mma16816(acc[mt][2 * p + 1], ah[mt], bl[2], bl[3]);
                }
            }
        }
    }

    const int g  = lane >> 2;
    const int tg = lane & 3;
    #pragma unroll
    for (int mt = 0; mt < 4; mt++) {
        const int row = m0 + warp_m * 64 + mt * 16 + g;
        #pragma unroll
        for (int nt = 0; nt < 4; nt++) {
            const int col = n0 + warp_n * 32 + nt * 8 + 2 * tg;
            const float bx = bias[col], by = bias[col + 1];
            float v00 = acc[mt][nt][0] + bx, v01 = acc[mt][nt][1] + by;
            float v10 = acc[mt][nt][2] + bx, v11 = acc[mt][nt][3] + by;
            if (add_pe) {
                const float* p0 = g_pet + (size_t)(row & (S_ - 1)) * D_ + col;
                const float* p1 = g_pet + (size_t)((row + 8) & (S_ - 1)) * D_ + col;
                float2 e0 = *reinterpret_cast<const float2*>(p0);
                float2 e1 = *reinterpret_cast<const float2*>(p1);
                v00 += e0.x; v01 += e0.y;
                v10 += e1.x; v11 += e1.y;
            }
            if (Cf) {
                *reinterpret_cast<float2*>(Cf + (size_t)row * D_ + col) = make_float2(v00, v01);
                *reinterpret_cast<float2*>(Cf + (size_t)(row + 8) * D_ + col) = make_float2(v10, v11);
            } else if (Clo) {
                uint32_t l0, l1;
                const uint32_t h0 = pack_hilo_h(v00, v01, l0);
                const uint32_t h1 = pack_hilo_h(v10, v11, l1);
                *reinterpret_cast<uint32_t*>(Chi + (size_t)row * D_ + col) = h0;
                *reinterpret_cast<uint32_t*>(Clo + (size_t)row * D_ + col) = l0;
                *reinterpret_cast<uint32_t*>(Chi + (size_t)(row + 8) * D_ + col) = h1;
                *reinterpret_cast<uint32_t*>(Clo + (size_t)(row + 8) * D_ + col) = l1;
            } else {
                *reinterpret_cast<uint32_t*>(Chi + (size_t)row * D_ + col) = pack_h(v00, v01);
                *reinterpret_cast<uint32_t*>(Chi + (size_t)(row + 8) * D_ + col) = pack_h(v10, v11);
            }
        }
    }
}

// Persistent Q/K/V projection: 768 tiles on a 296-CTA grid (no wave tail).
__global__ __launch_bounds__(256, 2)
void qkv_gemm_kernel(const float* __restrict__ bq,
                     const float* __restrict__ bk,
                     const float* __restrict__ bv)
{
    extern __shared__ char sm[];
    const size_t off = (size_t)M_ * D_;
    for (int t = blockIdx.x; t < 768; t += gridDim.x) {
        const int z   = t >> 8;            // 0..2
        const int rem = t & 255;
        const int m0  = (rem >> 3) * 128;  // 32 m-tiles
        const int n0  = (rem & 7) * 128;   // 8 n-tiles
        const __half* A  = g_in + (size_t)z * off;
        const __half* Bh = g_whi + (size_t)z * D_ * D_;
        const __half* Bl = g_wlo + (size_t)z * D_ * D_;
        const float* bias = (z == 0) ? bq : (z == 1) ? bk : bv;
        __half* Chi = (z == 0) ? g_q    : (z == 1) ? g_khi : g_vhi;
        __half* Clo = (z == 0) ? nullptr : (z == 1) ? g_klo : g_vlo;
        gemm_core(A, Bh, Bl, bias, nullptr, Chi, Clo, (z == 1), sm, m0, n0);
    }
}

__global__ __launch_bounds__(256, 2)
void oproj_gemm_kernel(const float* __restrict__ bo, float* __restrict__ out)
{
    extern __shared__ char sm[];
    gemm_core(g_ao, g_whi + 3 * D_ * D_, g_wlo + 3 * D_ * D_,
              bo, out, nullptr, nullptr, 0,
              sm, blockIdx.y * 128, blockIdx.x * 128);
}

// ===========================================================================
// Flash attention (round-16 proven): fp16, Q/P single, K_eff/V split.
// ===========================================================================
#define APAD 72
#define SQ 0
#define SKV_OFF (128 * APAD * 2)               // 18432 (Q single)
#define HALF_BYTES (64 * APAD * 2)             // 9216
#define STAGE_BYTES (4 * HALF_BYTES)           // 36864 (KH,KL,VH,VL)
#define ATTN_SMEM (SKV_OFF + 2 * STAGE_BYTES)  // 92160

#define QK_SCALE (0.125f * 1.4426950408889634f)

__global__ __launch_bounds__(256, 2)
void attn_mma_kernel()
{
    extern __shared__ char sm[];
    const uint32_t smb = smem_u32(sm);
    const int b    = blockIdx.z;
    const int h    = blockIdx.y;
    const int q0   = blockIdx.x * 128;
    const int tid  = threadIdx.x;
    const int wid  = tid >> 5;
    const int lane = tid & 31;
    const int g    = lane >> 2;
    const int tg   = lane & 3;

    const uint32_t q_off = (uint32_t)((wid * 16 + (lane & 7) + (lane & 8)) * APAD +
                                      ((lane >> 4) & 1) * 8) * 2;
    const uint32_t k_off = (uint32_t)(((lane & 7) + ((lane >> 4) & 1) * 8) * APAD +
                                      ((lane >> 3) & 1) * 8) * 2;
    const uint32_t v_off = (uint32_t)(((lane & 7) + (lane & 8)) * APAD +
                                      ((lane >> 4) & 1) * 8) * 2;

    const size_t kvg = ((size_t)b * S_) * D_ + h * DK_;

    {
        const size_t qg = ((size_t)b * S_ + q0) * D_ + h * DK_;
        #pragma unroll
        for (int i = 0; i < 4; i++) {
            const int chunk = tid + i * 256;
            const int row = chunk >> 3, c8 = (chunk & 7) * 8;
            *reinterpret_cast<uint4*>(sm + SQ + (row * APAD + c8) * 2) =
                *reinterpret_cast<const uint4*>(g_q + qg + (size_t)row * D_ + c8);
        }
    }

    auto issue = [&](int it) {
        const uint32_t sbase = smb + SKV_OFF + (uint32_t)(it & 1) * STAGE_BYTES;
        const size_t tg0 = kvg + (size_t)it * 64 * D_;
        #pragma unroll
        for (int c = 0; c < 2; c++) {
            const int chunk = tid + c * 256;
            const int row = chunk >> 3, c8 = (chunk & 7) * 8;
            const uint32_t so = (uint32_t)(row * APAD + c8) * 2;
            const size_t go = tg0 + (size_t)row * D_ + c8;
            cp16(sbase + 0 * HALF_BYTES + so, g_khi + go);
            cp16(sbase + 1 * HALF_BYTES + so, g_klo + go);
            cp16(sbase + 2 * HALF_BYTES + so, g_vhi + go);
            cp16(sbase + 3 * HALF_BYTES + so, g_vlo + go);
        }
        CP_COMMIT();
    };

    issue(0);
    CP_WAIT0();
    __syncthreads();

    uint32_t qh[4][4];
    #pragma unroll
    for (int ks = 0; ks < 4; ks++)
        ldsm4(qh[ks], smb + SQ + q_off + (uint32_t)(ks * 16) * 2);

    float m_[2] = {-1e30f, -1e30f};
    float l_[2] = {0.f, 0.f};
    float o[8][4];
    #pragma unroll
    for (int nt = 0; nt < 8; nt++)
        #pragma unroll
        for (int i = 0; i < 4; i++) o[nt][i] = 0.f;

    for (int it = 0; it < S_ / 64; it++) {
        if (it > 0) {
            CP_WAIT0();
            __syncthreads();
        }
        if (it + 1 < S_ / 64) issue(it + 1);

        const uint32_t skv = smb + SKV_OFF + (it & 1) * STAGE_BYTES;

        float s[8][4];
        #pragma unroll
        for (int nt = 0; nt < 8; nt++)
            #pragma unroll
            for (int i = 0; i < 4; i++) s[nt][i] = 0.f;

        #pragma unroll
        for (int ks = 0; ks < 4; ks++) {
            #pragma unroll
            for (int p = 0; p < 4; p++) {
                uint32_t kh[4], kl[4];
                const uint32_t d = (uint32_t)(p * 16 * APAD + ks * 16) * 2;
                ldsm4(kh, skv + k_off + d);
                ldsm4(kl, skv + HALF_BYTES + k_off + d);
                mma16816(s[2 * p],     qh[ks], kh[0], kh[1]);
                mma16816(s[2 * p + 1], qh[ks], kh[2], kh[3]);
                mma16816(s[2 * p],     qh[ks], kl[0], kl[1]);
                mma16816(s[2 * p + 1], qh[ks], kl[2], kl[3]);
            }
        }

        float mx0 = -1e30f, mx1 = -1e30f;
        #pragma unroll
        for (int nt = 0; nt < 8; nt++) {
            #pragma unroll
            for (int i = 0; i < 4; i++) s[nt][i] *= QK_SCALE;
            mx0 = fmaxf(mx0, fmaxf(s[nt][0], s[nt][1]));
            mx1 = fmaxf(mx1, fmaxf(s[nt][2], s[nt][3]));
        }
        mx0 = fmaxf(mx0, __shfl_xor_sync(0xffffffffu, mx0, 1));
        mx0 = fmaxf(mx0, __shfl_xor_sync(0xffffffffu, mx0, 2));
        mx1 = fmaxf(mx1, __shfl_xor_sync(0xffffffffu, mx1, 1));
        mx1 = fmaxf(mx1, __shfl_xor_sync(0xffffffffu, mx1, 2));

        const float mn0 = fmaxf(m_[0], mx0);
        const float mn1 = fmaxf(m_[1], mx1);
        const float c0 = ex2f(m_[0] - mn0);
        const float c1 = ex2f(m_[1] - mn1);
        m_[0] = mn0; m_[1] = mn1;

        float r0 = 0.f, r1 = 0.f;
        #pragma unroll
        for (int nt = 0; nt < 8; nt++) {
            s[nt][0] = ex2f(s[nt][0] - mn0);
            s[nt][1] = ex2f(s[nt][1] - mn0);
            s[nt][2] = ex2f(s[nt][2] - mn1);
            s[nt][3] = ex2f(s[nt][3] - mn1);
            r0 += s[nt][0] + s[nt][1];
            r1 += s[nt][2] + s[nt][3];
        }
        r0 += __shfl_xor_sync(0xffffffffu, r0, 1);
        r0 += __shfl_xor_sync(0xffffffffu, r0, 2);
        r1 += __shfl_xor_sync(0xffffffffu, r1, 1);
        r1 += __shfl_xor_sync(0xffffffffu, r1, 2);
        l_[0] = l_[0] * c0 + r0;
        l_[1] = l_[1] * c1 + r1;

        #pragma unroll
        for (int nt = 0; nt < 8; nt++) {
            o[nt][0] *= c0; o[nt][1] *= c0;
            o[nt][2] *= c1; o[nt][3] *= c1;
        }

        #pragma unroll
        for (int jp = 0; jp < 4; jp++) {
            uint32_t ph[4];
            ph[0] = pack_h(s[2 * jp][0],     s[2 * jp][1]);
            ph[1] = pack_h(s[2 * jp][2],     s[2 * jp][3]);
            ph[2] = pack_h(s[2 * jp + 1][0], s[2 * jp + 1][1]);
            ph[3] = pack_h(s[2 * jp + 1][2], s[2 * jp + 1][3]);
            #pragma unroll
            for (int p = 0; p < 4; p++) {
                uint32_t vh[4], vl[4];
                const uint32_t d = (uint32_t)(jp * 16 * APAD + p * 16) * 2;
                ldsm4t(vh, skv + 2 * HALF_BYTES + v_off + d);
                ldsm4t(vl, skv + 3 * HALF_BYTES + v_off + d);
                mma16816(o[2 * p],     ph, vh[0], vh[1]);
                mma16816(o[2 * p + 1], ph, vh[2], vh[3]);
                mma16816(o[2 * p],     ph, vl[0], vl[1]);
                mma16816(o[2 * p + 1], ph, vl[2], vl[3]);
            }
        }
    }

    const float inv0 = 1.f / l_[0];
    const float inv1 = 1.f / l_[1];
    const int row = q0 + wid * 16 + g;
    const size_t ob = ((size_t)b * S_ + row) * D_ + h * DK_;
    #pragma unroll
    for (int nt = 0; nt < 8; nt++) {
        const int col = nt * 8 + 2 * tg;
        *reinterpret_cast<uint32_t*>(g_ao + ob + col) =
            pack_h(o[nt][0] * inv0, o[nt][1] * inv0);
        *reinterpret_cast<uint32_t*>(g_ao + ob + (size_t)8 * D_ + col) =
            pack_h(o[nt][2] * inv1, o[nt][3] * inv1);
    }
}

// ===========================================================================
extern "C" void kernel_launch(void* const* d_in, const int* in_sizes, int n_in,
                              void* d_out, int out_size)
{
    const float* q  = (const float*)d_in[0];
    const float* k  = (const float*)d_in[1];
    const float* v  = (const float*)d_in[2];
    const float* pe = (const float*)d_in[3];
    const float* Wq = (const float*)d_in[4];
    const float* bq = (const float*)d_in[5];
    const float* Wk = (const float*)d_in[6];
    const float* bk = (const float*)d_in[7];
    const float* Wv = (const float*)d_in[8];
    const float* bv = (const float*)d_in[9];
    const float* Wo = (const float*)d_in[10];
    const float* bo = (const float*)d_in[11];
    float* out = (float*)d_out;

    __half *whi, *wlo;
    cudaGetSymbolAddress((void**)&whi, g_whi);
    cudaGetSymbolAddress((void**)&wlo, g_wlo);

    cudaFuncSetAttribute(qkv_gemm_kernel,
                         cudaFuncAttributeMaxDynamicSharedMemorySize, GEMM_SMEM);
    cudaFuncSetAttribute(oproj_gemm_kernel,
                         cudaFuncAttributeMaxDynamicSharedMemorySize, GEMM_SMEM);
    cudaFuncSetAttribute(attn_mma_kernel,
                         cudaFuncAttributeMaxDynamicSharedMemorySize, ATTN_SMEM);

    // 1) preprocessing
    split_transpose4_kernel<<<dim3(D_ / 32, D_ / 32, 4), dim3(32, 8)>>>(
        Wq, Wk, Wv, Wo, whi, wlo);
    pet_kernel<<<dim3(S_ / 32, D_ / 32), dim3(32, 8)>>>(pe);
    split_in_kernel<<<dim3((M_ * D_) / 1024, 3), 256>>>(q, k, v);

    // 2) persistent batched Q/K/V projections (K gets +PE in epilogue)
    qkv_gemm_kernel<<<296, 256, GEMM_SMEM>>>(bq, bk, bv);

    // 3) attention
    attn_mma_kernel<<<dim3(S_ / 128, H_, B_), 256, ATTN_SMEM>>>();

    // 4) output projection -> fp32 out
    oproj_gemm_kernel<<<dim3(D_ / 128, M_ / 128), 256, GEMM_SMEM>>>(bo, out);
}